// round 1
// baseline (speedup 1.0000x reference)
#include <cuda_runtime.h>
#include <math.h>

#define DEV_INLINE __device__ __forceinline__

// Problem constants
constexpr int Bn = 32, Ln = 256, DNn = 512, DEn = 64, NHn = 32, DDn = 16;
constexpr int FNn = 1024, FEn = 128;
constexpr int ROWS = Bn * Ln;            // 8192 (b,l) rows
constexpr float EPSc = 1e-5f;

// ---------------- device scratch (no allocations allowed) ----------------
__device__ float g_hln[ROWS * DNn];      // LN(h)
__device__ float g_qkv[ROWS * 3 * DNn];  // QKV rows (1536 each)
__device__ float g_vatt[ROWS * DNn];     // attention output (k*32+h layout)
__device__ float g_h2[ROWS * DNn];       // h after attention residual
__device__ float g_hff[ROWS * DNn];      // LN(h2)
__device__ float g_t[ROWS * FNn];        // elu(h_ff @ W_h1 + b)

// ---------------- LayerNorm over 512, one block per row ----------------
__global__ void __launch_bounds__(128) ln512_kernel(
    const float* __restrict__ x, const float* __restrict__ g,
    const float* __restrict__ b, float* __restrict__ y)
{
    int row = blockIdx.x, tid = threadIdx.x;
    const float4* xr = (const float4*)(x + (size_t)row * 512);
    float4 v = xr[tid];
    float s  = v.x + v.y + v.z + v.w;
    float s2 = v.x*v.x + v.y*v.y + v.z*v.z + v.w*v.w;
    #pragma unroll
    for (int o = 16; o; o >>= 1) {
        s  += __shfl_xor_sync(0xffffffffu, s,  o);
        s2 += __shfl_xor_sync(0xffffffffu, s2, o);
    }
    __shared__ float aS[4], aS2[4];
    if ((tid & 31) == 0) { aS[tid >> 5] = s; aS2[tid >> 5] = s2; }
    __syncthreads();
    s  = aS[0] + aS[1] + aS[2] + aS[3];
    s2 = aS2[0] + aS2[1] + aS2[2] + aS2[3];
    float mean = s * (1.f / 512.f);
    float var  = s2 * (1.f / 512.f) - mean * mean;
    float rstd = rsqrtf(var + EPSc);
    int c = tid * 4;
    float4 gv = *(const float4*)(g + c);
    float4 bv = *(const float4*)(b + c);
    float4 o;
    o.x = (v.x - mean) * rstd * gv.x + bv.x;
    o.y = (v.y - mean) * rstd * gv.y + bv.y;
    o.z = (v.z - mean) * rstd * gv.z + bv.z;
    o.w = (v.w - mean) * rstd * gv.w + bv.w;
    ((float4*)(y + (size_t)row * 512))[tid] = o;
}

// ---------------- generic tiled SGEMM: C = A(MxK) @ B(KxN) + epilogue ---------
// MODE 0: +bias ; MODE 1: +bias+res ; MODE 2: elu(+bias)
template<int MODE>
__global__ void __launch_bounds__(256) sgemm128(
    const float* __restrict__ A, const float* __restrict__ B, float* __restrict__ C,
    const float* __restrict__ bias, const float* __restrict__ res,
    int M, int N, int K)
{
    __shared__ float As[8][128];
    __shared__ float Bs[8][128];
    int tid  = threadIdx.x;
    int row0 = blockIdx.y * 128, col0 = blockIdx.x * 128;
    int arow = tid >> 1,  acol = (tid & 1) * 4;
    int brow = tid >> 5,  bcol = (tid & 31) * 4;
    int ty   = (tid >> 4) * 8, tx = (tid & 15) * 8;
    float acc[8][8] = {};

    for (int k0 = 0; k0 < K; k0 += 8) {
        float4 av = *(const float4*)&A[(size_t)(row0 + arow) * K + k0 + acol];
        As[acol + 0][arow] = av.x;
        As[acol + 1][arow] = av.y;
        As[acol + 2][arow] = av.z;
        As[acol + 3][arow] = av.w;
        float4 bv = *(const float4*)&B[(size_t)(k0 + brow) * N + col0 + bcol];
        *(float4*)&Bs[brow][bcol] = bv;
        __syncthreads();
        #pragma unroll
        for (int kk = 0; kk < 8; kk++) {
            float4 a0 = *(const float4*)&As[kk][ty];
            float4 a1 = *(const float4*)&As[kk][ty + 4];
            float4 b0 = *(const float4*)&Bs[kk][tx];
            float4 b1 = *(const float4*)&Bs[kk][tx + 4];
            float aa[8] = {a0.x,a0.y,a0.z,a0.w,a1.x,a1.y,a1.z,a1.w};
            float bb[8] = {b0.x,b0.y,b0.z,b0.w,b1.x,b1.y,b1.z,b1.w};
            #pragma unroll
            for (int i = 0; i < 8; i++)
                #pragma unroll
                for (int j = 0; j < 8; j++)
                    acc[i][j] += aa[i] * bb[j];
        }
        __syncthreads();
    }
    #pragma unroll
    for (int i = 0; i < 8; i++) {
        size_t roff = (size_t)(row0 + ty + i) * N + col0 + tx;
        #pragma unroll
        for (int j = 0; j < 8; j++) {
            float v = acc[i][j] + bias[col0 + tx + j];
            if (MODE == 1) v += res[roff + j];
            if (MODE == 2) v = v > 0.f ? v : (__expf(v) - 1.f);
            C[roff + j] = v;
        }
    }
}

// ---------------- block GEMM helper for the edge kernel ----------------
// 16x16 thread grid; each thread owns a TM x TN register tile.
template<int TM, int TN, int KK>
DEV_INLINE void bgemm(float acc[TM][TN], const float* __restrict__ A, int lda,
                      const float* __restrict__ W, int ldw, int tr, int tc)
{
    #pragma unroll 8
    for (int k = 0; k < KK; k++) {
        float a[TM];
        #pragma unroll
        for (int i = 0; i < TM; i++) a[i] = A[(tr + i) * lda + k];
        #pragma unroll
        for (int j = 0; j < TN; j += 4) {
            float4 w = *(const float4*)(W + k * ldw + tc + j);
            #pragma unroll
            for (int i = 0; i < TM; i++) {
                acc[i][j+0] += a[i] * w.x;
                acc[i][j+1] += a[i] * w.y;
                acc[i][j+2] += a[i] * w.z;
                acc[i][j+3] += a[i] * w.w;
            }
        }
    }
}

// LayerNorm of 32 rows x 64 cols held in smem (row stride 68). 8 threads/row.
DEV_INLINE void ln_rows32(const float* __restrict__ src, float* __restrict__ dst,
                          const float* __restrict__ gam, const float* __restrict__ bet,
                          int tid)
{
    int r = tid >> 3, sub = tid & 7;
    const float* sr = src + r * 68 + sub * 8;
    float x[8]; float s = 0.f, s2 = 0.f;
    #pragma unroll
    for (int i = 0; i < 8; i++) { x[i] = sr[i]; s += x[i]; s2 += x[i]*x[i]; }
    #pragma unroll
    for (int o = 4; o >= 1; o >>= 1) {
        s  += __shfl_xor_sync(0xffffffffu, s,  o);
        s2 += __shfl_xor_sync(0xffffffffu, s2, o);
    }
    float mean = s * (1.f / 64.f);
    float rstd = rsqrtf(s2 * (1.f / 64.f) - mean * mean + EPSc);
    float* dr = dst + r * 68 + sub * 8;
    #pragma unroll
    for (int i = 0; i < 8; i++) {
        int c = sub * 8 + i;
        dr[i] = (x[i] - mean) * rstd * gam[c] + bet[c];
    }
}

// ---------------- fused edge + attention kernel: one block per (b,l) ----------
constexpr int EDGE_SMEM_FLOATS = 52576;
constexpr int EDGE_SMEM_BYTES  = EDGE_SMEM_FLOATS * 4;

__global__ void __launch_bounds__(256) edge_kernel(
    const float* __restrict__ e, const float* __restrict__ mask,
    const float* __restrict__ lng, const float* __restrict__ lnb,
    const float* __restrict__ flg, const float* __restrict__ flb,
    const float* __restrict__ W_E,  const float* __restrict__ b_E,
    const float* __restrict__ W_G,  const float* __restrict__ b_G,
    const float* __restrict__ W_Oe, const float* __restrict__ b_Oe,
    const float* __restrict__ W_e1, const float* __restrict__ b_e1,
    const float* __restrict__ W_e2, const float* __restrict__ b_e2,
    float* __restrict__ e_out)
{
    extern __shared__ float sm[];
    float* sQ    = sm;                 // 512
    float* sWEG  = sQ    + 512;        // 4096 (64x64: cols 0..31 = W_E, 32..63 = W_G)
    float* sbEG  = sWEG  + 4096;       // 64
    float* sWOe  = sbEG  + 64;         // 2048 (32x64)
    float* sbOe  = sWOe  + 2048;       // 64
    float* sWe1  = sbOe  + 64;         // 8192 (64x128)
    float* sbe1  = sWe1  + 8192;       // 128
    float* sWe2  = sbe1  + 128;        // 8192 (128x64)
    float* sbe2  = sWe2  + 8192;       // 64
    float* sLg   = sbe2  + 64;         // 64
    float* sLb   = sLg   + 64;         // 64
    float* sFg   = sLb   + 64;         // 64
    float* sFb   = sFg   + 64;         // 64
    float* sMask = sFb   + 64;         // 256
    float* sG    = sMask + 256;        // 8192 (256 x 32)  G projections
    float* sH    = sG    + 8192;       // 8192 (256 x 32)  H_hat, then softmax weights
    float* sRed  = sH    + 8192;       // 256
    float* sRed2 = sRed  + 256;        // 256
    float* sE    = sRed2 + 256;        // 2176 (32 x 68)
    float* sEln  = sE    + 2176;       // 2176
    float* sE2   = sEln  + 2176;       // 2176
    float* sEtmp = sE2   + 2176;       // 1056 (32 x 33)  E projections per tile
    float* sT    = sEtmp + 1056;       // 4224 (32 x 132) edge-FFN hidden

    int tid = threadIdx.x;
    int bl  = blockIdx.x;          // b*256 + l
    int b   = bl >> 8;

    // -------- preload weights / params --------
    for (int i = tid; i < 512; i += 256)  sQ[i] = g_qkv[(size_t)bl * 1536 + i];
    for (int i = tid; i < 4096; i += 256) {
        int k = i >> 6, j = i & 63;
        sWEG[i] = (j < 32) ? W_E[k * 32 + j] : W_G[k * 32 + (j - 32)];
    }
    if (tid < 64)  sbEG[tid] = (tid < 32) ? b_E[tid] : b_G[tid - 32];
    for (int i = tid; i < 2048; i += 256) sWOe[i] = W_Oe[i];
    if (tid < 64)  sbOe[tid] = b_Oe[tid];
    for (int i = tid; i < 8192; i += 256) sWe1[i] = W_e1[i];
    if (tid < 128) sbe1[tid] = b_e1[tid];
    for (int i = tid; i < 8192; i += 256) sWe2[i] = W_e2[i];
    if (tid < 64)  sbe2[tid] = b_e2[tid];
    if (tid < 64) { sLg[tid] = lng[tid]; sLb[tid] = lnb[tid];
                    sFg[tid] = flg[tid]; sFb[tid] = flb[tid]; }
    sMask[tid] = mask[(size_t)bl * 256 + tid];
    __syncthreads();

    int tr4  = tid >> 4;   // 0..15
    int tc16 = tid & 15;   // 0..15

    // -------- stage 1: 8 tiles of 32 m-rows; full e-path per tile --------
    for (int t = 0; t < 8; t++) {
        int m0 = t * 32;
        // load e tile (32x64) coalesced float4
        {
            const float4* eg = (const float4*)(e + ((size_t)bl * 256 + m0) * 64);
            #pragma unroll
            for (int i = 0; i < 2; i++) {
                int idx = tid + i * 256;        // 0..511
                int r = idx >> 4, c4 = idx & 15;
                *(float4*)&sE[r * 68 + c4 * 4] = eg[r * 16 + c4];
            }
        }
        __syncthreads();
        ln_rows32(sE, sEln, sLg, sLb, tid);
        __syncthreads();
        // GEMM1: e_ln @ [W_E|W_G]  -> E to sEtmp, G to sG
        {
            int tr = tr4 * 2, tc = tc16 * 4;
            float acc[2][4] = {};
            bgemm<2,4,64>(acc, sEln, 68, sWEG, 64, tr, tc);
            #pragma unroll
            for (int i = 0; i < 2; i++)
                #pragma unroll
                for (int j = 0; j < 4; j++) {
                    int r = tr + i, c = tc + j;
                    float v = acc[i][j] + sbEG[c];
                    if (c < 32) sEtmp[r * 33 + c] = v;
                    else        sG[(m0 + r) * 32 + (c - 32)] = v;
                }
        }
        __syncthreads();
        // A_hat = (Q . K)/4, H_hat = clip + E
        {
            int h = tid & 31, mi = tid >> 5;
            #pragma unroll
            for (int mm = 0; mm < 4; mm++) {
                int m = mi * 4 + mm;
                const float* Kp = g_qkv + ((size_t)(b * 256) + m0 + m) * 1536 + 512 + h;
                float a = 0.f;
                #pragma unroll
                for (int d = 0; d < 16; d++) a += sQ[d * 32 + h] * Kp[d * 32];
                a *= 0.25f;                         // DD^-0.5
                a = fminf(fmaxf(a, -5.f), 5.f) + sEtmp[m * 33 + h];
                sH[(m0 + m) * 32 + h] = a;
            }
        }
        __syncthreads();
        // GEMM2: e2 = H_hat @ W_Oe + b + e
        {
            int tr = tr4 * 2, tc = tc16 * 4;
            float acc[2][4] = {};
            bgemm<2,4,32>(acc, sH + m0 * 32, 32, sWOe, 64, tr, tc);
            #pragma unroll
            for (int i = 0; i < 2; i++)
                #pragma unroll
                for (int j = 0; j < 4; j++) {
                    int r = tr + i, c = tc + j;
                    sE2[r * 68 + c] = acc[i][j] + sbOe[c] + sE[r * 68 + c];
                }
        }
        __syncthreads();
        ln_rows32(sE2, sEln, sFg, sFb, tid);     // eff into sEln (reused)
        __syncthreads();
        // GEMM3: T = elu(eff @ W_e1 + b)
        {
            int tr = tr4 * 2, tc = tc16 * 8;
            float acc[2][8] = {};
            bgemm<2,8,64>(acc, sEln, 68, sWe1, 128, tr, tc);
            #pragma unroll
            for (int i = 0; i < 2; i++)
                #pragma unroll
                for (int j = 0; j < 8; j++) {
                    int r = tr + i, c = tc + j;
                    float v = acc[i][j] + sbe1[c];
                    v = v > 0.f ? v : (__expf(v) - 1.f);
                    sT[r * 132 + c] = v;
                }
        }
        __syncthreads();
        // GEMM4: e_out = T @ W_e2 + b + e2  (direct global store)
        {
            int tr = tr4 * 2, tc = tc16 * 4;
            float acc[2][4] = {};
            bgemm<2,4,128>(acc, sT, 132, sWe2, 64, tr, tc);
            #pragma unroll
            for (int i = 0; i < 2; i++) {
                int r = tr + i;
                float4 v4;
                v4.x = acc[i][0] + sbe2[tc+0] + sE2[r * 68 + tc + 0];
                v4.y = acc[i][1] + sbe2[tc+1] + sE2[r * 68 + tc + 1];
                v4.z = acc[i][2] + sbe2[tc+2] + sE2[r * 68 + tc + 2];
                v4.w = acc[i][3] + sbe2[tc+3] + sE2[r * 68 + tc + 3];
                *(float4*)&e_out[((size_t)bl * 256 + m0 + r) * 64 + tc] = v4;
            }
        }
        __syncthreads();
    }

    // -------- stage 2: softmax over m, gated V accumulation --------
    {
        int h = tid & 31, g = tid >> 5;         // 8 groups of 32 m each
        float pmax = -1e30f;
        for (int mm = 0; mm < 32; mm++) {
            int m = g * 32 + mm;
            pmax = fmaxf(pmax, sH[m * 32 + h] + sMask[m]);
        }
        sRed[g * 32 + h] = pmax;
        __syncthreads();
        float M = -1e30f;
        #pragma unroll
        for (int gg = 0; gg < 8; gg++) M = fmaxf(M, sRed[gg * 32 + h]);
        float ssum = 0.f;
        for (int mm = 0; mm < 32; mm++) {
            int m = g * 32 + mm;
            float mk = sMask[m];
            float w  = __expf(sH[m * 32 + h] + mk - M);
            ssum += w;
            float gate = 1.f / (1.f + __expf(-(sG[m * 32 + h] + mk)));
            sH[m * 32 + h] = w * gate;          // numerator weight (gated)
        }
        sRed2[g * 32 + h] = ssum;
        __syncthreads();
        float S = 0.f;
        #pragma unroll
        for (int gg = 0; gg < 8; gg++) S += sRed2[gg * 32 + h];
        float inv = 1.f / S;

        int k0 = (tid >> 5) * 2;                // each thread: two k values
        float a0 = 0.f, a1 = 0.f;
        const float* Vbase = g_qkv + (size_t)(b * 256) * 1536 + 1024 + h;
        #pragma unroll 4
        for (int m = 0; m < 256; m++) {
            float w = sH[m * 32 + h];
            const float* Vp = Vbase + (size_t)m * 1536;
            a0 += w * Vp[k0 * 32];
            a1 += w * Vp[k0 * 32 + 32];
        }
        g_vatt[(size_t)bl * 512 + k0 * 32 + h]       = a0 * inv;
        g_vatt[(size_t)bl * 512 + (k0 + 1) * 32 + h] = a1 * inv;
    }
}

// ---------------- launch ----------------
extern "C" void kernel_launch(void* const* d_in, const int* in_sizes, int n_in,
                              void* d_out, int out_size)
{
    const float* h         = (const float*)d_in[0];
    const float* e         = (const float*)d_in[1];
    const float* mask      = (const float*)d_in[2];
    const float* ln_h_g    = (const float*)d_in[3];
    const float* ln_h_b    = (const float*)d_in[4];
    const float* ln_e_g    = (const float*)d_in[5];
    const float* ln_e_b    = (const float*)d_in[6];
    const float* ffn_ln_h_g= (const float*)d_in[7];
    const float* ffn_ln_h_b= (const float*)d_in[8];
    const float* ffn_ln_e_g= (const float*)d_in[9];
    const float* ffn_ln_e_b= (const float*)d_in[10];
    const float* W_qkv     = (const float*)d_in[11];
    const float* b_qkv     = (const float*)d_in[12];
    const float* W_E       = (const float*)d_in[13];
    const float* b_E       = (const float*)d_in[14];
    const float* W_G       = (const float*)d_in[15];
    const float* b_G       = (const float*)d_in[16];
    const float* W_Oh      = (const float*)d_in[17];
    const float* b_Oh      = (const float*)d_in[18];
    const float* W_h1      = (const float*)d_in[19];
    const float* b_h1      = (const float*)d_in[20];
    const float* W_h2      = (const float*)d_in[21];
    const float* b_h2      = (const float*)d_in[22];
    const float* W_Oe      = (const float*)d_in[23];
    const float* b_Oe      = (const float*)d_in[24];
    const float* W_e1      = (const float*)d_in[25];
    const float* b_e1      = (const float*)d_in[26];
    const float* W_e2      = (const float*)d_in[27];
    const float* b_e2      = (const float*)d_in[28];

    float* h_out = (float*)d_out;                       // 8192*512
    float* e_out = (float*)d_out + (size_t)ROWS * DNn;  // 32*256*256*64

    float *p_hln, *p_qkv, *p_vatt, *p_h2, *p_hff, *p_t;
    cudaGetSymbolAddress((void**)&p_hln,  g_hln);
    cudaGetSymbolAddress((void**)&p_qkv,  g_qkv);
    cudaGetSymbolAddress((void**)&p_vatt, g_vatt);
    cudaGetSymbolAddress((void**)&p_h2,   g_h2);
    cudaGetSymbolAddress((void**)&p_hff,  g_hff);
    cudaGetSymbolAddress((void**)&p_t,    g_t);

    cudaFuncSetAttribute(edge_kernel, cudaFuncAttributeMaxDynamicSharedMemorySize,
                         EDGE_SMEM_BYTES);

    // 1) h_ln
    ln512_kernel<<<ROWS, 128>>>(h, ln_h_g, ln_h_b, p_hln);
    // 2) QKV = h_ln @ W_qkv + b_qkv
    sgemm128<0><<<dim3(1536/128, ROWS/128), 256>>>(p_hln, W_qkv, p_qkv,
                                                   b_qkv, nullptr, ROWS, 1536, 512);
    // 3) fused edge path + attention (writes e_out and g_vatt)
    edge_kernel<<<ROWS, 256, EDGE_SMEM_BYTES>>>(e, mask, ln_e_g, ln_e_b,
        ffn_ln_e_g, ffn_ln_e_b, W_E, b_E, W_G, b_G, W_Oe, b_Oe,
        W_e1, b_e1, W_e2, b_e2, e_out);
    // 4) h2 = V_att @ W_Oh + b + h
    sgemm128<1><<<dim3(512/128, ROWS/128), 256>>>(p_vatt, W_Oh, p_h2,
                                                  b_Oh, h, ROWS, 512, 512);
    // 5) h_ff = LN(h2)
    ln512_kernel<<<ROWS, 128>>>(p_h2, ffn_ln_h_g, ffn_ln_h_b, p_hff);
    // 6) t = elu(h_ff @ W_h1 + b)
    sgemm128<2><<<dim3(1024/128, ROWS/128), 256>>>(p_hff, W_h1, p_t,
                                                   b_h1, nullptr, ROWS, 1024, 512);
    // 7) h_out = t @ W_h2 + b + h2
    sgemm128<1><<<dim3(512/128, ROWS/128), 256>>>(p_t, W_h2, h_out,
                                                  b_h2, p_h2, ROWS, 512, 1024);
}

// round 2
// speedup vs baseline: 1.0449x; 1.0449x over previous
#include <cuda_runtime.h>
#include <math.h>
#include <stdint.h>

#define DEV_INLINE __device__ __forceinline__

// Problem constants
constexpr int Bn = 32, Ln = 256, DNn = 512;
constexpr int ROWS = Bn * Ln;            // 8192 (b,l) rows
constexpr int FNn = 1024;
constexpr float EPSc = 1e-5f;

// ---------------- device scratch (no allocations allowed) ----------------
__device__ float g_hln[ROWS * DNn];      // LN(h)
__device__ float g_qkv[ROWS * 3 * DNn];  // QKV rows (1536 each)
__device__ float g_vatt[ROWS * DNn];     // attention output (k*32+h layout)
__device__ float g_h2[ROWS * DNn];       // h after attention residual
__device__ float g_hff[ROWS * DNn];      // LN(h2)
__device__ float g_t[ROWS * FNn];        // elu(h_ff @ W_h1 + b)

DEV_INLINE float to_tf32(float x) {
    float y;
    asm("cvt.rna.tf32.f32 %0, %1;" : "=f"(y) : "f"(x));
    return y;
}

DEV_INLINE void mma8(float c[4], uint32_t a0, uint32_t a1, uint32_t a2, uint32_t a3,
                     uint32_t b0, uint32_t b1)
{
    asm volatile(
        "mma.sync.aligned.m16n8k8.row.col.f32.tf32.tf32.f32 "
        "{%0,%1,%2,%3},{%4,%5,%6,%7},{%8,%9},{%0,%1,%2,%3};"
        : "+f"(c[0]), "+f"(c[1]), "+f"(c[2]), "+f"(c[3])
        : "r"(a0), "r"(a1), "r"(a2), "r"(a3), "r"(b0), "r"(b1));
}

// Warp-tile GEMM: one 16-row m-tile, NTW consecutive 8-col n-tiles, KS k-steps of 8.
// Arow: base of the warp's 16-row slice. Bcol: base of first n-tile column.
template<int NTW, int KS>
DEV_INLINE void wgemm(float c[NTW][4], const float* __restrict__ Arow, int lda,
                      const float* __restrict__ Bcol, int ldb, int g, int qt)
{
    #pragma unroll
    for (int ks = 0; ks < KS; ks++) {
        int k = ks * 8;
        uint32_t a0 = __float_as_uint(Arow[(g)     * lda + k + qt]);
        uint32_t a1 = __float_as_uint(Arow[(g + 8) * lda + k + qt]);
        uint32_t a2 = __float_as_uint(Arow[(g)     * lda + k + qt + 4]);
        uint32_t a3 = __float_as_uint(Arow[(g + 8) * lda + k + qt + 4]);
        #pragma unroll
        for (int j = 0; j < NTW; j++) {
            uint32_t b0 = __float_as_uint(Bcol[(k + qt)     * ldb + j * 8 + g]);
            uint32_t b1 = __float_as_uint(Bcol[(k + qt + 4) * ldb + j * 8 + g]);
            mma8(c[j], a0, a1, a2, a3, b0, b1);
        }
    }
}

// ---------------- LayerNorm over 512, one block per row ----------------
__global__ void __launch_bounds__(128) ln512_kernel(
    const float* __restrict__ x, const float* __restrict__ g,
    const float* __restrict__ b, float* __restrict__ y)
{
    int row = blockIdx.x, tid = threadIdx.x;
    const float4* xr = (const float4*)(x + (size_t)row * 512);
    float4 v = xr[tid];
    float s  = v.x + v.y + v.z + v.w;
    float s2 = v.x*v.x + v.y*v.y + v.z*v.z + v.w*v.w;
    #pragma unroll
    for (int o = 16; o; o >>= 1) {
        s  += __shfl_xor_sync(0xffffffffu, s,  o);
        s2 += __shfl_xor_sync(0xffffffffu, s2, o);
    }
    __shared__ float aS[4], aS2[4];
    if ((tid & 31) == 0) { aS[tid >> 5] = s; aS2[tid >> 5] = s2; }
    __syncthreads();
    s  = aS[0] + aS[1] + aS[2] + aS[3];
    s2 = aS2[0] + aS2[1] + aS2[2] + aS2[3];
    float mean = s * (1.f / 512.f);
    float var  = s2 * (1.f / 512.f) - mean * mean;
    float rstd = rsqrtf(var + EPSc);
    int c = tid * 4;
    float4 gv = *(const float4*)(g + c);
    float4 bv = *(const float4*)(b + c);
    float4 o;
    o.x = (v.x - mean) * rstd * gv.x + bv.x;
    o.y = (v.y - mean) * rstd * gv.y + bv.y;
    o.z = (v.z - mean) * rstd * gv.z + bv.z;
    o.w = (v.w - mean) * rstd * gv.w + bv.w;
    ((float4*)(y + (size_t)row * 512))[tid] = o;
}

// ---------------- generic tiled SGEMM (h-path) ----------------
// MODE 0: +bias ; MODE 1: +bias+res ; MODE 2: elu(+bias)
template<int MODE>
__global__ void __launch_bounds__(256) sgemm128(
    const float* __restrict__ A, const float* __restrict__ B, float* __restrict__ C,
    const float* __restrict__ bias, const float* __restrict__ res,
    int M, int N, int K)
{
    __shared__ float As[8][128];
    __shared__ float Bs[8][128];
    int tid  = threadIdx.x;
    int row0 = blockIdx.y * 128, col0 = blockIdx.x * 128;
    int arow = tid >> 1,  acol = (tid & 1) * 4;
    int brow = tid >> 5,  bcol = (tid & 31) * 4;
    int ty   = (tid >> 4) * 8, tx = (tid & 15) * 8;
    float acc[8][8] = {};

    for (int k0 = 0; k0 < K; k0 += 8) {
        float4 av = *(const float4*)&A[(size_t)(row0 + arow) * K + k0 + acol];
        As[acol + 0][arow] = av.x;
        As[acol + 1][arow] = av.y;
        As[acol + 2][arow] = av.z;
        As[acol + 3][arow] = av.w;
        float4 bv = *(const float4*)&B[(size_t)(k0 + brow) * N + col0 + bcol];
        *(float4*)&Bs[brow][bcol] = bv;
        __syncthreads();
        #pragma unroll
        for (int kk = 0; kk < 8; kk++) {
            float4 a0 = *(const float4*)&As[kk][ty];
            float4 a1 = *(const float4*)&As[kk][ty + 4];
            float4 b0 = *(const float4*)&Bs[kk][tx];
            float4 b1 = *(const float4*)&Bs[kk][tx + 4];
            float aa[8] = {a0.x,a0.y,a0.z,a0.w,a1.x,a1.y,a1.z,a1.w};
            float bb[8] = {b0.x,b0.y,b0.z,b0.w,b1.x,b1.y,b1.z,b1.w};
            #pragma unroll
            for (int i = 0; i < 8; i++)
                #pragma unroll
                for (int j = 0; j < 8; j++)
                    acc[i][j] += aa[i] * bb[j];
        }
        __syncthreads();
    }
    #pragma unroll
    for (int i = 0; i < 8; i++) {
        size_t roff = (size_t)(row0 + ty + i) * N + col0 + tx;
        #pragma unroll
        for (int j = 0; j < 8; j++) {
            float v = acc[i][j] + bias[col0 + tx + j];
            if (MODE == 1) v += res[roff + j];
            if (MODE == 2) v = v > 0.f ? v : (__expf(v) - 1.f);
            C[roff + j] = v;
        }
    }
}

// LayerNorm of 32 rows x 64 cols in smem (stride 68), output rounded to tf32.
DEV_INLINE void ln_rows32(const float* __restrict__ src, float* __restrict__ dst,
                          const float* __restrict__ gam, const float* __restrict__ bet,
                          int tid)
{
    int r = tid >> 3, sub = tid & 7;
    const float* sr = src + r * 68 + sub * 8;
    float x[8]; float s = 0.f, s2 = 0.f;
    #pragma unroll
    for (int i = 0; i < 8; i++) { x[i] = sr[i]; s += x[i]; s2 += x[i]*x[i]; }
    #pragma unroll
    for (int o = 4; o >= 1; o >>= 1) {
        s  += __shfl_xor_sync(0xffffffffu, s,  o);
        s2 += __shfl_xor_sync(0xffffffffu, s2, o);
    }
    float mean = s * (1.f / 64.f);
    float rstd = rsqrtf(s2 * (1.f / 64.f) - mean * mean + EPSc);
    float* dr = dst + r * 68 + sub * 8;
    #pragma unroll
    for (int i = 0; i < 8; i++) {
        int c = sub * 8 + i;
        dr[i] = to_tf32((x[i] - mean) * rstd * gam[c] + bet[c]);
    }
}

// ---------------- fused edge + attention kernel: one block per (b,l) ----------
constexpr int EDGE_SMEM_FLOATS = 54848;
constexpr int EDGE_SMEM_BYTES  = EDGE_SMEM_FLOATS * 4;   // 219392 B

__global__ void __launch_bounds__(256) edge_kernel(
    const float* __restrict__ e, const float* __restrict__ mask,
    const float* __restrict__ lng, const float* __restrict__ lnb,
    const float* __restrict__ flg, const float* __restrict__ flb,
    const float* __restrict__ W_E,  const float* __restrict__ b_E,
    const float* __restrict__ W_G,  const float* __restrict__ b_G,
    const float* __restrict__ W_Oe, const float* __restrict__ b_Oe,
    const float* __restrict__ W_e1, const float* __restrict__ b_e1,
    const float* __restrict__ W_e2, const float* __restrict__ b_e2,
    float* __restrict__ e_out)
{
    extern __shared__ float sm[];
    float* sQ    = sm;                 // 512
    float* sWEG  = sQ    + 512;        // 64 x 72 (cols 0..31 W_E, 32..63 W_G)
    float* sWOe  = sWEG  + 4608;       // 32 x 72
    float* sWe1  = sWOe  + 2304;       // 64 x 136
    float* sWe2  = sWe1  + 8704;       // 128 x 72
    float* sbEG  = sWe2  + 9216;       // 64
    float* sbOe  = sbEG  + 64;         // 64
    float* sbe1  = sbOe  + 64;         // 128
    float* sbe2  = sbe1  + 128;        // 64
    float* sLg   = sbe2  + 64;         // 64
    float* sLb   = sLg   + 64;         // 64
    float* sFg   = sLb   + 64;         // 64
    float* sFb   = sFg   + 64;         // 64
    float* sMask = sFb   + 64;         // 256
    float* sG    = sMask + 256;        // 256 x 32 (raw G + bias)
    float* sH    = sG    + 8192;       // 256 x 36 (H_hat tf32, then weights)
    float* sRed  = sH    + 9216;       // 256
    float* sRed2 = sRed  + 256;        // 256
    float* sE    = sRed2 + 256;        // 32 x 68 (e tile, fp32)
    float* sEln  = sE    + 2176;       // 32 x 68 (LN out, tf32)
    float* sE2   = sEln  + 2176;       // 32 x 68 (e2, fp32)
    float* sT    = sE2   + 2176;       // 32 x 132 (FFN hidden tf32; also E temp @33)

    int tid = threadIdx.x;
    int bl  = blockIdx.x;          // b*256 + l
    int b   = bl >> 8;

    int w  = tid >> 5;             // warp 0..7
    int g  = (tid & 31) >> 2;      // groupID 0..7
    int qt = tid & 3;              // threadID_in_group 0..3
    int mi = w >> 2;               // warp's m-tile (0/1)
    int wq = w & 3;                // warp's n-quadrant

    // -------- preload weights / params (tf32-rounded) --------
    for (int i = tid; i < 512; i += 256)  sQ[i] = g_qkv[(size_t)bl * 1536 + i];
    for (int i = tid; i < 64 * 64; i += 256) {
        int k = i >> 6, n = i & 63;
        sWEG[k * 72 + n] = to_tf32(n < 32 ? W_E[k * 32 + n] : W_G[k * 32 + n - 32]);
    }
    for (int i = tid; i < 32 * 64; i += 256) {
        int k = i >> 6, n = i & 63;
        sWOe[k * 72 + n] = to_tf32(W_Oe[i]);
    }
    for (int i = tid; i < 64 * 128; i += 256) {
        int k = i >> 7, n = i & 127;
        sWe1[k * 136 + n] = to_tf32(W_e1[i]);
    }
    for (int i = tid; i < 128 * 64; i += 256) {
        int k = i >> 6, n = i & 63;
        sWe2[k * 72 + n] = to_tf32(W_e2[i]);
    }
    if (tid < 64)  sbEG[tid] = (tid < 32) ? b_E[tid] : b_G[tid - 32];
    if (tid < 64)  sbOe[tid] = b_Oe[tid];
    if (tid < 128) sbe1[tid] = b_e1[tid];
    if (tid < 64)  sbe2[tid] = b_e2[tid];
    if (tid < 64) { sLg[tid] = lng[tid]; sLb[tid] = lnb[tid];
                    sFg[tid] = flg[tid]; sFb[tid] = flb[tid]; }
    sMask[tid] = mask[(size_t)bl * 256 + tid];
    __syncthreads();

    // -------- stage 1: 8 tiles of 32 m-rows --------
    for (int tile = 0; tile < 8; tile++) {
        int m0 = tile * 32;
        // load e tile (32x64) coalesced float4
        {
            const float4* eg = (const float4*)(e + ((size_t)bl * 256 + m0) * 64);
            #pragma unroll
            for (int i = 0; i < 2; i++) {
                int idx = tid + i * 256;
                int r = idx >> 4, c4 = idx & 15;
                *(float4*)&sE[r * 68 + c4 * 4] = eg[r * 16 + c4];
            }
        }
        __syncthreads();
        ln_rows32(sE, sEln, sLg, sLb, tid);
        __syncthreads();

        // GEMM1: e_ln(32x64) @ [W_E|W_G](64x64) -> E (sT @33), G (sG)
        {
            float c[2][4] = {};
            wgemm<2, 8>(c, sEln + mi * 16 * 68, 68, sWEG + wq * 16, 72, g, qt);
            #pragma unroll
            for (int j = 0; j < 2; j++) {
                int col = wq * 16 + j * 8 + 2 * qt;
                #pragma unroll
                for (int half = 0; half < 2; half++) {
                    int r = mi * 16 + g + half * 8;
                    float v0 = c[j][half * 2 + 0] + sbEG[col];
                    float v1 = c[j][half * 2 + 1] + sbEG[col + 1];
                    if (col < 32) {
                        sT[r * 33 + col]     = v0;
                        sT[r * 33 + col + 1] = v1;
                    } else {
                        sG[(m0 + r) * 32 + col - 32]     = v0;
                        sG[(m0 + r) * 32 + col - 32 + 1] = v1;
                    }
                }
            }
        }
        __syncthreads();

        // A_hat = (Q.K)*DD^-0.5 ; H_hat = clip + E  (scalar fp32, tf32-rounded out)
        {
            int h = tid & 31, miq = tid >> 5;
            #pragma unroll
            for (int mm = 0; mm < 4; mm++) {
                int m = miq * 4 + mm;
                const float* Kp = g_qkv + ((size_t)(b * 256) + m0 + m) * 1536 + 512 + h;
                float a = 0.f;
                #pragma unroll
                for (int d = 0; d < 16; d++) a += sQ[d * 32 + h] * Kp[d * 32];
                a *= 0.25f;
                a = fminf(fmaxf(a, -5.f), 5.f) + sT[m * 33 + h];
                sH[(m0 + m) * 36 + h] = to_tf32(a);
            }
        }
        __syncthreads();

        // GEMM2: e2 = H_hat(32x32) @ W_Oe(32x64) + b + e   (fp32 result in sE2)
        {
            float c[2][4] = {};
            wgemm<2, 4>(c, sH + (m0 + mi * 16) * 36, 36, sWOe + wq * 16, 72, g, qt);
            #pragma unroll
            for (int j = 0; j < 2; j++) {
                int col = wq * 16 + j * 8 + 2 * qt;
                #pragma unroll
                for (int half = 0; half < 2; half++) {
                    int r = mi * 16 + g + half * 8;
                    sE2[r * 68 + col]     = c[j][half * 2 + 0] + sbOe[col]     + sE[r * 68 + col];
                    sE2[r * 68 + col + 1] = c[j][half * 2 + 1] + sbOe[col + 1] + sE[r * 68 + col + 1];
                }
            }
        }
        __syncthreads();
        ln_rows32(sE2, sEln, sFg, sFb, tid);
        __syncthreads();

        // GEMM3: T = elu(e_ff(32x64) @ W_e1(64x128) + b)  -> sT @132 (tf32)
        {
            float c[4][4] = {};
            wgemm<4, 8>(c, sEln + mi * 16 * 68, 68, sWe1 + wq * 32, 136, g, qt);
            #pragma unroll
            for (int j = 0; j < 4; j++) {
                int col = wq * 32 + j * 8 + 2 * qt;
                #pragma unroll
                for (int half = 0; half < 2; half++) {
                    int r = mi * 16 + g + half * 8;
                    float v0 = c[j][half * 2 + 0] + sbe1[col];
                    float v1 = c[j][half * 2 + 1] + sbe1[col + 1];
                    v0 = v0 > 0.f ? v0 : (__expf(v0) - 1.f);
                    v1 = v1 > 0.f ? v1 : (__expf(v1) - 1.f);
                    sT[r * 132 + col]     = to_tf32(v0);
                    sT[r * 132 + col + 1] = to_tf32(v1);
                }
            }
        }
        __syncthreads();

        // GEMM4: e_out = T(32x128) @ W_e2(128x64) + b + e2  (direct global store)
        {
            float c[2][4] = {};
            wgemm<2, 16>(c, sT + mi * 16 * 132, 132, sWe2 + wq * 16, 72, g, qt);
            #pragma unroll
            for (int j = 0; j < 2; j++) {
                int col = wq * 16 + j * 8 + 2 * qt;
                #pragma unroll
                for (int half = 0; half < 2; half++) {
                    int r = mi * 16 + g + half * 8;
                    float2 v;
                    v.x = c[j][half * 2 + 0] + sbe2[col]     + sE2[r * 68 + col];
                    v.y = c[j][half * 2 + 1] + sbe2[col + 1] + sE2[r * 68 + col + 1];
                    *(float2*)&e_out[((size_t)bl * 256 + m0 + r) * 64 + col] = v;
                }
            }
        }
        __syncthreads();
    }

    // -------- stage 2: softmax over m, gated V accumulation --------
    {
        int h = tid & 31, gq = tid >> 5;        // 8 groups of 32 m each
        float pmax = -1e30f;
        for (int mm = 0; mm < 32; mm++) {
            int m = gq * 32 + mm;
            pmax = fmaxf(pmax, sH[m * 36 + h] + sMask[m]);
        }
        sRed[gq * 32 + h] = pmax;
        __syncthreads();
        float M = -1e30f;
        #pragma unroll
        for (int gg = 0; gg < 8; gg++) M = fmaxf(M, sRed[gg * 32 + h]);
        float ssum = 0.f;
        for (int mm = 0; mm < 32; mm++) {
            int m = gq * 32 + mm;
            float mk = sMask[m];
            float wgt = __expf(sH[m * 36 + h] + mk - M);
            ssum += wgt;
            float gate = 1.f / (1.f + __expf(-(sG[m * 32 + h] + mk)));
            sH[m * 36 + h] = wgt * gate;
        }
        sRed2[gq * 32 + h] = ssum;
        __syncthreads();
        float S = 0.f;
        #pragma unroll
        for (int gg = 0; gg < 8; gg++) S += sRed2[gg * 32 + h];
        float inv = 1.f / S;

        int k0 = (tid >> 5) * 2;
        float a0 = 0.f, a1 = 0.f;
        const float* Vbase = g_qkv + (size_t)(b * 256) * 1536 + 1024 + h;
        #pragma unroll 4
        for (int m = 0; m < 256; m++) {
            float wgt = sH[m * 36 + h];
            const float* Vp = Vbase + (size_t)m * 1536;
            a0 += wgt * Vp[k0 * 32];
            a1 += wgt * Vp[k0 * 32 + 32];
        }
        g_vatt[(size_t)bl * 512 + k0 * 32 + h]       = a0 * inv;
        g_vatt[(size_t)bl * 512 + (k0 + 1) * 32 + h] = a1 * inv;
    }
}

// ---------------- launch ----------------
extern "C" void kernel_launch(void* const* d_in, const int* in_sizes, int n_in,
                              void* d_out, int out_size)
{
    const float* h         = (const float*)d_in[0];
    const float* e         = (const float*)d_in[1];
    const float* mask      = (const float*)d_in[2];
    const float* ln_h_g    = (const float*)d_in[3];
    const float* ln_h_b    = (const float*)d_in[4];
    const float* ln_e_g    = (const float*)d_in[5];
    const float* ln_e_b    = (const float*)d_in[6];
    const float* ffn_ln_h_g= (const float*)d_in[7];
    const float* ffn_ln_h_b= (const float*)d_in[8];
    const float* ffn_ln_e_g= (const float*)d_in[9];
    const float* ffn_ln_e_b= (const float*)d_in[10];
    const float* W_qkv     = (const float*)d_in[11];
    const float* b_qkv     = (const float*)d_in[12];
    const float* W_E       = (const float*)d_in[13];
    const float* b_E       = (const float*)d_in[14];
    const float* W_G       = (const float*)d_in[15];
    const float* b_G       = (const float*)d_in[16];
    const float* W_Oh      = (const float*)d_in[17];
    const float* b_Oh      = (const float*)d_in[18];
    const float* W_h1      = (const float*)d_in[19];
    const float* b_h1      = (const float*)d_in[20];
    const float* W_h2      = (const float*)d_in[21];
    const float* b_h2      = (const float*)d_in[22];
    const float* W_Oe      = (const float*)d_in[23];
    const float* b_Oe      = (const float*)d_in[24];
    const float* W_e1      = (const float*)d_in[25];
    const float* b_e1      = (const float*)d_in[26];
    const float* W_e2      = (const float*)d_in[27];
    const float* b_e2      = (const float*)d_in[28];

    float* h_out = (float*)d_out;                       // 8192*512
    float* e_out = (float*)d_out + (size_t)ROWS * DNn;  // 32*256*256*64

    float *p_hln, *p_qkv, *p_vatt, *p_h2, *p_hff, *p_t;
    cudaGetSymbolAddress((void**)&p_hln,  g_hln);
    cudaGetSymbolAddress((void**)&p_qkv,  g_qkv);
    cudaGetSymbolAddress((void**)&p_vatt, g_vatt);
    cudaGetSymbolAddress((void**)&p_h2,   g_h2);
    cudaGetSymbolAddress((void**)&p_hff,  g_hff);
    cudaGetSymbolAddress((void**)&p_t,    g_t);

    cudaFuncSetAttribute(edge_kernel, cudaFuncAttributeMaxDynamicSharedMemorySize,
                         EDGE_SMEM_BYTES);

    // 1) h_ln
    ln512_kernel<<<ROWS, 128>>>(h, ln_h_g, ln_h_b, p_hln);
    // 2) QKV = h_ln @ W_qkv + b_qkv
    sgemm128<0><<<dim3(1536/128, ROWS/128), 256>>>(p_hln, W_qkv, p_qkv,
                                                   b_qkv, nullptr, ROWS, 1536, 512);
    // 3) fused edge path + attention (writes e_out and g_vatt)
    edge_kernel<<<ROWS, 256, EDGE_SMEM_BYTES>>>(e, mask, ln_e_g, ln_e_b,
        ffn_ln_e_g, ffn_ln_e_b, W_E, b_E, W_G, b_G, W_Oe, b_Oe,
        W_e1, b_e1, W_e2, b_e2, e_out);
    // 4) h2 = V_att @ W_Oh + b + h
    sgemm128<1><<<dim3(512/128, ROWS/128), 256>>>(p_vatt, W_Oh, p_h2,
                                                  b_Oh, h, ROWS, 512, 512);
    // 5) h_ff = LN(h2)
    ln512_kernel<<<ROWS, 128>>>(p_h2, ffn_ln_h_g, ffn_ln_h_b, p_hff);
    // 6) t = elu(h_ff @ W_h1 + b)
    sgemm128<2><<<dim3(1024/128, ROWS/128), 256>>>(p_hff, W_h1, p_t,
                                                   b_h1, nullptr, ROWS, 1024, 512);
    // 7) h_out = t @ W_h2 + b + h2
    sgemm128<1><<<dim3(512/128, ROWS/128), 256>>>(p_t, W_h2, h_out,
                                                  b_h2, p_h2, ROWS, 512, 1024);
}

// round 3
// speedup vs baseline: 2.2865x; 2.1884x over previous
#include <cuda_runtime.h>
#include <math.h>
#include <stdint.h>

#define DEV_INLINE __device__ __forceinline__

constexpr int Bn = 32, Ln = 256, DNn = 512;
constexpr int ROWS = Bn * Ln;            // 8192 (b,l) rows
constexpr int EROWS = ROWS * Ln;         // 2,097,152 edge rows
constexpr int FNn = 1024;
constexpr float EPSc = 1e-5f;

// ---------------- device scratch ----------------
__device__ float g_hln[ROWS * DNn];
__device__ float g_qkv[ROWS * 3 * DNn];
__device__ float g_vatt[ROWS * DNn];
__device__ float g_h2[ROWS * DNn];
__device__ float g_hff[ROWS * DNn];
__device__ float g_t[ROWS * FNn];
__device__ float g_H[(size_t)EROWS * 32];     // H_hat (fp32) per edge-row x head
__device__ float g_gate[(size_t)EROWS * 32];  // sigmoid(G+mask)

DEV_INLINE float to_tf32(float x) {
    float y;
    asm("cvt.rna.tf32.f32 %0, %1;" : "=f"(y) : "f"(x));
    return y;
}

DEV_INLINE void mma8(float c[4], uint32_t a0, uint32_t a1, uint32_t a2, uint32_t a3,
                     uint32_t b0, uint32_t b1)
{
    asm volatile(
        "mma.sync.aligned.m16n8k8.row.col.f32.tf32.tf32.f32 "
        "{%0,%1,%2,%3},{%4,%5,%6,%7},{%8,%9},{%0,%1,%2,%3};"
        : "+f"(c[0]), "+f"(c[1]), "+f"(c[2]), "+f"(c[3])
        : "r"(a0), "r"(a1), "r"(a2), "r"(a3), "r"(b0), "r"(b1));
}

// Warp-tile GEMM: 16-row m-tile, NTW 8-col n-tiles, KS k-steps of 8.
template<int NTW, int KS>
DEV_INLINE void wgemm(float c[NTW][4], const float* __restrict__ Arow, int lda,
                      const float* __restrict__ Bcol, int ldb, int g, int qt)
{
    #pragma unroll
    for (int ks = 0; ks < KS; ks++) {
        int k = ks * 8;
        uint32_t a0 = __float_as_uint(Arow[(g)     * lda + k + qt]);
        uint32_t a1 = __float_as_uint(Arow[(g + 8) * lda + k + qt]);
        uint32_t a2 = __float_as_uint(Arow[(g)     * lda + k + qt + 4]);
        uint32_t a3 = __float_as_uint(Arow[(g + 8) * lda + k + qt + 4]);
        #pragma unroll
        for (int j = 0; j < NTW; j++) {
            uint32_t b0 = __float_as_uint(Bcol[(k + qt)     * ldb + j * 8 + g]);
            uint32_t b1 = __float_as_uint(Bcol[(k + qt + 4) * ldb + j * 8 + g]);
            mma8(c[j], a0, a1, a2, a3, b0, b1);
        }
    }
}

// ---------------- LayerNorm over 512, one block per row ----------------
__global__ void __launch_bounds__(128) ln512_kernel(
    const float* __restrict__ x, const float* __restrict__ g,
    const float* __restrict__ b, float* __restrict__ y)
{
    int row = blockIdx.x, tid = threadIdx.x;
    const float4* xr = (const float4*)(x + (size_t)row * 512);
    float4 v = xr[tid];
    float s  = v.x + v.y + v.z + v.w;
    float s2 = v.x*v.x + v.y*v.y + v.z*v.z + v.w*v.w;
    #pragma unroll
    for (int o = 16; o; o >>= 1) {
        s  += __shfl_xor_sync(0xffffffffu, s,  o);
        s2 += __shfl_xor_sync(0xffffffffu, s2, o);
    }
    __shared__ float aS[4], aS2[4];
    if ((tid & 31) == 0) { aS[tid >> 5] = s; aS2[tid >> 5] = s2; }
    __syncthreads();
    s  = aS[0] + aS[1] + aS[2] + aS[3];
    s2 = aS2[0] + aS2[1] + aS2[2] + aS2[3];
    float mean = s * (1.f / 512.f);
    float rstd = rsqrtf(s2 * (1.f / 512.f) - mean * mean + EPSc);
    int c = tid * 4;
    float4 gv = *(const float4*)(g + c);
    float4 bv = *(const float4*)(b + c);
    float4 o;
    o.x = (v.x - mean) * rstd * gv.x + bv.x;
    o.y = (v.y - mean) * rstd * gv.y + bv.y;
    o.z = (v.z - mean) * rstd * gv.z + bv.z;
    o.w = (v.w - mean) * rstd * gv.w + bv.w;
    ((float4*)(y + (size_t)row * 512))[tid] = o;
}

// ---------------- tf32 tensor-core GEMM for h-path ----------------
// Tile 128(M) x 64(N), K-chunks of 32. 256 threads, 8 warps (16 rows each).
// MODE 0: +bias ; MODE 1: +bias+res ; MODE 2: elu(+bias)
template<int MODE>
__global__ void __launch_bounds__(256) tgemm(
    const float* __restrict__ A, const float* __restrict__ B, float* __restrict__ C,
    const float* __restrict__ bias, const float* __restrict__ res,
    int M, int N, int K)
{
    __shared__ float As[128 * 36];
    __shared__ float Bs[32 * 72];
    int tid = threadIdx.x;
    int row0 = blockIdx.y * 128, col0 = blockIdx.x * 64;
    int w = tid >> 5;
    int g = (tid & 31) >> 2, qt = tid & 3;
    float acc[8][4] = {};

    for (int k0 = 0; k0 < K; k0 += 32) {
        #pragma unroll
        for (int i = 0; i < 4; i++) {
            int idx = tid + i * 256;
            int r = idx >> 3, c4 = idx & 7;
            float4 v = *(const float4*)&A[(size_t)(row0 + r) * K + k0 + c4 * 4];
            float4 t;
            t.x = to_tf32(v.x); t.y = to_tf32(v.y); t.z = to_tf32(v.z); t.w = to_tf32(v.w);
            *(float4*)&As[r * 36 + c4 * 4] = t;
        }
        #pragma unroll
        for (int i = 0; i < 2; i++) {
            int idx = tid + i * 256;
            int r = idx >> 4, c4 = idx & 15;
            float4 v = *(const float4*)&B[(size_t)(k0 + r) * N + col0 + c4 * 4];
            float4 t;
            t.x = to_tf32(v.x); t.y = to_tf32(v.y); t.z = to_tf32(v.z); t.w = to_tf32(v.w);
            *(float4*)&Bs[r * 72 + c4 * 4] = t;
        }
        __syncthreads();
        wgemm<8, 4>(acc, As + w * 16 * 36, 36, Bs, 72, g, qt);
        __syncthreads();
    }
    #pragma unroll
    for (int j = 0; j < 8; j++) {
        int col = col0 + j * 8 + 2 * qt;
        #pragma unroll
        for (int hf = 0; hf < 2; hf++) {
            int r = row0 + w * 16 + g + hf * 8;
            float v0 = acc[j][hf * 2 + 0] + bias[col];
            float v1 = acc[j][hf * 2 + 1] + bias[col + 1];
            if (MODE == 1) {
                float2 rv = *(const float2*)&res[(size_t)r * N + col];
                v0 += rv.x; v1 += rv.y;
            }
            if (MODE == 2) {
                v0 = v0 > 0.f ? v0 : __expf(v0) - 1.f;
                v1 = v1 > 0.f ? v1 : __expf(v1) - 1.f;
            }
            float2 ov; ov.x = v0; ov.y = v1;
            *(float2*)&C[(size_t)r * N + col] = ov;
        }
    }
}

// LN of 128 rows x 64 cols in smem (stride 68), in place, 4 threads/row, tf32 out.
DEV_INLINE void ln128(float* sX, const float* gam, const float* bet, int tid)
{
    int r = tid >> 2, sub = tid & 3;
    float* p = sX + r * 68 + sub * 16;
    float x[16]; float s = 0.f, s2 = 0.f;
    #pragma unroll
    for (int i = 0; i < 16; i += 4) {
        float4 v = *(float4*)(p + i);
        x[i] = v.x; x[i+1] = v.y; x[i+2] = v.z; x[i+3] = v.w;
    }
    #pragma unroll
    for (int i = 0; i < 16; i++) { s += x[i]; s2 += x[i] * x[i]; }
    s  += __shfl_xor_sync(0xffffffffu, s, 1);  s  += __shfl_xor_sync(0xffffffffu, s, 2);
    s2 += __shfl_xor_sync(0xffffffffu, s2, 1); s2 += __shfl_xor_sync(0xffffffffu, s2, 2);
    float mean = s * (1.f / 64.f);
    float rstd = rsqrtf(s2 * (1.f / 64.f) - mean * mean + EPSc);
    #pragma unroll
    for (int i = 0; i < 16; i++) {
        int c = sub * 16 + i;
        x[i] = to_tf32((x[i] - mean) * rstd * gam[c] + bet[c]);
    }
    #pragma unroll
    for (int i = 0; i < 16; i += 4) {
        float4 v; v.x = x[i]; v.y = x[i+1]; v.z = x[i+2]; v.w = x[i+3];
        *(float4*)(p + i) = v;
    }
}

// ---------------- edge pipeline kernel: 128 edge rows per CTA, 512 threads ------
constexpr int EA_SMEM_FLOATS = 56256;
constexpr int EA_SMEM_BYTES  = EA_SMEM_FLOATS * 4;   // 225024 B

__global__ void __launch_bounds__(512) ea_kernel(
    const float* __restrict__ e, const float* __restrict__ mask,
    const float* __restrict__ lng, const float* __restrict__ lnb,
    const float* __restrict__ flg, const float* __restrict__ flb,
    const float* __restrict__ W_E,  const float* __restrict__ b_E,
    const float* __restrict__ W_G,  const float* __restrict__ b_G,
    const float* __restrict__ W_Oe, const float* __restrict__ b_Oe,
    const float* __restrict__ W_e1, const float* __restrict__ b_e1,
    const float* __restrict__ W_e2, const float* __restrict__ b_e2,
    float* __restrict__ e_out)
{
    extern __shared__ float sm[];
    float* sQ    = sm;              // 512
    float* sWEG  = sm + 512;        // 64 x 72
    float* sWOe  = sm + 5120;       // 32 x 72
    float* sWe1  = sm + 7424;       // 64 x 136
    float* sWe2  = sm + 16128;      // 128 x 72
    float* sbEG  = sm + 25344;      // 64
    float* sbOe  = sm + 25408;      // 64
    float* sbe1  = sm + 25472;      // 128
    float* sbe2  = sm + 25600;      // 64
    float* sLg   = sm + 25664;      // 64
    float* sLb   = sm + 25728;      // 64
    float* sFg   = sm + 25792;      // 64
    float* sFb   = sm + 25856;      // 64
    float* sMask = sm + 25920;      // 128
    float* sX    = sm + 26048;      // 128 x 68  (e -> eln -> e2 -> eff)
    float* sA    = sm + 34752;      // 128 x 36  (A_hat -> H tf32)
    float* sT    = sm + 39360;      // 128 x 132 (FFN hidden, tf32)

    int tid = threadIdx.x;
    int blk  = blockIdx.x;
    int bl   = blk >> 1, half = blk & 1;
    int b    = bl >> 8;
    int m0   = half * 128;
    size_t R0 = (size_t)bl * 256 + m0;

    int w  = tid >> 5, wm = w >> 1, wn = w & 1;
    int g  = (tid & 31) >> 2, qt = tid & 3;

    // -------- preload weights / params --------
    if (tid < 512) sQ[tid] = g_qkv[(size_t)bl * 1536 + tid];
    for (int i = tid; i < 64 * 64; i += 512) {
        int k = i >> 6, n = i & 63;
        sWEG[k * 72 + n] = to_tf32(n < 32 ? W_E[k * 32 + n] : W_G[k * 32 + n - 32]);
    }
    for (int i = tid; i < 32 * 64; i += 512) {
        int k = i >> 6, n = i & 63;
        sWOe[k * 72 + n] = to_tf32(W_Oe[i]);
    }
    for (int i = tid; i < 64 * 128; i += 512) {
        int k = i >> 7, n = i & 127;
        sWe1[k * 136 + n] = to_tf32(W_e1[i]);
    }
    for (int i = tid; i < 128 * 64; i += 512) {
        int k = i >> 6, n = i & 63;
        sWe2[k * 72 + n] = to_tf32(W_e2[i]);
    }
    if (tid < 64) {
        sbEG[tid] = tid < 32 ? b_E[tid] : b_G[tid - 32];
        sbOe[tid] = b_Oe[tid];
        sbe2[tid] = b_e2[tid];
        sLg[tid] = lng[tid]; sLb[tid] = lnb[tid];
        sFg[tid] = flg[tid]; sFb[tid] = flb[tid];
    }
    if (tid < 128) {
        sbe1[tid]  = b_e1[tid];
        sMask[tid] = mask[(size_t)bl * 256 + m0 + tid];
    }
    __syncthreads();

    // P1: load e tile (128 x 64)
    {
        const float4* eg = (const float4*)(e + R0 * 64);
        #pragma unroll
        for (int i = 0; i < 4; i++) {
            int idx = tid + i * 512;
            int r = idx >> 4, c4 = idx & 15;
            *(float4*)&sX[r * 68 + c4 * 4] = eg[idx];
        }
    }
    __syncthreads();

    // P2: LN(e) in place (tf32)
    ln128(sX, sLg, sLb, tid);
    __syncthreads();

    // P3: QK pass (A_hat into sA) + GEMM1 mma (E|G fragments)
    float c1[4][4] = {};
    {
        int h = tid & 31, mr = tid >> 5;
        const float* Kb = g_qkv + ((size_t)(b * 256) + m0) * 1536 + 512 + h;
        #pragma unroll
        for (int rr = 0; rr < 8; rr++) {
            int ml = mr + rr * 16;
            const float* Kp = Kb + (size_t)ml * 1536;
            float a = 0.f;
            #pragma unroll
            for (int d = 0; d < 16; d++) a += sQ[d * 32 + h] * Kp[d * 32];
            sA[ml * 36 + h] = a * 0.25f;
        }
    }
    wgemm<4, 8>(c1, sX + wm * 16 * 68, 68, sWEG + wn * 32, 72, g, qt);
    __syncthreads();

    // P4: epilogue — wn=0: H = clip(A)+E -> g_H + sA(tf32); wn=1: gate -> g_gate
    #pragma unroll
    for (int j = 0; j < 4; j++) {
        int col = wn * 32 + j * 8 + 2 * qt;
        #pragma unroll
        for (int hf = 0; hf < 2; hf++) {
            int r = wm * 16 + g + hf * 8;
            float v0 = c1[j][hf * 2 + 0] + sbEG[col];
            float v1 = c1[j][hf * 2 + 1] + sbEG[col + 1];
            if (wn == 0) {
                float A0 = sA[r * 36 + col], A1 = sA[r * 36 + col + 1];
                float H0 = fminf(fmaxf(A0, -5.f), 5.f) + v0;
                float H1 = fminf(fmaxf(A1, -5.f), 5.f) + v1;
                float2 hw; hw.x = H0; hw.y = H1;
                *(float2*)&g_H[(R0 + r) * 32 + col] = hw;
                sA[r * 36 + col]     = to_tf32(H0);
                sA[r * 36 + col + 1] = to_tf32(H1);
            } else {
                float mk = sMask[r];
                float2 gw;
                gw.x = 1.f / (1.f + __expf(-(v0 + mk)));
                gw.y = 1.f / (1.f + __expf(-(v1 + mk)));
                *(float2*)&g_gate[(R0 + r) * 32 + col - 32] = gw;
            }
        }
    }
    __syncthreads();

    // P5: GEMM2  e2 = H @ W_Oe + b + e   (e2 kept in regs + written to sX)
    float e2r[4][4];
    {
        float c2[4][4] = {};
        wgemm<4, 4>(c2, sA + wm * 16 * 36, 36, sWOe + wn * 32, 72, g, qt);
        #pragma unroll
        for (int j = 0; j < 4; j++) {
            int col = wn * 32 + j * 8 + 2 * qt;
            #pragma unroll
            for (int hf = 0; hf < 2; hf++) {
                int r = wm * 16 + g + hf * 8;
                float2 ev = *(const float2*)&e[(R0 + r) * 64 + col];
                float v0 = c2[j][hf * 2 + 0] + sbOe[col]     + ev.x;
                float v1 = c2[j][hf * 2 + 1] + sbOe[col + 1] + ev.y;
                e2r[j][hf * 2 + 0] = v0;
                e2r[j][hf * 2 + 1] = v1;
                sX[r * 68 + col]     = v0;
                sX[r * 68 + col + 1] = v1;
            }
        }
    }
    __syncthreads();

    // P6: LN(e2) in place (tf32 eff)
    ln128(sX, sFg, sFb, tid);
    __syncthreads();

    // P7: GEMM3  T = elu(eff @ W_e1 + b)  -> sT (tf32)
    {
        float c3[8][4] = {};
        wgemm<8, 8>(c3, sX + wm * 16 * 68, 68, sWe1 + wn * 64, 136, g, qt);
        #pragma unroll
        for (int j = 0; j < 8; j++) {
            int col = wn * 64 + j * 8 + 2 * qt;
            #pragma unroll
            for (int hf = 0; hf < 2; hf++) {
                int r = wm * 16 + g + hf * 8;
                float v0 = c3[j][hf * 2 + 0] + sbe1[col];
                float v1 = c3[j][hf * 2 + 1] + sbe1[col + 1];
                v0 = v0 > 0.f ? v0 : __expf(v0) - 1.f;
                v1 = v1 > 0.f ? v1 : __expf(v1) - 1.f;
                float2 tv; tv.x = to_tf32(v0); tv.y = to_tf32(v1);
                *(float2*)&sT[r * 132 + col] = tv;
            }
        }
    }
    __syncthreads();

    // P8: GEMM4  e_out = T @ W_e2 + b + e2(regs)
    {
        float c4[4][4] = {};
        wgemm<4, 16>(c4, sT + wm * 16 * 132, 132, sWe2 + wn * 32, 72, g, qt);
        #pragma unroll
        for (int j = 0; j < 4; j++) {
            int col = wn * 32 + j * 8 + 2 * qt;
            #pragma unroll
            for (int hf = 0; hf < 2; hf++) {
                int r = wm * 16 + g + hf * 8;
                float2 ov;
                ov.x = c4[j][hf * 2 + 0] + sbe2[col]     + e2r[j][hf * 2 + 0];
                ov.y = c4[j][hf * 2 + 1] + sbe2[col + 1] + e2r[j][hf * 2 + 1];
                *(float2*)&e_out[(R0 + r) * 64 + col] = ov;
            }
        }
    }
}

// ---------------- softmax + gated V accumulation: one block per (b,l) ----------
__global__ void __launch_bounds__(256) eb_kernel(
    const float* __restrict__ mask)
{
    __shared__ float sH[256 * 36];
    __shared__ float sMask[256];
    __shared__ float sRed[256];
    __shared__ float sRed2[256];

    int tid = threadIdx.x;
    int bl  = blockIdx.x;
    int b   = bl >> 8;

    const float4* Hg = (const float4*)(g_H + (size_t)bl * 8192);
    #pragma unroll
    for (int i = 0; i < 8; i++) {
        int idx = tid + i * 256;
        int m = idx >> 3, c4 = idx & 7;
        *(float4*)&sH[m * 36 + c4 * 4] = Hg[idx];
    }
    sMask[tid] = mask[(size_t)bl * 256 + tid];
    __syncthreads();

    int h = tid & 31, grp = tid >> 5;
    float pmax = -1e30f;
    for (int mm = 0; mm < 32; mm++) {
        int m = grp * 32 + mm;
        pmax = fmaxf(pmax, sH[m * 36 + h] + sMask[m]);
    }
    sRed[grp * 32 + h] = pmax;
    __syncthreads();
    float M = -1e30f;
    #pragma unroll
    for (int gg = 0; gg < 8; gg++) M = fmaxf(M, sRed[gg * 32 + h]);

    const float* gate = g_gate + (size_t)bl * 8192;
    float ssum = 0.f;
    for (int mm = 0; mm < 32; mm++) {
        int m = grp * 32 + mm;
        float wv = __expf(sH[m * 36 + h] + sMask[m] - M);
        ssum += wv;
        sH[m * 36 + h] = wv * gate[m * 32 + h];
    }
    sRed2[grp * 32 + h] = ssum;
    __syncthreads();
    float S = 0.f;
    #pragma unroll
    for (int gg = 0; gg < 8; gg++) S += sRed2[gg * 32 + h];
    float inv = 1.f / S;

    int k0 = grp * 2;
    float a0 = 0.f, a1 = 0.f;
    const float* Vb = g_qkv + (size_t)(b * 256) * 1536 + 1024 + k0 * 32 + h;
    #pragma unroll 4
    for (int m = 0; m < 256; m++) {
        float wv = sH[m * 36 + h];
        const float* Vp = Vb + (size_t)m * 1536;
        a0 += wv * Vp[0];
        a1 += wv * Vp[32];
    }
    g_vatt[(size_t)bl * 512 + k0 * 32 + h]       = a0 * inv;
    g_vatt[(size_t)bl * 512 + (k0 + 1) * 32 + h] = a1 * inv;
}

// ---------------- launch ----------------
extern "C" void kernel_launch(void* const* d_in, const int* in_sizes, int n_in,
                              void* d_out, int out_size)
{
    const float* h         = (const float*)d_in[0];
    const float* e         = (const float*)d_in[1];
    const float* mask      = (const float*)d_in[2];
    const float* ln_h_g    = (const float*)d_in[3];
    const float* ln_h_b    = (const float*)d_in[4];
    const float* ln_e_g    = (const float*)d_in[5];
    const float* ln_e_b    = (const float*)d_in[6];
    const float* ffn_ln_h_g= (const float*)d_in[7];
    const float* ffn_ln_h_b= (const float*)d_in[8];
    const float* ffn_ln_e_g= (const float*)d_in[9];
    const float* ffn_ln_e_b= (const float*)d_in[10];
    const float* W_qkv     = (const float*)d_in[11];
    const float* b_qkv     = (const float*)d_in[12];
    const float* W_E       = (const float*)d_in[13];
    const float* b_E       = (const float*)d_in[14];
    const float* W_G       = (const float*)d_in[15];
    const float* b_G       = (const float*)d_in[16];
    const float* W_Oh      = (const float*)d_in[17];
    const float* b_Oh      = (const float*)d_in[18];
    const float* W_h1      = (const float*)d_in[19];
    const float* b_h1      = (const float*)d_in[20];
    const float* W_h2      = (const float*)d_in[21];
    const float* b_h2      = (const float*)d_in[22];
    const float* W_Oe      = (const float*)d_in[23];
    const float* b_Oe      = (const float*)d_in[24];
    const float* W_e1      = (const float*)d_in[25];
    const float* b_e1      = (const float*)d_in[26];
    const float* W_e2      = (const float*)d_in[27];
    const float* b_e2      = (const float*)d_in[28];

    float* h_out = (float*)d_out;
    float* e_out = (float*)d_out + (size_t)ROWS * DNn;

    float *p_hln, *p_qkv, *p_vatt, *p_h2, *p_hff, *p_t;
    cudaGetSymbolAddress((void**)&p_hln,  g_hln);
    cudaGetSymbolAddress((void**)&p_qkv,  g_qkv);
    cudaGetSymbolAddress((void**)&p_vatt, g_vatt);
    cudaGetSymbolAddress((void**)&p_h2,   g_h2);
    cudaGetSymbolAddress((void**)&p_hff,  g_hff);
    cudaGetSymbolAddress((void**)&p_t,    g_t);

    cudaFuncSetAttribute(ea_kernel, cudaFuncAttributeMaxDynamicSharedMemorySize,
                         EA_SMEM_BYTES);

    // 1) h_ln
    ln512_kernel<<<ROWS, 128>>>(h, ln_h_g, ln_h_b, p_hln);
    // 2) QKV = h_ln @ W_qkv + b_qkv   (tf32)
    tgemm<0><<<dim3(1536/64, ROWS/128), 256>>>(p_hln, W_qkv, p_qkv,
                                               b_qkv, nullptr, ROWS, 1536, 512);
    // 3) edge pipeline (writes e_out, g_H, g_gate)
    ea_kernel<<<ROWS * 2, 512, EA_SMEM_BYTES>>>(e, mask, ln_e_g, ln_e_b,
        ffn_ln_e_g, ffn_ln_e_b, W_E, b_E, W_G, b_G, W_Oe, b_Oe,
        W_e1, b_e1, W_e2, b_e2, e_out);
    // 4) softmax + gated V accumulation (writes g_vatt)
    eb_kernel<<<ROWS, 256>>>(mask);
    // 5) h2 = V_att @ W_Oh + b + h
    tgemm<1><<<dim3(512/64, ROWS/128), 256>>>(p_vatt, W_Oh, p_h2,
                                              b_Oh, h, ROWS, 512, 512);
    // 6) h_ff = LN(h2)
    ln512_kernel<<<ROWS, 128>>>(p_h2, ffn_ln_h_g, ffn_ln_h_b, p_hff);
    // 7) t = elu(h_ff @ W_h1 + b)
    tgemm<2><<<dim3(1024/64, ROWS/128), 256>>>(p_hff, W_h1, p_t,
                                               b_h1, nullptr, ROWS, 1024, 512);
    // 8) h_out = t @ W_h2 + b + h2
    tgemm<1><<<dim3(512/64, ROWS/128), 256>>>(p_t, W_h2, h_out,
                                              b_h2, p_h2, ROWS, 512, 1024);
}

// round 4
// speedup vs baseline: 2.6222x; 1.1468x over previous
#include <cuda_runtime.h>
#include <math.h>
#include <stdint.h>

#define DEV_INLINE __device__ __forceinline__

constexpr int Bn = 32, Ln = 256, DNn = 512;
constexpr int ROWS = Bn * Ln;            // 8192 (b,l) rows
constexpr int EROWS = ROWS * Ln;         // 2,097,152 edge rows
constexpr int FNn = 1024;
constexpr float EPSc = 1e-5f;

// ---------------- device scratch ----------------
__device__ float g_hln[ROWS * DNn];
__device__ float g_qkv[ROWS * 3 * DNn];
__device__ float g_vatt[ROWS * DNn];
__device__ float g_h2[ROWS * DNn];
__device__ float g_hff[ROWS * DNn];
__device__ float g_t[ROWS * FNn];
__device__ float g_H[(size_t)EROWS * 32];     // H_hat + mask (fp32)
__device__ float g_gate[(size_t)EROWS * 32];  // sigmoid(G+mask)
// packed tf32 edge weights (L2-resident, fed to mma via LDG)
__device__ float g_WEGp[64 * 64];
__device__ float g_WOep[32 * 64];
__device__ float g_We1p[64 * 128];
__device__ float g_We2p[128 * 64];

DEV_INLINE float to_tf32(float x) {
    float y;
    asm("cvt.rna.tf32.f32 %0, %1;" : "=f"(y) : "f"(x));
    return y;
}

DEV_INLINE void mma8(float c[4], uint32_t a0, uint32_t a1, uint32_t a2, uint32_t a3,
                     uint32_t b0, uint32_t b1)
{
    asm volatile(
        "mma.sync.aligned.m16n8k8.row.col.f32.tf32.tf32.f32 "
        "{%0,%1,%2,%3},{%4,%5,%6,%7},{%8,%9},{%0,%1,%2,%3};"
        : "+f"(c[0]), "+f"(c[1]), "+f"(c[2]), "+f"(c[3])
        : "r"(a0), "r"(a1), "r"(a2), "r"(a3), "r"(b0), "r"(b1));
}

// smem-B warp GEMM (h-path)
template<int NTW, int KS>
DEV_INLINE void wgemm(float c[NTW][4], const float* __restrict__ Arow, int lda,
                      const float* __restrict__ Bcol, int ldb, int g, int qt)
{
    #pragma unroll
    for (int ks = 0; ks < KS; ks++) {
        int k = ks * 8;
        uint32_t a0 = __float_as_uint(Arow[(g)     * lda + k + qt]);
        uint32_t a1 = __float_as_uint(Arow[(g + 8) * lda + k + qt]);
        uint32_t a2 = __float_as_uint(Arow[(g)     * lda + k + qt + 4]);
        uint32_t a3 = __float_as_uint(Arow[(g + 8) * lda + k + qt + 4]);
        #pragma unroll
        for (int j = 0; j < NTW; j++) {
            uint32_t b0 = __float_as_uint(Bcol[(k + qt)     * ldb + j * 8 + g]);
            uint32_t b1 = __float_as_uint(Bcol[(k + qt + 4) * ldb + j * 8 + g]);
            mma8(c[j], a0, a1, a2, a3, b0, b1);
        }
    }
}

// global-B warp GEMM (edge path; B is packed tf32 in L2)
template<int NTW, int KS>
DEV_INLINE void wgemm_g(float c[NTW][4], const float* __restrict__ As, int lda,
                        const float* __restrict__ Bg, int ldb, int g, int qt)
{
    const float* B0 = Bg + qt * ldb + g;
    const float* B4 = Bg + (qt + 4) * ldb + g;
    #pragma unroll
    for (int ks = 0; ks < KS; ks++) {
        int k = ks * 8;
        uint32_t a0 = __float_as_uint(As[(g)     * lda + k + qt]);
        uint32_t a1 = __float_as_uint(As[(g + 8) * lda + k + qt]);
        uint32_t a2 = __float_as_uint(As[(g)     * lda + k + qt + 4]);
        uint32_t a3 = __float_as_uint(As[(g + 8) * lda + k + qt + 4]);
        float bf0[NTW], bf1[NTW];
        #pragma unroll
        for (int j = 0; j < NTW; j++) {
            bf0[j] = __ldg(&B0[k * ldb + j * 8]);
            bf1[j] = __ldg(&B4[k * ldb + j * 8]);
        }
        #pragma unroll
        for (int j = 0; j < NTW; j++)
            mma8(c[j], a0, a1, a2, a3,
                 __float_as_uint(bf0[j]), __float_as_uint(bf1[j]));
    }
}

// ---------------- weight packing (once per launch) ----------------
__global__ void pack_weights(const float* __restrict__ W_E, const float* __restrict__ W_G,
                             const float* __restrict__ W_Oe, const float* __restrict__ W_e1,
                             const float* __restrict__ W_e2)
{
    int i = blockIdx.x * 256 + threadIdx.x;
    if (i < 4096) {
        int k = i >> 6, n = i & 63;
        g_WEGp[i] = to_tf32(n < 32 ? W_E[k * 32 + n] : W_G[k * 32 + n - 32]);
    } else if (i < 6144) {
        g_WOep[i - 4096] = to_tf32(W_Oe[i - 4096]);
    } else if (i < 14336) {
        g_We1p[i - 6144] = to_tf32(W_e1[i - 6144]);
    } else if (i < 22528) {
        g_We2p[i - 14336] = to_tf32(W_e2[i - 14336]);
    }
}

// ---------------- LayerNorm over 512, one block per row ----------------
__global__ void __launch_bounds__(128) ln512_kernel(
    const float* __restrict__ x, const float* __restrict__ g,
    const float* __restrict__ b, float* __restrict__ y)
{
    int row = blockIdx.x, tid = threadIdx.x;
    const float4* xr = (const float4*)(x + (size_t)row * 512);
    float4 v = xr[tid];
    float s  = v.x + v.y + v.z + v.w;
    float s2 = v.x*v.x + v.y*v.y + v.z*v.z + v.w*v.w;
    #pragma unroll
    for (int o = 16; o; o >>= 1) {
        s  += __shfl_xor_sync(0xffffffffu, s,  o);
        s2 += __shfl_xor_sync(0xffffffffu, s2, o);
    }
    __shared__ float aS[4], aS2[4];
    if ((tid & 31) == 0) { aS[tid >> 5] = s; aS2[tid >> 5] = s2; }
    __syncthreads();
    s  = aS[0] + aS[1] + aS[2] + aS[3];
    s2 = aS2[0] + aS2[1] + aS2[2] + aS2[3];
    float mean = s * (1.f / 512.f);
    float rstd = rsqrtf(s2 * (1.f / 512.f) - mean * mean + EPSc);
    int c = tid * 4;
    float4 gv = *(const float4*)(g + c);
    float4 bv = *(const float4*)(b + c);
    float4 o;
    o.x = (v.x - mean) * rstd * gv.x + bv.x;
    o.y = (v.y - mean) * rstd * gv.y + bv.y;
    o.z = (v.z - mean) * rstd * gv.z + bv.z;
    o.w = (v.w - mean) * rstd * gv.w + bv.w;
    ((float4*)(y + (size_t)row * 512))[tid] = o;
}

// ---------------- tf32 tensor GEMM for h-path (128x64 tile, K-chunk 64) -------
// MODE 0: +bias ; MODE 1: +bias+res ; MODE 2: elu(+bias)
constexpr int TG_SMEM_BYTES = (128 * 68 + 64 * 72) * 4;   // 53248
template<int MODE>
__global__ void __launch_bounds__(256) tgemm(
    const float* __restrict__ A, const float* __restrict__ B, float* __restrict__ C,
    const float* __restrict__ bias, const float* __restrict__ res,
    int M, int N, int K)
{
    extern __shared__ float ts[];
    float* As = ts;              // 128 x 68
    float* Bs = ts + 128 * 68;   // 64 x 72
    int tid = threadIdx.x;
    int row0 = blockIdx.y * 128, col0 = blockIdx.x * 64;
    int w = tid >> 5;
    int g = (tid & 31) >> 2, qt = tid & 3;
    float acc[8][4] = {};

    for (int k0 = 0; k0 < K; k0 += 64) {
        #pragma unroll
        for (int i = 0; i < 8; i++) {
            int idx = tid + i * 256;
            int r = idx >> 4, c4 = idx & 15;
            float4 v = *(const float4*)&A[(size_t)(row0 + r) * K + k0 + c4 * 4];
            float4 t;
            t.x = to_tf32(v.x); t.y = to_tf32(v.y); t.z = to_tf32(v.z); t.w = to_tf32(v.w);
            *(float4*)&As[r * 68 + c4 * 4] = t;
        }
        #pragma unroll
        for (int i = 0; i < 4; i++) {
            int idx = tid + i * 256;
            int r = idx >> 4, c4 = idx & 15;
            float4 v = *(const float4*)&B[(size_t)(k0 + r) * N + col0 + c4 * 4];
            float4 t;
            t.x = to_tf32(v.x); t.y = to_tf32(v.y); t.z = to_tf32(v.z); t.w = to_tf32(v.w);
            *(float4*)&Bs[r * 72 + c4 * 4] = t;
        }
        __syncthreads();
        wgemm<8, 8>(acc, As + w * 16 * 68, 68, Bs, 72, g, qt);
        __syncthreads();
    }
    #pragma unroll
    for (int j = 0; j < 8; j++) {
        int col = col0 + j * 8 + 2 * qt;
        #pragma unroll
        for (int hf = 0; hf < 2; hf++) {
            int r = row0 + w * 16 + g + hf * 8;
            float v0 = acc[j][hf * 2 + 0] + bias[col];
            float v1 = acc[j][hf * 2 + 1] + bias[col + 1];
            if (MODE == 1) {
                float2 rv = *(const float2*)&res[(size_t)r * N + col];
                v0 += rv.x; v1 += rv.y;
            }
            if (MODE == 2) {
                v0 = v0 > 0.f ? v0 : __expf(v0) - 1.f;
                v1 = v1 > 0.f ? v1 : __expf(v1) - 1.f;
            }
            float2 ov; ov.x = v0; ov.y = v1;
            *(float2*)&C[(size_t)r * N + col] = ov;
        }
    }
}

// LN of 64 rows x 64 cols: src (stride sstr) -> dst (stride 68), tf32 out.
// 256 threads, 4 per row. Safe in-place (each thread owns its 16 cols).
DEV_INLINE void ln64(const float* __restrict__ src, int sstr, float* __restrict__ dst,
                     const float* __restrict__ gam, const float* __restrict__ bet, int tid)
{
    int r = tid >> 2, sub = tid & 3;
    const float* p = src + r * sstr + sub * 16;
    float x[16]; float s = 0.f, s2 = 0.f;
    #pragma unroll
    for (int i = 0; i < 16; i += 4) {
        float4 v = *(const float4*)(p + i);
        x[i] = v.x; x[i+1] = v.y; x[i+2] = v.z; x[i+3] = v.w;
    }
    #pragma unroll
    for (int i = 0; i < 16; i++) { s += x[i]; s2 += x[i] * x[i]; }
    s  += __shfl_xor_sync(0xffffffffu, s, 1);  s  += __shfl_xor_sync(0xffffffffu, s, 2);
    s2 += __shfl_xor_sync(0xffffffffu, s2, 1); s2 += __shfl_xor_sync(0xffffffffu, s2, 2);
    float mean = s * (1.f / 64.f);
    float rstd = rsqrtf(s2 * (1.f / 64.f) - mean * mean + EPSc);
    float* d = dst + r * 68 + sub * 16;
    #pragma unroll
    for (int i = 0; i < 16; i += 4) {
        int c = sub * 16 + i;
        float4 gv = *(const float4*)(gam + c);
        float4 bv = *(const float4*)(bet + c);
        float4 o;
        o.x = to_tf32((x[i+0] - mean) * rstd * gv.x + bv.x);
        o.y = to_tf32((x[i+1] - mean) * rstd * gv.y + bv.y);
        o.z = to_tf32((x[i+2] - mean) * rstd * gv.z + bv.z);
        o.w = to_tf32((x[i+3] - mean) * rstd * gv.w + bv.w);
        *(float4*)(d + i) = o;
    }
}

// ---------------- edge pipeline: 64 edge rows per CTA, 256 threads, 3 CTA/SM ---
constexpr int EA_SMEM_FLOATS = 64 * 68 + 64 * 36 + 64 * 132;   // 15104
constexpr int EA_SMEM_BYTES  = EA_SMEM_FLOATS * 4;             // 60416

__global__ void __launch_bounds__(256, 3) ea_kernel(
    const float* __restrict__ e, const float* __restrict__ mask,
    const float* __restrict__ lng, const float* __restrict__ lnb,
    const float* __restrict__ flg, const float* __restrict__ flb,
    const float* __restrict__ b_E,  const float* __restrict__ b_G,
    const float* __restrict__ b_Oe, const float* __restrict__ b_e1,
    const float* __restrict__ b_e2,
    float* __restrict__ e_out)
{
    extern __shared__ float sm[];
    float* sX = sm;              // 64 x 68 (eln -> e2 -> eff)
    float* sA = sm + 4352;       // 64 x 36 (A_hat -> H tf32)
    float* sT = sm + 6656;       // 64 x 132 (FFN hidden tf32)

    int tid = threadIdx.x;
    int blk = blockIdx.x;
    int bl  = blk >> 2, quad = blk & 3;
    int b   = bl >> 8;
    int m0  = quad * 64;
    size_t R0 = (size_t)bl * 256 + m0;

    int w  = tid >> 5, wm = w >> 1, wn = w & 1;
    int g  = (tid & 31) >> 2, qt = tid & 3;

    // Pa: LN(e) straight from global -> sX (tf32)
    ln64(e + R0 * 64, 64, sX, lng, lnb, tid);
    __syncthreads();

    // Pb: QK -> sA  +  GEMM1 (E|G) fragments
    {
        int h = tid & 31, mr = tid >> 5;
        float q[16];
        const float* Qp = g_qkv + (size_t)bl * 1536 + h;
        #pragma unroll
        for (int d = 0; d < 16; d++) q[d] = Qp[d * 32];
        const float* Kb = g_qkv + ((size_t)(b * 256) + m0) * 1536 + 512 + h;
        #pragma unroll
        for (int rr = 0; rr < 8; rr++) {
            int ml = mr + rr * 8;
            const float* Kp = Kb + (size_t)ml * 1536;
            float a = 0.f;
            #pragma unroll
            for (int d = 0; d < 16; d++) a += q[d] * Kp[d * 32];
            sA[ml * 36 + h] = a * 0.25f;
        }
    }
    float c1[4][4] = {};
    wgemm_g<4, 8>(c1, sX + wm * 16 * 68, 68, g_WEGp + wn * 32, 64, g, qt);
    __syncthreads();

    // Pc: epilogue — wn0: Hm -> g_H, tf32 H -> sA ; wn1: gate -> g_gate
    {
        float mk0 = mask[(size_t)bl * 256 + m0 + wm * 16 + g];
        float mk1 = mask[(size_t)bl * 256 + m0 + wm * 16 + g + 8];
        if (wn == 0) {
            #pragma unroll
            for (int j = 0; j < 4; j++) {
                int col = j * 8 + 2 * qt;
                float bv0 = b_E[col], bv1 = b_E[col + 1];
                #pragma unroll
                for (int hf = 0; hf < 2; hf++) {
                    int r = wm * 16 + g + hf * 8;
                    float A0 = sA[r * 36 + col], A1 = sA[r * 36 + col + 1];
                    float H0 = fminf(fmaxf(A0, -5.f), 5.f) + c1[j][hf * 2 + 0] + bv0;
                    float H1 = fminf(fmaxf(A1, -5.f), 5.f) + c1[j][hf * 2 + 1] + bv1;
                    float mk = hf ? mk1 : mk0;
                    float2 hw; hw.x = H0 + mk; hw.y = H1 + mk;
                    *(float2*)&g_H[(R0 + r) * 32 + col] = hw;
                    sA[r * 36 + col]     = to_tf32(H0);
                    sA[r * 36 + col + 1] = to_tf32(H1);
                }
            }
        } else {
            #pragma unroll
            for (int j = 0; j < 4; j++) {
                int col = j * 8 + 2 * qt;
                float bv0 = b_G[col], bv1 = b_G[col + 1];
                #pragma unroll
                for (int hf = 0; hf < 2; hf++) {
                    int r = wm * 16 + g + hf * 8;
                    float mk = hf ? mk1 : mk0;
                    float2 gw;
                    gw.x = 1.f / (1.f + __expf(-(c1[j][hf * 2 + 0] + bv0 + mk)));
                    gw.y = 1.f / (1.f + __expf(-(c1[j][hf * 2 + 1] + bv1 + mk)));
                    *(float2*)&g_gate[(R0 + r) * 32 + col] = gw;
                }
            }
        }
    }
    __syncthreads();

    // Pd: GEMM2  e2 = H @ W_Oe + b + e   (regs + sX)
    float e2r[4][4];
    {
        float c2[4][4] = {};
        wgemm_g<4, 4>(c2, sA + wm * 16 * 36, 36, g_WOep + wn * 32, 64, g, qt);
        #pragma unroll
        for (int j = 0; j < 4; j++) {
            int col = wn * 32 + j * 8 + 2 * qt;
            float bo0 = b_Oe[col], bo1 = b_Oe[col + 1];
            #pragma unroll
            for (int hf = 0; hf < 2; hf++) {
                int r = wm * 16 + g + hf * 8;
                float2 ev = *(const float2*)&e[(R0 + r) * 64 + col];
                float v0 = c2[j][hf * 2 + 0] + bo0 + ev.x;
                float v1 = c2[j][hf * 2 + 1] + bo1 + ev.y;
                e2r[j][hf * 2 + 0] = v0;
                e2r[j][hf * 2 + 1] = v1;
                sX[r * 68 + col]     = v0;
                sX[r * 68 + col + 1] = v1;
            }
        }
    }
    __syncthreads();

    // Pe: LN(e2) in place (tf32 eff)
    ln64(sX, 68, sX, flg, flb, tid);
    __syncthreads();

    // Pf: GEMM3  T = elu(eff @ W_e1 + b) -> sT (tf32)
    {
        float c3[8][4] = {};
        wgemm_g<8, 8>(c3, sX + wm * 16 * 68, 68, g_We1p + wn * 64, 128, g, qt);
        #pragma unroll
        for (int j = 0; j < 8; j++) {
            int col = wn * 64 + j * 8 + 2 * qt;
            float bb0 = b_e1[col], bb1 = b_e1[col + 1];
            #pragma unroll
            for (int hf = 0; hf < 2; hf++) {
                int r = wm * 16 + g + hf * 8;
                float v0 = c3[j][hf * 2 + 0] + bb0;
                float v1 = c3[j][hf * 2 + 1] + bb1;
                v0 = v0 > 0.f ? v0 : __expf(v0) - 1.f;
                v1 = v1 > 0.f ? v1 : __expf(v1) - 1.f;
                float2 tv; tv.x = to_tf32(v0); tv.y = to_tf32(v1);
                *(float2*)&sT[r * 132 + col] = tv;
            }
        }
    }
    __syncthreads();

    // Pg: GEMM4  e_out = T @ W_e2 + b + e2(regs)
    {
        float c4[4][4] = {};
        wgemm_g<4, 16>(c4, sT + wm * 16 * 132, 132, g_We2p + wn * 32, 64, g, qt);
        #pragma unroll
        for (int j = 0; j < 4; j++) {
            int col = wn * 32 + j * 8 + 2 * qt;
            float bz0 = b_e2[col], bz1 = b_e2[col + 1];
            #pragma unroll
            for (int hf = 0; hf < 2; hf++) {
                int r = wm * 16 + g + hf * 8;
                float2 ov;
                ov.x = c4[j][hf * 2 + 0] + bz0 + e2r[j][hf * 2 + 0];
                ov.y = c4[j][hf * 2 + 1] + bz1 + e2r[j][hf * 2 + 1];
                *(float2*)&e_out[(R0 + r) * 64 + col] = ov;
            }
        }
    }
}

// ---------------- softmax + gated V accumulation: one block per (b,l) ----------
__global__ void __launch_bounds__(256) eb_kernel()
{
    __shared__ float sH[256 * 36];
    __shared__ float sRed[256];
    __shared__ float sRed2[256];

    int tid = threadIdx.x;
    int bl  = blockIdx.x;
    int b   = bl >> 8;

    const float4* Hg = (const float4*)(g_H + (size_t)bl * 8192);
    #pragma unroll
    for (int i = 0; i < 8; i++) {
        int idx = tid + i * 256;
        int m = idx >> 3, c4 = idx & 7;
        *(float4*)&sH[m * 36 + c4 * 4] = Hg[idx];
    }
    __syncthreads();

    int h = tid & 31, grp = tid >> 5;
    float pmax = -1e30f;
    for (int mm = 0; mm < 32; mm++) {
        int m = grp * 32 + mm;
        pmax = fmaxf(pmax, sH[m * 36 + h]);
    }
    sRed[grp * 32 + h] = pmax;
    __syncthreads();
    float M = -1e30f;
    #pragma unroll
    for (int gg = 0; gg < 8; gg++) M = fmaxf(M, sRed[gg * 32 + h]);

    const float* gate = g_gate + (size_t)bl * 8192;
    float ssum = 0.f;
    for (int mm = 0; mm < 32; mm++) {
        int m = grp * 32 + mm;
        float wv = __expf(sH[m * 36 + h] - M);
        ssum += wv;
        sH[m * 36 + h] = wv * gate[m * 32 + h];
    }
    sRed2[grp * 32 + h] = ssum;
    __syncthreads();
    float S = 0.f;
    #pragma unroll
    for (int gg = 0; gg < 8; gg++) S += sRed2[gg * 32 + h];
    float inv = 1.f / S;

    int k0 = grp * 2;
    float a0 = 0.f, a1 = 0.f;
    const float* Vb = g_qkv + (size_t)(b * 256) * 1536 + 1024 + k0 * 32 + h;
    #pragma unroll 4
    for (int m = 0; m < 256; m++) {
        float wv = sH[m * 36 + h];
        const float* Vp = Vb + (size_t)m * 1536;
        a0 += wv * Vp[0];
        a1 += wv * Vp[32];
    }
    g_vatt[(size_t)bl * 512 + k0 * 32 + h]       = a0 * inv;
    g_vatt[(size_t)bl * 512 + (k0 + 1) * 32 + h] = a1 * inv;
}

// ---------------- launch ----------------
extern "C" void kernel_launch(void* const* d_in, const int* in_sizes, int n_in,
                              void* d_out, int out_size)
{
    const float* h         = (const float*)d_in[0];
    const float* e         = (const float*)d_in[1];
    const float* mask      = (const float*)d_in[2];
    const float* ln_h_g    = (const float*)d_in[3];
    const float* ln_h_b    = (const float*)d_in[4];
    const float* ln_e_g    = (const float*)d_in[5];
    const float* ln_e_b    = (const float*)d_in[6];
    const float* ffn_ln_h_g= (const float*)d_in[7];
    const float* ffn_ln_h_b= (const float*)d_in[8];
    const float* ffn_ln_e_g= (const float*)d_in[9];
    const float* ffn_ln_e_b= (const float*)d_in[10];
    const float* W_qkv     = (const float*)d_in[11];
    const float* b_qkv     = (const float*)d_in[12];
    const float* W_E       = (const float*)d_in[13];
    const float* b_E       = (const float*)d_in[14];
    const float* W_G       = (const float*)d_in[15];
    const float* b_G       = (const float*)d_in[16];
    const float* W_Oh      = (const float*)d_in[17];
    const float* b_Oh      = (const float*)d_in[18];
    const float* W_h1      = (const float*)d_in[19];
    const float* b_h1      = (const float*)d_in[20];
    const float* W_h2      = (const float*)d_in[21];
    const float* b_h2      = (const float*)d_in[22];
    const float* W_Oe      = (const float*)d_in[23];
    const float* b_Oe      = (const float*)d_in[24];
    const float* W_e1      = (const float*)d_in[25];
    const float* b_e1      = (const float*)d_in[26];
    const float* W_e2      = (const float*)d_in[27];
    const float* b_e2      = (const float*)d_in[28];

    float* h_out = (float*)d_out;
    float* e_out = (float*)d_out + (size_t)ROWS * DNn;

    float *p_hln, *p_qkv, *p_vatt, *p_h2, *p_hff, *p_t;
    cudaGetSymbolAddress((void**)&p_hln,  g_hln);
    cudaGetSymbolAddress((void**)&p_qkv,  g_qkv);
    cudaGetSymbolAddress((void**)&p_vatt, g_vatt);
    cudaGetSymbolAddress((void**)&p_h2,   g_h2);
    cudaGetSymbolAddress((void**)&p_hff,  g_hff);
    cudaGetSymbolAddress((void**)&p_t,    g_t);

    cudaFuncSetAttribute(ea_kernel, cudaFuncAttributeMaxDynamicSharedMemorySize,
                         EA_SMEM_BYTES);
    cudaFuncSetAttribute(tgemm<0>, cudaFuncAttributeMaxDynamicSharedMemorySize,
                         TG_SMEM_BYTES);
    cudaFuncSetAttribute(tgemm<1>, cudaFuncAttributeMaxDynamicSharedMemorySize,
                         TG_SMEM_BYTES);
    cudaFuncSetAttribute(tgemm<2>, cudaFuncAttributeMaxDynamicSharedMemorySize,
                         TG_SMEM_BYTES);

    // 0) pack edge weights to tf32 globals
    pack_weights<<<88, 256>>>(W_E, W_G, W_Oe, W_e1, W_e2);
    // 1) h_ln
    ln512_kernel<<<ROWS, 128>>>(h, ln_h_g, ln_h_b, p_hln);
    // 2) QKV = h_ln @ W_qkv + b_qkv   (tf32)
    tgemm<0><<<dim3(1536/64, ROWS/128), 256, TG_SMEM_BYTES>>>(p_hln, W_qkv, p_qkv,
                                               b_qkv, nullptr, ROWS, 1536, 512);
    // 3) edge pipeline (writes e_out, g_H(+mask), g_gate)
    ea_kernel<<<ROWS * 4, 256, EA_SMEM_BYTES>>>(e, mask, ln_e_g, ln_e_b,
        ffn_ln_e_g, ffn_ln_e_b, b_E, b_G, b_Oe, b_e1, b_e2, e_out);
    // 4) softmax + gated V accumulation (writes g_vatt)
    eb_kernel<<<ROWS, 256>>>();
    // 5) h2 = V_att @ W_Oh + b + h
    tgemm<1><<<dim3(512/64, ROWS/128), 256, TG_SMEM_BYTES>>>(p_vatt, W_Oh, p_h2,
                                              b_Oh, h, ROWS, 512, 512);
    // 6) h_ff = LN(h2)
    ln512_kernel<<<ROWS, 128>>>(p_h2, ffn_ln_h_g, ffn_ln_h_b, p_hff);
    // 7) t = elu(h_ff @ W_h1 + b)
    tgemm<2><<<dim3(1024/64, ROWS/128), 256, TG_SMEM_BYTES>>>(p_hff, W_h1, p_t,
                                               b_h1, nullptr, ROWS, 1024, 512);
    // 8) h_out = t @ W_h2 + b + h2
    tgemm<1><<<dim3(512/64, ROWS/128), 256, TG_SMEM_BYTES>>>(p_t, W_h2, h_out,
                                              b_h2, p_h2, ROWS, 512, 1024);
}

// round 5
// speedup vs baseline: 2.8067x; 1.0704x over previous
#include <cuda_runtime.h>
#include <math.h>
#include <stdint.h>

#define DEV_INLINE __device__ __forceinline__

constexpr int Bn = 32, Ln = 256, DNn = 512;
constexpr int ROWS = Bn * Ln;            // 8192 (b,l) rows
constexpr int EROWS = ROWS * Ln;         // 2,097,152 edge rows
constexpr int FNn = 1024;
constexpr float EPSc = 1e-5f;

// ---------------- device scratch ----------------
__device__ float g_hln[ROWS * DNn];
__device__ float g_qkv[ROWS * 3 * DNn];
__device__ float g_vatt[ROWS * DNn];
__device__ float g_h2[ROWS * DNn];
__device__ float g_hff[ROWS * DNn];
__device__ float g_t[ROWS * FNn];
__device__ float g_H[(size_t)EROWS * 32];     // H_hat + mask (fp32)
__device__ float g_gate[(size_t)EROWS * 32];  // sigmoid(G+mask)
// residue-packed tf32 edge weights: Wp[(n*4+qt)*K4 + k4]  (K4 = K/4)
__device__ float g_WEGp[64 * 64];     // K=64,  N=64  (cols 0..31 E, 32..63 G)
__device__ float g_WOep[32 * 64];     // K=32,  N=64
__device__ float g_We1p[64 * 128];    // K=64,  N=128
__device__ float g_We2p[128 * 64];    // K=128, N=64

DEV_INLINE float to_tf32(float x) {
    float y;
    asm("cvt.rna.tf32.f32 %0, %1;" : "=f"(y) : "f"(x));
    return y;
}

DEV_INLINE void mma8(float c[4], uint32_t a0, uint32_t a1, uint32_t a2, uint32_t a3,
                     uint32_t b0, uint32_t b1)
{
    asm volatile(
        "mma.sync.aligned.m16n8k8.row.col.f32.tf32.tf32.f32 "
        "{%0,%1,%2,%3},{%4,%5,%6,%7},{%8,%9},{%0,%1,%2,%3};"
        : "+f"(c[0]), "+f"(c[1]), "+f"(c[2]), "+f"(c[3])
        : "r"(a0), "r"(a1), "r"(a2), "r"(a3), "r"(b0), "r"(b1));
}

// smem-B warp GEMM (h-path)
template<int NTW, int KS>
DEV_INLINE void wgemm(float c[NTW][4], const float* __restrict__ Arow, int lda,
                      const float* __restrict__ Bcol, int ldb, int g, int qt)
{
    #pragma unroll
    for (int ks = 0; ks < KS; ks++) {
        int k = ks * 8;
        uint32_t a0 = __float_as_uint(Arow[(g)     * lda + k + qt]);
        uint32_t a1 = __float_as_uint(Arow[(g + 8) * lda + k + qt]);
        uint32_t a2 = __float_as_uint(Arow[(g)     * lda + k + qt + 4]);
        uint32_t a3 = __float_as_uint(Arow[(g + 8) * lda + k + qt + 4]);
        #pragma unroll
        for (int j = 0; j < NTW; j++) {
            uint32_t b0 = __float_as_uint(Bcol[(k + qt)     * ldb + j * 8 + g]);
            uint32_t b1 = __float_as_uint(Bcol[(k + qt + 4) * ldb + j * 8 + g]);
            mma8(c[j], a0, a1, a2, a3, b0, b1);
        }
    }
}

// residue-packed-B warp GEMM (edge path). TM 16-row m-tiles, NTW 8-col n-tiles.
// Bp pre-offset to the warp's first column: element ((col*4+qt)*K4 + k4).
// One float4 load = fragments for 2 consecutive k-steps (4 k-rows of B).
template<int TM, int NTW, int KS, int K4>
DEV_INLINE void wgemm_v(float c[TM][NTW][4], const float* __restrict__ As, int lda,
                        const float* __restrict__ Bp, int g, int qt)
{
    #pragma unroll
    for (int mg = 0; mg < KS / 2; mg++) {
        float4 bf[NTW];
        #pragma unroll
        for (int j = 0; j < NTW; j++)
            bf[j] = *(const float4*)&Bp[((j * 8 + g) * 4 + qt) * K4 + 4 * mg];
        #pragma unroll
        for (int s = 0; s < 2; s++) {
            int k = (2 * mg + s) * 8;
            #pragma unroll
            for (int tm = 0; tm < TM; tm++) {
                const float* Ar = As + tm * 16 * lda;
                uint32_t a0 = __float_as_uint(Ar[(g)     * lda + k + qt]);
                uint32_t a1 = __float_as_uint(Ar[(g + 8) * lda + k + qt]);
                uint32_t a2 = __float_as_uint(Ar[(g)     * lda + k + qt + 4]);
                uint32_t a3 = __float_as_uint(Ar[(g + 8) * lda + k + qt + 4]);
                #pragma unroll
                for (int j = 0; j < NTW; j++) {
                    const float* bb = (const float*)&bf[j];
                    mma8(c[tm][j], a0, a1, a2, a3,
                         __float_as_uint(bb[2 * s]), __float_as_uint(bb[2 * s + 1]));
                }
            }
        }
    }
}

// ---------------- weight packing (once per launch) ----------------
DEV_INLINE int packIdx(int n, int k, int K4) { return (n * 4 + (k & 3)) * K4 + (k >> 2); }

__global__ void pack_weights(const float* __restrict__ W_E, const float* __restrict__ W_G,
                             const float* __restrict__ W_Oe, const float* __restrict__ W_e1,
                             const float* __restrict__ W_e2)
{
    int i = blockIdx.x * 256 + threadIdx.x;
    if (i < 4096) {                       // WEG: K=64, N=64
        int k = i >> 6, n = i & 63;
        float v = n < 32 ? W_E[k * 32 + n] : W_G[k * 32 + n - 32];
        g_WEGp[packIdx(n, k, 16)] = to_tf32(v);
    } else if (i < 6144) {                // WOe: K=32, N=64
        int j = i - 4096; int k = j >> 6, n = j & 63;
        g_WOep[packIdx(n, k, 8)] = to_tf32(W_Oe[j]);
    } else if (i < 14336) {               // We1: K=64, N=128
        int j = i - 6144; int k = j >> 7, n = j & 127;
        g_We1p[packIdx(n, k, 16)] = to_tf32(W_e1[j]);
    } else if (i < 22528) {               // We2: K=128, N=64
        int j = i - 14336; int k = j >> 6, n = j & 63;
        g_We2p[packIdx(n, k, 32)] = to_tf32(W_e2[j]);
    }
}

// ---------------- LayerNorm over 512, one block per row ----------------
__global__ void __launch_bounds__(128) ln512_kernel(
    const float* __restrict__ x, const float* __restrict__ g,
    const float* __restrict__ b, float* __restrict__ y)
{
    int row = blockIdx.x, tid = threadIdx.x;
    const float4* xr = (const float4*)(x + (size_t)row * 512);
    float4 v = xr[tid];
    float s  = v.x + v.y + v.z + v.w;
    float s2 = v.x*v.x + v.y*v.y + v.z*v.z + v.w*v.w;
    #pragma unroll
    for (int o = 16; o; o >>= 1) {
        s  += __shfl_xor_sync(0xffffffffu, s,  o);
        s2 += __shfl_xor_sync(0xffffffffu, s2, o);
    }
    __shared__ float aS[4], aS2[4];
    if ((tid & 31) == 0) { aS[tid >> 5] = s; aS2[tid >> 5] = s2; }
    __syncthreads();
    s  = aS[0] + aS[1] + aS[2] + aS[3];
    s2 = aS2[0] + aS2[1] + aS2[2] + aS2[3];
    float mean = s * (1.f / 512.f);
    float rstd = rsqrtf(s2 * (1.f / 512.f) - mean * mean + EPSc);
    int c = tid * 4;
    float4 gv = *(const float4*)(g + c);
    float4 bv = *(const float4*)(b + c);
    float4 o;
    o.x = (v.x - mean) * rstd * gv.x + bv.x;
    o.y = (v.y - mean) * rstd * gv.y + bv.y;
    o.z = (v.z - mean) * rstd * gv.z + bv.z;
    o.w = (v.w - mean) * rstd * gv.w + bv.w;
    ((float4*)(y + (size_t)row * 512))[tid] = o;
}

// ---------------- tf32 tensor GEMM for h-path (128x64 tile, K-chunk 64) -------
constexpr int TG_SMEM_BYTES = (128 * 68 + 64 * 72) * 4;   // 53248
template<int MODE>
__global__ void __launch_bounds__(256) tgemm(
    const float* __restrict__ A, const float* __restrict__ B, float* __restrict__ C,
    const float* __restrict__ bias, const float* __restrict__ res,
    int M, int N, int K)
{
    extern __shared__ float ts[];
    float* As = ts;              // 128 x 68
    float* Bs = ts + 128 * 68;   // 64 x 72
    int tid = threadIdx.x;
    int row0 = blockIdx.y * 128, col0 = blockIdx.x * 64;
    int w = tid >> 5;
    int g = (tid & 31) >> 2, qt = tid & 3;
    float acc[8][4] = {};

    for (int k0 = 0; k0 < K; k0 += 64) {
        #pragma unroll
        for (int i = 0; i < 8; i++) {
            int idx = tid + i * 256;
            int r = idx >> 4, c4 = idx & 15;
            float4 v = *(const float4*)&A[(size_t)(row0 + r) * K + k0 + c4 * 4];
            float4 t;
            t.x = to_tf32(v.x); t.y = to_tf32(v.y); t.z = to_tf32(v.z); t.w = to_tf32(v.w);
            *(float4*)&As[r * 68 + c4 * 4] = t;
        }
        #pragma unroll
        for (int i = 0; i < 4; i++) {
            int idx = tid + i * 256;
            int r = idx >> 4, c4 = idx & 15;
            float4 v = *(const float4*)&B[(size_t)(k0 + r) * N + col0 + c4 * 4];
            float4 t;
            t.x = to_tf32(v.x); t.y = to_tf32(v.y); t.z = to_tf32(v.z); t.w = to_tf32(v.w);
            *(float4*)&Bs[r * 72 + c4 * 4] = t;
        }
        __syncthreads();
        wgemm<8, 8>(acc, As + w * 16 * 68, 68, Bs, 72, g, qt);
        __syncthreads();
    }
    #pragma unroll
    for (int j = 0; j < 8; j++) {
        int col = col0 + j * 8 + 2 * qt;
        #pragma unroll
        for (int hf = 0; hf < 2; hf++) {
            int r = row0 + w * 16 + g + hf * 8;
            float v0 = acc[j][hf * 2 + 0] + bias[col];
            float v1 = acc[j][hf * 2 + 1] + bias[col + 1];
            if (MODE == 1) {
                float2 rv = *(const float2*)&res[(size_t)r * N + col];
                v0 += rv.x; v1 += rv.y;
            }
            if (MODE == 2) {
                v0 = v0 > 0.f ? v0 : __expf(v0) - 1.f;
                v1 = v1 > 0.f ? v1 : __expf(v1) - 1.f;
            }
            float2 ov; ov.x = v0; ov.y = v1;
            *(float2*)&C[(size_t)r * N + col] = ov;
        }
    }
}

// LN of 64 rows x 64 cols: src (stride sstr) -> dst (stride 68), tf32 out.
DEV_INLINE void ln64(const float* __restrict__ src, int sstr, float* __restrict__ dst,
                     const float* __restrict__ gam, const float* __restrict__ bet, int tid)
{
    int r = tid >> 2, sub = tid & 3;
    const float* p = src + r * sstr + sub * 16;
    float x[16]; float s = 0.f, s2 = 0.f;
    #pragma unroll
    for (int i = 0; i < 16; i += 4) {
        float4 v = *(const float4*)(p + i);
        x[i] = v.x; x[i+1] = v.y; x[i+2] = v.z; x[i+3] = v.w;
    }
    #pragma unroll
    for (int i = 0; i < 16; i++) { s += x[i]; s2 += x[i] * x[i]; }
    s  += __shfl_xor_sync(0xffffffffu, s, 1);  s  += __shfl_xor_sync(0xffffffffu, s, 2);
    s2 += __shfl_xor_sync(0xffffffffu, s2, 1); s2 += __shfl_xor_sync(0xffffffffu, s2, 2);
    float mean = s * (1.f / 64.f);
    float rstd = rsqrtf(s2 * (1.f / 64.f) - mean * mean + EPSc);
    float* d = dst + r * 68 + sub * 16;
    #pragma unroll
    for (int i = 0; i < 16; i += 4) {
        int c = sub * 16 + i;
        float4 gv = *(const float4*)(gam + c);
        float4 bv = *(const float4*)(bet + c);
        float4 o;
        o.x = to_tf32((x[i+0] - mean) * rstd * gv.x + bv.x);
        o.y = to_tf32((x[i+1] - mean) * rstd * gv.y + bv.y);
        o.z = to_tf32((x[i+2] - mean) * rstd * gv.z + bv.z);
        o.w = to_tf32((x[i+3] - mean) * rstd * gv.w + bv.w);
        *(float4*)(d + i) = o;
    }
}

// ---------------- edge pipeline: 64 rows/CTA, 256 threads, 3 CTA/SM ------------
// Warp (wm2, wn): rows wm2*32..+31 (2 m-tiles), cols wn*(N/4).
constexpr int EA_SMEM_FLOATS = 64 * 68 + 64 * 36 + 64 * 132;   // 15104
constexpr int EA_SMEM_BYTES  = EA_SMEM_FLOATS * 4;             // 60416

__global__ void __launch_bounds__(256, 3) ea_kernel(
    const float* __restrict__ e, const float* __restrict__ mask,
    const float* __restrict__ lng, const float* __restrict__ lnb,
    const float* __restrict__ flg, const float* __restrict__ flb,
    const float* __restrict__ b_E,  const float* __restrict__ b_G,
    const float* __restrict__ b_Oe, const float* __restrict__ b_e1,
    const float* __restrict__ b_e2,
    float* __restrict__ e_out)
{
    extern __shared__ float sm[];
    float* sX = sm;              // 64 x 68 (eln -> e2 -> eff)
    float* sA = sm + 4352;       // 64 x 36 (A_hat -> H tf32)
    float* sT = sm + 6656;       // 64 x 132 (FFN hidden tf32)

    int tid = threadIdx.x;
    int blk = blockIdx.x;
    int bl  = blk >> 2, quad = blk & 3;
    int b   = bl >> 8;
    int m0  = quad * 64;
    size_t R0 = (size_t)bl * 256 + m0;

    int w   = tid >> 5;
    int wm2 = w >> 2, wn = w & 3;       // rows wm2*32, col quarter wn
    int g   = (tid & 31) >> 2, qt = tid & 3;
    int rowb = wm2 * 32;

    // Pa: LN(e) straight from global -> sX (tf32)
    ln64(e + R0 * 64, 64, sX, lng, lnb, tid);
    __syncthreads();

    // Pb: QK -> sA  +  GEMM1 (E|G)
    {
        int h = tid & 31, mr = tid >> 5;
        float q[16];
        const float* Qp = g_qkv + (size_t)bl * 1536 + h;
        #pragma unroll
        for (int d = 0; d < 16; d++) q[d] = Qp[d * 32];
        const float* Kb = g_qkv + ((size_t)(b * 256) + m0) * 1536 + 512 + h;
        #pragma unroll
        for (int rr = 0; rr < 8; rr++) {
            int ml = mr + rr * 8;
            const float* Kp = Kb + (size_t)ml * 1536;
            float a = 0.f;
            #pragma unroll
            for (int d = 0; d < 16; d++) a += q[d] * Kp[d * 32];
            sA[ml * 36 + h] = a * 0.25f;
        }
    }
    float c1[2][2][4] = {};
    wgemm_v<2, 2, 8, 16>(c1, sX + rowb * 68, 68, g_WEGp + (wn * 16) * 64, g, qt);
    __syncthreads();

    // Pc: epilogue — wn<2: H (cols 0..31); wn>=2: gate (cols 0..31 of G)
    {
        #pragma unroll
        for (int tm = 0; tm < 2; tm++) {
            float mk0 = mask[(size_t)bl * 256 + m0 + rowb + tm * 16 + g];
            float mk1 = mask[(size_t)bl * 256 + m0 + rowb + tm * 16 + g + 8];
            #pragma unroll
            for (int j = 0; j < 2; j++) {
                int colg = wn * 16 + j * 8 + 2 * qt;   // 0..63 global WEG col
                if (wn < 2) {
                    int col = colg;                    // E col 0..31
                    float bv0 = b_E[col], bv1 = b_E[col + 1];
                    #pragma unroll
                    for (int hf = 0; hf < 2; hf++) {
                        int r = rowb + tm * 16 + g + hf * 8;
                        float A0 = sA[r * 36 + col], A1 = sA[r * 36 + col + 1];
                        float H0 = fminf(fmaxf(A0, -5.f), 5.f) + c1[tm][j][hf * 2 + 0] + bv0;
                        float H1 = fminf(fmaxf(A1, -5.f), 5.f) + c1[tm][j][hf * 2 + 1] + bv1;
                        float mk = hf ? mk1 : mk0;
                        float2 hw; hw.x = H0 + mk; hw.y = H1 + mk;
                        *(float2*)&g_H[(R0 + r) * 32 + col] = hw;
                        sA[r * 36 + col]     = to_tf32(H0);
                        sA[r * 36 + col + 1] = to_tf32(H1);
                    }
                } else {
                    int col = colg - 32;               // G col 0..31
                    float bv0 = b_G[col], bv1 = b_G[col + 1];
                    #pragma unroll
                    for (int hf = 0; hf < 2; hf++) {
                        int r = rowb + tm * 16 + g + hf * 8;
                        float mk = hf ? mk1 : mk0;
                        float2 gw;
                        gw.x = 1.f / (1.f + __expf(-(c1[tm][j][hf * 2 + 0] + bv0 + mk)));
                        gw.y = 1.f / (1.f + __expf(-(c1[tm][j][hf * 2 + 1] + bv1 + mk)));
                        *(float2*)&g_gate[(R0 + r) * 32 + col] = gw;
                    }
                }
            }
        }
    }
    __syncthreads();

    // Pd: GEMM2  e2 = H @ W_Oe + b + e   (regs + sX)
    float e2r[2][2][4];
    {
        float c2[2][2][4] = {};
        wgemm_v<2, 2, 4, 8>(c2, sA + rowb * 36, 36, g_WOep + (wn * 16) * 32, g, qt);
        #pragma unroll
        for (int tm = 0; tm < 2; tm++)
            #pragma unroll
            for (int j = 0; j < 2; j++) {
                int col = wn * 16 + j * 8 + 2 * qt;
                float bo0 = b_Oe[col], bo1 = b_Oe[col + 1];
                #pragma unroll
                for (int hf = 0; hf < 2; hf++) {
                    int r = rowb + tm * 16 + g + hf * 8;
                    float2 ev = *(const float2*)&e[(R0 + r) * 64 + col];
                    float v0 = c2[tm][j][hf * 2 + 0] + bo0 + ev.x;
                    float v1 = c2[tm][j][hf * 2 + 1] + bo1 + ev.y;
                    e2r[tm][j][hf * 2 + 0] = v0;
                    e2r[tm][j][hf * 2 + 1] = v1;
                    sX[r * 68 + col]     = v0;
                    sX[r * 68 + col + 1] = v1;
                }
            }
    }
    __syncthreads();

    // Pe: LN(e2) in place (tf32 eff)
    ln64(sX, 68, sX, flg, flb, tid);
    __syncthreads();

    // Pf: GEMM3  T = elu(eff @ W_e1 + b) -> sT, two 16-col halves per warp
    #pragma unroll
    for (int half = 0; half < 2; half++) {
        float c3[2][2][4] = {};
        int cb = wn * 32 + half * 16;
        wgemm_v<2, 2, 8, 16>(c3, sX + rowb * 68, 68, g_We1p + cb * 64, g, qt);
        #pragma unroll
        for (int tm = 0; tm < 2; tm++)
            #pragma unroll
            for (int j = 0; j < 2; j++) {
                int col = cb + j * 8 + 2 * qt;
                float bb0 = b_e1[col], bb1 = b_e1[col + 1];
                #pragma unroll
                for (int hf = 0; hf < 2; hf++) {
                    int r = rowb + tm * 16 + g + hf * 8;
                    float v0 = c3[tm][j][hf * 2 + 0] + bb0;
                    float v1 = c3[tm][j][hf * 2 + 1] + bb1;
                    v0 = v0 > 0.f ? v0 : __expf(v0) - 1.f;
                    v1 = v1 > 0.f ? v1 : __expf(v1) - 1.f;
                    float2 tv; tv.x = to_tf32(v0); tv.y = to_tf32(v1);
                    *(float2*)&sT[r * 132 + col] = tv;
                }
            }
    }
    __syncthreads();

    // Pg: GEMM4  e_out = T @ W_e2 + b + e2(regs)
    {
        float c4[2][2][4] = {};
        wgemm_v<2, 2, 16, 32>(c4, sT + rowb * 132, 132, g_We2p + (wn * 16) * 128, g, qt);
        #pragma unroll
        for (int tm = 0; tm < 2; tm++)
            #pragma unroll
            for (int j = 0; j < 2; j++) {
                int col = wn * 16 + j * 8 + 2 * qt;
                float bz0 = b_e2[col], bz1 = b_e2[col + 1];
                #pragma unroll
                for (int hf = 0; hf < 2; hf++) {
                    int r = rowb + tm * 16 + g + hf * 8;
                    float2 ov;
                    ov.x = c4[tm][j][hf * 2 + 0] + bz0 + e2r[tm][j][hf * 2 + 0];
                    ov.y = c4[tm][j][hf * 2 + 1] + bz1 + e2r[tm][j][hf * 2 + 1];
                    *(float2*)&e_out[(R0 + r) * 64 + col] = ov;
                }
            }
    }
}

// ---------------- softmax + gated V accumulation: one block per (b,l) ----------
__global__ void __launch_bounds__(256) eb_kernel()
{
    __shared__ float sH[256 * 36];
    __shared__ float sRed[256];
    __shared__ float sRed2[256];

    int tid = threadIdx.x;
    int bl  = blockIdx.x;
    int b   = bl >> 8;

    const float4* Hg = (const float4*)(g_H + (size_t)bl * 8192);
    #pragma unroll
    for (int i = 0; i < 8; i++) {
        int idx = tid + i * 256;
        int m = idx >> 3, c4 = idx & 7;
        *(float4*)&sH[m * 36 + c4 * 4] = Hg[idx];
    }
    __syncthreads();

    int h = tid & 31, grp = tid >> 5;
    float pmax = -1e30f;
    for (int mm = 0; mm < 32; mm++) {
        int m = grp * 32 + mm;
        pmax = fmaxf(pmax, sH[m * 36 + h]);
    }
    sRed[grp * 32 + h] = pmax;
    __syncthreads();
    float M = -1e30f;
    #pragma unroll
    for (int gg = 0; gg < 8; gg++) M = fmaxf(M, sRed[gg * 32 + h]);

    const float* gate = g_gate + (size_t)bl * 8192;
    float ssum = 0.f;
    for (int mm = 0; mm < 32; mm++) {
        int m = grp * 32 + mm;
        float wv = __expf(sH[m * 36 + h] - M);
        ssum += wv;
        sH[m * 36 + h] = wv * gate[m * 32 + h];
    }
    sRed2[grp * 32 + h] = ssum;
    __syncthreads();
    float S = 0.f;
    #pragma unroll
    for (int gg = 0; gg < 8; gg++) S += sRed2[gg * 32 + h];
    float inv = 1.f / S;

    int k0 = grp * 2;
    float a0 = 0.f, a1 = 0.f;
    const float* Vb = g_qkv + (size_t)(b * 256) * 1536 + 1024 + k0 * 32 + h;
    #pragma unroll 8
    for (int m = 0; m < 256; m++) {
        float wv = sH[m * 36 + h];
        const float* Vp = Vb + (size_t)m * 1536;
        a0 += wv * Vp[0];
        a1 += wv * Vp[32];
    }
    g_vatt[(size_t)bl * 512 + k0 * 32 + h]       = a0 * inv;
    g_vatt[(size_t)bl * 512 + (k0 + 1) * 32 + h] = a1 * inv;
}

// ---------------- launch ----------------
extern "C" void kernel_launch(void* const* d_in, const int* in_sizes, int n_in,
                              void* d_out, int out_size)
{
    const float* h         = (const float*)d_in[0];
    const float* e         = (const float*)d_in[1];
    const float* mask      = (const float*)d_in[2];
    const float* ln_h_g    = (const float*)d_in[3];
    const float* ln_h_b    = (const float*)d_in[4];
    const float* ln_e_g    = (const float*)d_in[5];
    const float* ln_e_b    = (const float*)d_in[6];
    const float* ffn_ln_h_g= (const float*)d_in[7];
    const float* ffn_ln_h_b= (const float*)d_in[8];
    const float* ffn_ln_e_g= (const float*)d_in[9];
    const float* ffn_ln_e_b= (const float*)d_in[10];
    const float* W_qkv     = (const float*)d_in[11];
    const float* b_qkv     = (const float*)d_in[12];
    const float* W_E       = (const float*)d_in[13];
    const float* b_E       = (const float*)d_in[14];
    const float* W_G       = (const float*)d_in[15];
    const float* b_G       = (const float*)d_in[16];
    const float* W_Oh      = (const float*)d_in[17];
    const float* b_Oh      = (const float*)d_in[18];
    const float* W_h1      = (const float*)d_in[19];
    const float* b_h1      = (const float*)d_in[20];
    const float* W_h2      = (const float*)d_in[21];
    const float* b_h2      = (const float*)d_in[22];
    const float* W_Oe      = (const float*)d_in[23];
    const float* b_Oe      = (const float*)d_in[24];
    const float* W_e1      = (const float*)d_in[25];
    const float* b_e1      = (const float*)d_in[26];
    const float* W_e2      = (const float*)d_in[27];
    const float* b_e2      = (const float*)d_in[28];

    float* h_out = (float*)d_out;
    float* e_out = (float*)d_out + (size_t)ROWS * DNn;

    float *p_hln, *p_qkv, *p_vatt, *p_h2, *p_hff, *p_t;
    cudaGetSymbolAddress((void**)&p_hln,  g_hln);
    cudaGetSymbolAddress((void**)&p_qkv,  g_qkv);
    cudaGetSymbolAddress((void**)&p_vatt, g_vatt);
    cudaGetSymbolAddress((void**)&p_h2,   g_h2);
    cudaGetSymbolAddress((void**)&p_hff,  g_hff);
    cudaGetSymbolAddress((void**)&p_t,    g_t);

    cudaFuncSetAttribute(ea_kernel, cudaFuncAttributeMaxDynamicSharedMemorySize,
                         EA_SMEM_BYTES);
    cudaFuncSetAttribute(tgemm<0>, cudaFuncAttributeMaxDynamicSharedMemorySize,
                         TG_SMEM_BYTES);
    cudaFuncSetAttribute(tgemm<1>, cudaFuncAttributeMaxDynamicSharedMemorySize,
                         TG_SMEM_BYTES);
    cudaFuncSetAttribute(tgemm<2>, cudaFuncAttributeMaxDynamicSharedMemorySize,
                         TG_SMEM_BYTES);

    // 0) pack edge weights to residue-packed tf32 globals
    pack_weights<<<88, 256>>>(W_E, W_G, W_Oe, W_e1, W_e2);
    // 1) h_ln
    ln512_kernel<<<ROWS, 128>>>(h, ln_h_g, ln_h_b, p_hln);
    // 2) QKV = h_ln @ W_qkv + b_qkv   (tf32)
    tgemm<0><<<dim3(1536/64, ROWS/128), 256, TG_SMEM_BYTES>>>(p_hln, W_qkv, p_qkv,
                                               b_qkv, nullptr, ROWS, 1536, 512);
    // 3) edge pipeline (writes e_out, g_H(+mask), g_gate)
    ea_kernel<<<ROWS * 4, 256, EA_SMEM_BYTES>>>(e, mask, ln_e_g, ln_e_b,
        ffn_ln_e_g, ffn_ln_e_b, b_E, b_G, b_Oe, b_e1, b_e2, e_out);
    // 4) softmax + gated V accumulation (writes g_vatt)
    eb_kernel<<<ROWS, 256>>>();
    // 5) h2 = V_att @ W_Oh + b + h
    tgemm<1><<<dim3(512/64, ROWS/128), 256, TG_SMEM_BYTES>>>(p_vatt, W_Oh, p_h2,
                                              b_Oh, h, ROWS, 512, 512);
    // 6) h_ff = LN(h2)
    ln512_kernel<<<ROWS, 128>>>(p_h2, ffn_ln_h_g, ffn_ln_h_b, p_hff);
    // 7) t = elu(h_ff @ W_h1 + b)
    tgemm<2><<<dim3(1024/64, ROWS/128), 256, TG_SMEM_BYTES>>>(p_hff, W_h1, p_t,
                                               b_h1, nullptr, ROWS, 1024, 512);
    // 8) h_out = t @ W_h2 + b + h2
    tgemm<1><<<dim3(512/64, ROWS/128), 256, TG_SMEM_BYTES>>>(p_t, W_h2, h_out,
                                              b_h2, p_h2, ROWS, 512, 1024);
}

// round 6
// speedup vs baseline: 4.3527x; 1.5508x over previous
#include <cuda_runtime.h>
#include <cuda_bf16.h>
#include <math.h>
#include <stdint.h>

#define DEV_INLINE __device__ __forceinline__

constexpr int Bn = 32, Ln = 256, DNn = 512;
constexpr int ROWS = Bn * Ln;            // 8192 (b,l) rows
constexpr int EROWS = ROWS * Ln;         // 2,097,152 edge rows
constexpr int FNn = 1024;
constexpr float EPSc = 1e-5f;

// ---------------- device scratch ----------------
__device__ float g_hln[ROWS * DNn];
__device__ float g_qkv[ROWS * 3 * DNn];
__device__ float g_vatt[ROWS * DNn];
__device__ float g_h2[ROWS * DNn];
__device__ float g_hff[ROWS * DNn];
__device__ float g_t[ROWS * FNn];
__device__ float g_H[(size_t)EROWS * 32];     // H_hat + mask (fp32)
__device__ float g_gate[(size_t)EROWS * 32];  // sigmoid(G+mask)
// bf16 fragment-packed edge weights (see packB) and bf16 K copy
__device__ __nv_bfloat16 g_WEGb[64 * 64];
__device__ __nv_bfloat16 g_WOeb[32 * 64];
__device__ __nv_bfloat16 g_We1b[64 * 128];
__device__ __nv_bfloat16 g_We2b[128 * 64];
__device__ __nv_bfloat162 g_kb[(size_t)ROWS * 256];   // [(row)*256 + dp*32 + h]

DEV_INLINE float to_tf32(float x) {
    float y;
    asm("cvt.rna.tf32.f32 %0, %1;" : "=f"(y) : "f"(x));
    return y;
}

DEV_INLINE void mma8(float c[4], uint32_t a0, uint32_t a1, uint32_t a2, uint32_t a3,
                     uint32_t b0, uint32_t b1)
{
    asm volatile(
        "mma.sync.aligned.m16n8k8.row.col.f32.tf32.tf32.f32 "
        "{%0,%1,%2,%3},{%4,%5,%6,%7},{%8,%9},{%0,%1,%2,%3};"
        : "+f"(c[0]), "+f"(c[1]), "+f"(c[2]), "+f"(c[3])
        : "r"(a0), "r"(a1), "r"(a2), "r"(a3), "r"(b0), "r"(b1));
}

DEV_INLINE void mma16(float c[4], uint32_t a0, uint32_t a1, uint32_t a2, uint32_t a3,
                      uint32_t b0, uint32_t b1)
{
    asm volatile(
        "mma.sync.aligned.m16n8k16.row.col.f32.bf16.bf16.f32 "
        "{%0,%1,%2,%3},{%4,%5,%6,%7},{%8,%9},{%0,%1,%2,%3};"
        : "+f"(c[0]), "+f"(c[1]), "+f"(c[2]), "+f"(c[3])
        : "r"(a0), "r"(a1), "r"(a2), "r"(a3), "r"(b0), "r"(b1));
}

// smem-B tf32 warp GEMM (h-path)
template<int NTW, int KS>
DEV_INLINE void wgemm(float c[NTW][4], const float* __restrict__ Arow, int lda,
                      const float* __restrict__ Bcol, int ldb, int g, int qt)
{
    #pragma unroll
    for (int ks = 0; ks < KS; ks++) {
        int k = ks * 8;
        uint32_t a0 = __float_as_uint(Arow[(g)     * lda + k + qt]);
        uint32_t a1 = __float_as_uint(Arow[(g + 8) * lda + k + qt]);
        uint32_t a2 = __float_as_uint(Arow[(g)     * lda + k + qt + 4]);
        uint32_t a3 = __float_as_uint(Arow[(g + 8) * lda + k + qt + 4]);
        #pragma unroll
        for (int j = 0; j < NTW; j++) {
            uint32_t b0 = __float_as_uint(Bcol[(k + qt)     * ldb + j * 8 + g]);
            uint32_t b1 = __float_as_uint(Bcol[(k + qt + 4) * ldb + j * 8 + g]);
            mma8(c[j], a0, a1, a2, a3, b0, b1);
        }
    }
}

// bf16 warp GEMM, m16n8k16. A in smem as u32 (bf16x2), sb2 = u32 words per row.
// Bp = packed weights (u32 view) pre-offset by warp col base (cb*16).
// S = number of 16-wide k-steps. N = full output width of the packed weight.
template<int TM, int NTW, int S, int N>
DEV_INLINE void wgemm_b(float c[TM][NTW][4], const uint32_t* __restrict__ As, int sb2,
                        const uint32_t* __restrict__ Bp, int g, int qt)
{
    #pragma unroll
    for (int t = 0; t < (S + 1) / 2; t++) {
        uint4 bq[NTW];
        #pragma unroll
        for (int j = 0; j < NTW; j++)
            bq[j] = *(const uint4*)&Bp[(t * (N * 4) + (j * 8 + g) * 4 + qt) * 4];
        #pragma unroll
        for (int se = 0; se < 2; se++) {
            int s = 2 * t + se;
            if (s >= S) break;
            #pragma unroll
            for (int tm = 0; tm < TM; tm++) {
                const uint32_t* Ar = As + tm * 16 * sb2;
                uint32_t a0 = Ar[(g)     * sb2 + 8 * s + qt];
                uint32_t a2 = Ar[(g)     * sb2 + 8 * s + qt + 4];
                uint32_t a1 = Ar[(g + 8) * sb2 + 8 * s + qt];
                uint32_t a3 = Ar[(g + 8) * sb2 + 8 * s + qt + 4];
                #pragma unroll
                for (int j = 0; j < NTW; j++) {
                    uint32_t b0 = se ? bq[j].z : bq[j].x;
                    uint32_t b1 = se ? bq[j].w : bq[j].y;
                    mma16(c[tm][j], a0, a1, a2, a3, b0, b1);
                }
            }
        }
    }
}

// bf16 fragment pack index: element (k,n) of a KxN col-fragment weight.
DEV_INLINE int packB(int n, int k, int N) {
    int p = k >> 1, lo = k & 1;
    int qt = p & 3, half = (p >> 2) & 1, s = p >> 3;
    int t = s >> 1, se = s & 1;
    int u32i = (t * (N * 4) + n * 4 + qt) * 4 + se * 2 + half;
    return u32i * 2 + lo;
}

__global__ void pack_weights(const float* __restrict__ W_E, const float* __restrict__ W_G,
                             const float* __restrict__ W_Oe, const float* __restrict__ W_e1,
                             const float* __restrict__ W_e2)
{
    int i = blockIdx.x * 256 + threadIdx.x;
    if (i < 4096) {                       // WEG: K=64, N=64
        int k = i >> 6, n = i & 63;
        float v = n < 32 ? W_E[k * 32 + n] : W_G[k * 32 + n - 32];
        g_WEGb[packB(n, k, 64)] = __float2bfloat16(v);
    } else if (i < 6144) {                // WOe: K=32, N=64
        int j = i - 4096; int k = j >> 6, n = j & 63;
        g_WOeb[packB(n, k, 64)] = __float2bfloat16(W_Oe[j]);
    } else if (i < 14336) {               // We1: K=64, N=128
        int j = i - 6144; int k = j >> 7, n = j & 127;
        g_We1b[packB(n, k, 128)] = __float2bfloat16(W_e1[j]);
    } else if (i < 22528) {               // We2: K=128, N=64
        int j = i - 14336; int k = j >> 6, n = j & 63;
        g_We2b[packB(n, k, 64)] = __float2bfloat16(W_e2[j]);
    }
}

// K -> interleaved bf16 pairs: g_kb[row*256 + dp*32 + h] = (K[2dp][h], K[2dp+1][h])
__global__ void kconv_kernel()
{
    int idx = blockIdx.x * 256 + threadIdx.x;
    int row = idx >> 8, t = idx & 255;
    int dp = t >> 5, h = t & 31;
    const float* base = g_qkv + (size_t)row * 1536 + 512 + dp * 64 + h;
    g_kb[idx] = __floats2bfloat162_rn(base[0], base[32]);
}

// ---------------- LayerNorm over 512, one block per row ----------------
__global__ void __launch_bounds__(128) ln512_kernel(
    const float* __restrict__ x, const float* __restrict__ g,
    const float* __restrict__ b, float* __restrict__ y)
{
    int row = blockIdx.x, tid = threadIdx.x;
    const float4* xr = (const float4*)(x + (size_t)row * 512);
    float4 v = xr[tid];
    float s  = v.x + v.y + v.z + v.w;
    float s2 = v.x*v.x + v.y*v.y + v.z*v.z + v.w*v.w;
    #pragma unroll
    for (int o = 16; o; o >>= 1) {
        s  += __shfl_xor_sync(0xffffffffu, s,  o);
        s2 += __shfl_xor_sync(0xffffffffu, s2, o);
    }
    __shared__ float aS[4], aS2[4];
    if ((tid & 31) == 0) { aS[tid >> 5] = s; aS2[tid >> 5] = s2; }
    __syncthreads();
    s  = aS[0] + aS[1] + aS[2] + aS[3];
    s2 = aS2[0] + aS2[1] + aS2[2] + aS2[3];
    float mean = s * (1.f / 512.f);
    float rstd = rsqrtf(s2 * (1.f / 512.f) - mean * mean + EPSc);
    int c = tid * 4;
    float4 gv = *(const float4*)(g + c);
    float4 bv = *(const float4*)(b + c);
    float4 o;
    o.x = (v.x - mean) * rstd * gv.x + bv.x;
    o.y = (v.y - mean) * rstd * gv.y + bv.y;
    o.z = (v.z - mean) * rstd * gv.z + bv.z;
    o.w = (v.w - mean) * rstd * gv.w + bv.w;
    ((float4*)(y + (size_t)row * 512))[tid] = o;
}

// ---------------- tf32 tensor GEMM for h-path (unchanged) ----------------
constexpr int TG_SMEM_BYTES = (128 * 68 + 64 * 72) * 4;   // 53248
template<int MODE>
__global__ void __launch_bounds__(256) tgemm(
    const float* __restrict__ A, const float* __restrict__ B, float* __restrict__ C,
    const float* __restrict__ bias, const float* __restrict__ res,
    int M, int N, int K)
{
    extern __shared__ float ts[];
    float* As = ts;              // 128 x 68
    float* Bs = ts + 128 * 68;   // 64 x 72
    int tid = threadIdx.x;
    int row0 = blockIdx.y * 128, col0 = blockIdx.x * 64;
    int w = tid >> 5;
    int g = (tid & 31) >> 2, qt = tid & 3;
    float acc[8][4] = {};

    for (int k0 = 0; k0 < K; k0 += 64) {
        #pragma unroll
        for (int i = 0; i < 8; i++) {
            int idx = tid + i * 256;
            int r = idx >> 4, c4 = idx & 15;
            float4 v = *(const float4*)&A[(size_t)(row0 + r) * K + k0 + c4 * 4];
            float4 t;
            t.x = to_tf32(v.x); t.y = to_tf32(v.y); t.z = to_tf32(v.z); t.w = to_tf32(v.w);
            *(float4*)&As[r * 68 + c4 * 4] = t;
        }
        #pragma unroll
        for (int i = 0; i < 4; i++) {
            int idx = tid + i * 256;
            int r = idx >> 4, c4 = idx & 15;
            float4 v = *(const float4*)&B[(size_t)(k0 + r) * N + col0 + c4 * 4];
            float4 t;
            t.x = to_tf32(v.x); t.y = to_tf32(v.y); t.z = to_tf32(v.z); t.w = to_tf32(v.w);
            *(float4*)&Bs[r * 72 + c4 * 4] = t;
        }
        __syncthreads();
        wgemm<8, 8>(acc, As + w * 16 * 68, 68, Bs, 72, g, qt);
        __syncthreads();
    }
    #pragma unroll
    for (int j = 0; j < 8; j++) {
        int col = col0 + j * 8 + 2 * qt;
        #pragma unroll
        for (int hf = 0; hf < 2; hf++) {
            int r = row0 + w * 16 + g + hf * 8;
            float v0 = acc[j][hf * 2 + 0] + bias[col];
            float v1 = acc[j][hf * 2 + 1] + bias[col + 1];
            if (MODE == 1) {
                float2 rv = *(const float2*)&res[(size_t)r * N + col];
                v0 += rv.x; v1 += rv.y;
            }
            if (MODE == 2) {
                v0 = v0 > 0.f ? v0 : __expf(v0) - 1.f;
                v1 = v1 > 0.f ? v1 : __expf(v1) - 1.f;
            }
            float2 ov; ov.x = v0; ov.y = v1;
            *(float2*)&C[(size_t)r * N + col] = ov;
        }
    }
}

// LN of 64 rows x 64 cols: fp32 src (stride sstr) -> bf16x2 dst (dsb2 u32/row).
DEV_INLINE void ln64b(const float* __restrict__ src, int sstr, uint32_t* __restrict__ dst,
                      int dsb2, const float* __restrict__ gam,
                      const float* __restrict__ bet, int tid)
{
    int r = tid >> 2, sub = tid & 3;
    const float* p = src + r * sstr + sub * 16;
    float x[16]; float s = 0.f, s2 = 0.f;
    #pragma unroll
    for (int i = 0; i < 16; i += 4) {
        float4 v = *(const float4*)(p + i);
        x[i] = v.x; x[i+1] = v.y; x[i+2] = v.z; x[i+3] = v.w;
    }
    #pragma unroll
    for (int i = 0; i < 16; i++) { s += x[i]; s2 += x[i] * x[i]; }
    s  += __shfl_xor_sync(0xffffffffu, s, 1);  s  += __shfl_xor_sync(0xffffffffu, s, 2);
    s2 += __shfl_xor_sync(0xffffffffu, s2, 1); s2 += __shfl_xor_sync(0xffffffffu, s2, 2);
    float mean = s * (1.f / 64.f);
    float rstd = rsqrtf(s2 * (1.f / 64.f) - mean * mean + EPSc);
    uint32_t* d = dst + r * dsb2 + sub * 8;
    #pragma unroll
    for (int i = 0; i < 16; i += 2) {
        int c = sub * 16 + i;
        float y0 = (x[i]     - mean) * rstd * gam[c]     + bet[c];
        float y1 = (x[i + 1] - mean) * rstd * gam[c + 1] + bet[c + 1];
        __nv_bfloat162 h2 = __floats2bfloat162_rn(y0, y1);
        d[i >> 1] = *(uint32_t*)&h2;
    }
}

// ---------------- edge pipeline: 64 rows/CTA, 256 threads, 3 CTA/SM ------------
constexpr int EA_SMEM_BYTES = (4352 + 2176 + 2304 + 1280 + 4352) * 4;  // 57856

__global__ void __launch_bounds__(256, 3) ea_kernel(
    const float* __restrict__ e, const float* __restrict__ mask,
    const float* __restrict__ lng, const float* __restrict__ lnb,
    const float* __restrict__ flg, const float* __restrict__ flb,
    const float* __restrict__ b_E,  const float* __restrict__ b_G,
    const float* __restrict__ b_Oe, const float* __restrict__ b_e1,
    const float* __restrict__ b_e2,
    float* __restrict__ e_out)
{
    extern __shared__ float sm[];
    float*    sX  = sm;                          // 64 x 68 fp32 (e2 residual)
    float*    sAf = sm + 4352;                   // 64 x 34 fp32 (A_hat)
    uint32_t* sXb = (uint32_t*)(sm + 6528);      // 64 x 36 u32 (eln/eff bf16x2)
    uint32_t* sAb = (uint32_t*)(sm + 8832);      // 64 x 20 u32 (H bf16x2)
    uint32_t* sTb = (uint32_t*)(sm + 10112);     // 64 x 68 u32 (T bf16x2)

    int tid = threadIdx.x;
    int blk = blockIdx.x;
    int bl  = blk >> 2, quad = blk & 3;
    int b   = bl >> 8;
    int m0  = quad * 64;
    size_t R0 = (size_t)bl * 256 + m0;

    int w   = tid >> 5;
    int wm2 = w >> 2, wn = w & 3;       // rows wm2*32, col quarter wn
    int g   = (tid & 31) >> 2, qt = tid & 3;
    int rowb = wm2 * 32;

    const uint32_t* WEGu = (const uint32_t*)g_WEGb;
    const uint32_t* WOeu = (const uint32_t*)g_WOeb;
    const uint32_t* We1u = (const uint32_t*)g_We1b;
    const uint32_t* We2u = (const uint32_t*)g_We2b;

    // Pa: LN(e) from global -> sXb (bf16)
    ln64b(e + R0 * 64, 64, sXb, 36, lng, lnb, tid);
    __syncthreads();

    // Pb: QK (bf16 K) -> sAf  +  GEMM1 (E|G)
    {
        int h = tid & 31, mr = tid >> 5;
        float q[16];
        const float* Qp = g_qkv + (size_t)bl * 1536 + h;
        #pragma unroll
        for (int d = 0; d < 16; d++) q[d] = Qp[d * 32];
        const __nv_bfloat162* Kb = g_kb + ((size_t)(b * 256) + m0) * 256 + h;
        #pragma unroll
        for (int rr = 0; rr < 8; rr++) {
            int ml = mr + rr * 8;
            const __nv_bfloat162* Kp = Kb + (size_t)ml * 256;
            float a = 0.f;
            #pragma unroll
            for (int dp = 0; dp < 8; dp++) {
                float2 kv = __bfloat1622float2(Kp[dp * 32]);
                a += q[2 * dp] * kv.x + q[2 * dp + 1] * kv.y;
            }
            sAf[ml * 34 + h] = a * 0.25f;
        }
    }
    float c1[2][2][4] = {};
    wgemm_b<2, 2, 4, 64>(c1, sXb + rowb * 36, 36, WEGu + wn * 256, g, qt);
    __syncthreads();

    // Pc: epilogue — wn<2: H (cols 0..31) -> g_H + sAb ; wn>=2: gate -> g_gate
    {
        #pragma unroll
        for (int tm = 0; tm < 2; tm++) {
            float mk0 = mask[(size_t)bl * 256 + m0 + rowb + tm * 16 + g];
            float mk1 = mask[(size_t)bl * 256 + m0 + rowb + tm * 16 + g + 8];
            #pragma unroll
            for (int j = 0; j < 2; j++) {
                int colg = wn * 16 + j * 8 + 2 * qt;
                if (wn < 2) {
                    int col = colg;
                    float bv0 = b_E[col], bv1 = b_E[col + 1];
                    #pragma unroll
                    for (int hf = 0; hf < 2; hf++) {
                        int r = rowb + tm * 16 + g + hf * 8;
                        float A0 = sAf[r * 34 + col], A1 = sAf[r * 34 + col + 1];
                        float H0 = fminf(fmaxf(A0, -5.f), 5.f) + c1[tm][j][hf * 2 + 0] + bv0;
                        float H1 = fminf(fmaxf(A1, -5.f), 5.f) + c1[tm][j][hf * 2 + 1] + bv1;
                        float mk = hf ? mk1 : mk0;
                        float2 hw; hw.x = H0 + mk; hw.y = H1 + mk;
                        *(float2*)&g_H[(R0 + r) * 32 + col] = hw;
                        __nv_bfloat162 hb = __floats2bfloat162_rn(H0, H1);
                        sAb[r * 20 + (col >> 1)] = *(uint32_t*)&hb;
                    }
                } else {
                    int col = colg - 32;
                    float bv0 = b_G[col], bv1 = b_G[col + 1];
                    #pragma unroll
                    for (int hf = 0; hf < 2; hf++) {
                        int r = rowb + tm * 16 + g + hf * 8;
                        float mk = hf ? mk1 : mk0;
                        float2 gw;
                        gw.x = 1.f / (1.f + __expf(-(c1[tm][j][hf * 2 + 0] + bv0 + mk)));
                        gw.y = 1.f / (1.f + __expf(-(c1[tm][j][hf * 2 + 1] + bv1 + mk)));
                        *(float2*)&g_gate[(R0 + r) * 32 + col] = gw;
                    }
                }
            }
        }
    }
    __syncthreads();

    // Pd: GEMM2  e2 = H @ W_Oe + b + e   (regs + sX fp32)
    float e2r[2][2][4];
    {
        float c2[2][2][4] = {};
        wgemm_b<2, 2, 2, 64>(c2, sAb + rowb * 20, 20, WOeu + wn * 256, g, qt);
        #pragma unroll
        for (int tm = 0; tm < 2; tm++)
            #pragma unroll
            for (int j = 0; j < 2; j++) {
                int col = wn * 16 + j * 8 + 2 * qt;
                float bo0 = b_Oe[col], bo1 = b_Oe[col + 1];
                #pragma unroll
                for (int hf = 0; hf < 2; hf++) {
                    int r = rowb + tm * 16 + g + hf * 8;
                    float2 ev = *(const float2*)&e[(R0 + r) * 64 + col];
                    float v0 = c2[tm][j][hf * 2 + 0] + bo0 + ev.x;
                    float v1 = c2[tm][j][hf * 2 + 1] + bo1 + ev.y;
                    e2r[tm][j][hf * 2 + 0] = v0;
                    e2r[tm][j][hf * 2 + 1] = v1;
                    sX[r * 68 + col]     = v0;
                    sX[r * 68 + col + 1] = v1;
                }
            }
    }
    __syncthreads();

    // Pe: LN(e2) -> sXb (bf16 eff)
    ln64b(sX, 68, sXb, 36, flg, flb, tid);
    __syncthreads();

    // Pf: GEMM3  T = elu(eff @ W_e1 + b) -> sTb, two 16-col halves per warp
    #pragma unroll
    for (int half = 0; half < 2; half++) {
        float c3[2][2][4] = {};
        int cb = wn * 32 + half * 16;
        wgemm_b<2, 2, 4, 128>(c3, sXb + rowb * 36, 36, We1u + cb * 16, g, qt);
        #pragma unroll
        for (int tm = 0; tm < 2; tm++)
            #pragma unroll
            for (int j = 0; j < 2; j++) {
                int col = cb + j * 8 + 2 * qt;
                float bb0 = b_e1[col], bb1 = b_e1[col + 1];
                #pragma unroll
                for (int hf = 0; hf < 2; hf++) {
                    int r = rowb + tm * 16 + g + hf * 8;
                    float v0 = c3[tm][j][hf * 2 + 0] + bb0;
                    float v1 = c3[tm][j][hf * 2 + 1] + bb1;
                    v0 = v0 > 0.f ? v0 : __expf(v0) - 1.f;
                    v1 = v1 > 0.f ? v1 : __expf(v1) - 1.f;
                    __nv_bfloat162 tb = __floats2bfloat162_rn(v0, v1);
                    sTb[r * 68 + (col >> 1)] = *(uint32_t*)&tb;
                }
            }
    }
    __syncthreads();

    // Pg: GEMM4  e_out = T @ W_e2 + b + e2(regs)
    {
        float c4[2][2][4] = {};
        wgemm_b<2, 2, 8, 64>(c4, sTb + rowb * 68, 68, We2u + wn * 256, g, qt);
        #pragma unroll
        for (int tm = 0; tm < 2; tm++)
            #pragma unroll
            for (int j = 0; j < 2; j++) {
                int col = wn * 16 + j * 8 + 2 * qt;
                float bz0 = b_e2[col], bz1 = b_e2[col + 1];
                #pragma unroll
                for (int hf = 0; hf < 2; hf++) {
                    int r = rowb + tm * 16 + g + hf * 8;
                    float2 ov;
                    ov.x = c4[tm][j][hf * 2 + 0] + bz0 + e2r[tm][j][hf * 2 + 0];
                    ov.y = c4[tm][j][hf * 2 + 1] + bz1 + e2r[tm][j][hf * 2 + 1];
                    *(float2*)&e_out[(R0 + r) * 64 + col] = ov;
                }
            }
    }
}

// ---------------- softmax + gated V accumulation: one block per (b,l) ----------
__global__ void __launch_bounds__(256) eb_kernel()
{
    __shared__ float sH[256 * 36];
    __shared__ float sRed[256];
    __shared__ float sRed2[256];

    int tid = threadIdx.x;
    int bl  = blockIdx.x;
    int b   = bl >> 8;

    const float4* Hg = (const float4*)(g_H + (size_t)bl * 8192);
    #pragma unroll
    for (int i = 0; i < 8; i++) {
        int idx = tid + i * 256;
        int m = idx >> 3, c4 = idx & 7;
        *(float4*)&sH[m * 36 + c4 * 4] = Hg[idx];
    }
    __syncthreads();

    int h = tid & 31, grp = tid >> 5;
    float pmax = -1e30f;
    for (int mm = 0; mm < 32; mm++) {
        int m = grp * 32 + mm;
        pmax = fmaxf(pmax, sH[m * 36 + h]);
    }
    sRed[grp * 32 + h] = pmax;
    __syncthreads();
    float M = -1e30f;
    #pragma unroll
    for (int gg = 0; gg < 8; gg++) M = fmaxf(M, sRed[gg * 32 + h]);

    const float* gate = g_gate + (size_t)bl * 8192;
    float ssum = 0.f;
    for (int mm = 0; mm < 32; mm++) {
        int m = grp * 32 + mm;
        float wv = __expf(sH[m * 36 + h] - M);
        ssum += wv;
        sH[m * 36 + h] = wv * gate[m * 32 + h];
    }
    sRed2[grp * 32 + h] = ssum;
    __syncthreads();
    float S = 0.f;
    #pragma unroll
    for (int gg = 0; gg < 8; gg++) S += sRed2[gg * 32 + h];
    float inv = 1.f / S;

    int k0 = grp * 2;
    float a0 = 0.f, a1 = 0.f;
    const float* Vb = g_qkv + (size_t)(b * 256) * 1536 + 1024 + k0 * 32 + h;
    #pragma unroll 8
    for (int m = 0; m < 256; m++) {
        float wv = sH[m * 36 + h];
        const float* Vp = Vb + (size_t)m * 1536;
        a0 += wv * Vp[0];
        a1 += wv * Vp[32];
    }
    g_vatt[(size_t)bl * 512 + k0 * 32 + h]       = a0 * inv;
    g_vatt[(size_t)bl * 512 + (k0 + 1) * 32 + h] = a1 * inv;
}

// ---------------- launch ----------------
extern "C" void kernel_launch(void* const* d_in, const int* in_sizes, int n_in,
                              void* d_out, int out_size)
{
    const float* h         = (const float*)d_in[0];
    const float* e         = (const float*)d_in[1];
    const float* mask      = (const float*)d_in[2];
    const float* ln_h_g    = (const float*)d_in[3];
    const float* ln_h_b    = (const float*)d_in[4];
    const float* ln_e_g    = (const float*)d_in[5];
    const float* ln_e_b    = (const float*)d_in[6];
    const float* ffn_ln_h_g= (const float*)d_in[7];
    const float* ffn_ln_h_b= (const float*)d_in[8];
    const float* ffn_ln_e_g= (const float*)d_in[9];
    const float* ffn_ln_e_b= (const float*)d_in[10];
    const float* W_qkv     = (const float*)d_in[11];
    const float* b_qkv     = (const float*)d_in[12];
    const float* W_E       = (const float*)d_in[13];
    const float* b_E       = (const float*)d_in[14];
    const float* W_G       = (const float*)d_in[15];
    const float* b_G       = (const float*)d_in[16];
    const float* W_Oh      = (const float*)d_in[17];
    const float* b_Oh      = (const float*)d_in[18];
    const float* W_h1      = (const float*)d_in[19];
    const float* b_h1      = (const float*)d_in[20];
    const float* W_h2      = (const float*)d_in[21];
    const float* b_h2      = (const float*)d_in[22];
    const float* W_Oe      = (const float*)d_in[23];
    const float* b_Oe      = (const float*)d_in[24];
    const float* W_e1      = (const float*)d_in[25];
    const float* b_e1      = (const float*)d_in[26];
    const float* W_e2      = (const float*)d_in[27];
    const float* b_e2      = (const float*)d_in[28];

    float* h_out = (float*)d_out;
    float* e_out = (float*)d_out + (size_t)ROWS * DNn;

    float *p_hln, *p_qkv, *p_vatt, *p_h2, *p_hff, *p_t;
    cudaGetSymbolAddress((void**)&p_hln,  g_hln);
    cudaGetSymbolAddress((void**)&p_qkv,  g_qkv);
    cudaGetSymbolAddress((void**)&p_vatt, g_vatt);
    cudaGetSymbolAddress((void**)&p_h2,   g_h2);
    cudaGetSymbolAddress((void**)&p_hff,  g_hff);
    cudaGetSymbolAddress((void**)&p_t,    g_t);

    cudaFuncSetAttribute(ea_kernel, cudaFuncAttributeMaxDynamicSharedMemorySize,
                         EA_SMEM_BYTES);
    cudaFuncSetAttribute(tgemm<0>, cudaFuncAttributeMaxDynamicSharedMemorySize,
                         TG_SMEM_BYTES);
    cudaFuncSetAttribute(tgemm<1>, cudaFuncAttributeMaxDynamicSharedMemorySize,
                         TG_SMEM_BYTES);
    cudaFuncSetAttribute(tgemm<2>, cudaFuncAttributeMaxDynamicSharedMemorySize,
                         TG_SMEM_BYTES);

    // 0) pack edge weights (bf16 fragments)
    pack_weights<<<88, 256>>>(W_E, W_G, W_Oe, W_e1, W_e2);
    // 1) h_ln
    ln512_kernel<<<ROWS, 128>>>(h, ln_h_g, ln_h_b, p_hln);
    // 2) QKV = h_ln @ W_qkv + b_qkv   (tf32)
    tgemm<0><<<dim3(1536/64, ROWS/128), 256, TG_SMEM_BYTES>>>(p_hln, W_qkv, p_qkv,
                                               b_qkv, nullptr, ROWS, 1536, 512);
    // 2.5) K -> bf16 interleaved copy
    kconv_kernel<<<ROWS, 256>>>();
    // 3) edge pipeline (writes e_out, g_H(+mask), g_gate)
    ea_kernel<<<ROWS * 4, 256, EA_SMEM_BYTES>>>(e, mask, ln_e_g, ln_e_b,
        ffn_ln_e_g, ffn_ln_e_b, b_E, b_G, b_Oe, b_e1, b_e2, e_out);
    // 4) softmax + gated V accumulation (writes g_vatt)
    eb_kernel<<<ROWS, 256>>>();
    // 5) h2 = V_att @ W_Oh + b + h
    tgemm<1><<<dim3(512/64, ROWS/128), 256, TG_SMEM_BYTES>>>(p_vatt, W_Oh, p_h2,
                                              b_Oh, h, ROWS, 512, 512);
    // 6) h_ff = LN(h2)
    ln512_kernel<<<ROWS, 128>>>(p_h2, ffn_ln_h_g, ffn_ln_h_b, p_hff);
    // 7) t = elu(h_ff @ W_h1 + b)
    tgemm<2><<<dim3(1024/64, ROWS/128), 256, TG_SMEM_BYTES>>>(p_hff, W_h1, p_t,
                                               b_h1, nullptr, ROWS, 1024, 512);
    // 8) h_out = t @ W_h2 + b + h2
    tgemm<1><<<dim3(512/64, ROWS/128), 256, TG_SMEM_BYTES>>>(p_t, W_h2, h_out,
                                              b_h2, p_h2, ROWS, 512, 1024);
}

// round 7
// speedup vs baseline: 4.8110x; 1.1053x over previous
#include <cuda_runtime.h>
#include <cuda_bf16.h>
#include <math.h>
#include <stdint.h>

#define DEV_INLINE __device__ __forceinline__

constexpr int Bn = 32, Ln = 256, DNn = 512;
constexpr int ROWS = Bn * Ln;            // 8192 (b,l) rows
constexpr int EROWS = ROWS * Ln;         // 2,097,152 edge rows
constexpr int FNn = 1024;
constexpr float EPSc = 1e-5f;

// ---------------- device scratch ----------------
__device__ float g_hln[ROWS * DNn];
__device__ float g_qkv[ROWS * 3 * DNn];
__device__ float g_vatt[ROWS * DNn];
__device__ float g_h2[ROWS * DNn];
__device__ float g_hff[ROWS * DNn];
__device__ float g_t[ROWS * FNn];
__device__ uint32_t g_Hb[(size_t)EROWS * 16];     // H_hat + mask, bf16x2
__device__ uint32_t g_gateb[(size_t)EROWS * 16];  // sigmoid(G+mask), bf16x2
// bf16 fragment-packed edge weights (see packB); bf16 K and V copies
__device__ __nv_bfloat16 g_WEGb[64 * 64];
__device__ __nv_bfloat16 g_WOeb[32 * 64];
__device__ __nv_bfloat16 g_We1b[64 * 128];
__device__ __nv_bfloat16 g_We2b[128 * 64];
__device__ __nv_bfloat162 g_kb[(size_t)ROWS * 256];   // [(row)*256 + dp*32 + h]
__device__ __nv_bfloat162 g_vb[(size_t)ROWS * 256];   // [(row)*256 + kp*32 + h]

DEV_INLINE float to_tf32(float x) {
    float y;
    asm("cvt.rna.tf32.f32 %0, %1;" : "=f"(y) : "f"(x));
    return y;
}

DEV_INLINE void mma8(float c[4], uint32_t a0, uint32_t a1, uint32_t a2, uint32_t a3,
                     uint32_t b0, uint32_t b1)
{
    asm volatile(
        "mma.sync.aligned.m16n8k8.row.col.f32.tf32.tf32.f32 "
        "{%0,%1,%2,%3},{%4,%5,%6,%7},{%8,%9},{%0,%1,%2,%3};"
        : "+f"(c[0]), "+f"(c[1]), "+f"(c[2]), "+f"(c[3])
        : "r"(a0), "r"(a1), "r"(a2), "r"(a3), "r"(b0), "r"(b1));
}

DEV_INLINE void mma16(float c[4], uint32_t a0, uint32_t a1, uint32_t a2, uint32_t a3,
                      uint32_t b0, uint32_t b1)
{
    asm volatile(
        "mma.sync.aligned.m16n8k16.row.col.f32.bf16.bf16.f32 "
        "{%0,%1,%2,%3},{%4,%5,%6,%7},{%8,%9},{%0,%1,%2,%3};"
        : "+f"(c[0]), "+f"(c[1]), "+f"(c[2]), "+f"(c[3])
        : "r"(a0), "r"(a1), "r"(a2), "r"(a3), "r"(b0), "r"(b1));
}

// smem-B tf32 warp GEMM (h-path)
template<int NTW, int KS>
DEV_INLINE void wgemm(float c[NTW][4], const float* __restrict__ Arow, int lda,
                      const float* __restrict__ Bcol, int ldb, int g, int qt)
{
    #pragma unroll
    for (int ks = 0; ks < KS; ks++) {
        int k = ks * 8;
        uint32_t a0 = __float_as_uint(Arow[(g)     * lda + k + qt]);
        uint32_t a1 = __float_as_uint(Arow[(g + 8) * lda + k + qt]);
        uint32_t a2 = __float_as_uint(Arow[(g)     * lda + k + qt + 4]);
        uint32_t a3 = __float_as_uint(Arow[(g + 8) * lda + k + qt + 4]);
        #pragma unroll
        for (int j = 0; j < NTW; j++) {
            uint32_t b0 = __float_as_uint(Bcol[(k + qt)     * ldb + j * 8 + g]);
            uint32_t b1 = __float_as_uint(Bcol[(k + qt + 4) * ldb + j * 8 + g]);
            mma8(c[j], a0, a1, a2, a3, b0, b1);
        }
    }
}

// bf16 warp GEMM, m16n8k16. A in smem as u32 (bf16x2), sb2 = u32 words per row.
template<int TM, int NTW, int S, int N>
DEV_INLINE void wgemm_b(float c[TM][NTW][4], const uint32_t* __restrict__ As, int sb2,
                        const uint32_t* __restrict__ Bp, int g, int qt)
{
    #pragma unroll
    for (int t = 0; t < (S + 1) / 2; t++) {
        uint4 bq[NTW];
        #pragma unroll
        for (int j = 0; j < NTW; j++)
            bq[j] = *(const uint4*)&Bp[(t * (N * 4) + (j * 8 + g) * 4 + qt) * 4];
        #pragma unroll
        for (int se = 0; se < 2; se++) {
            int s = 2 * t + se;
            if (s >= S) break;
            #pragma unroll
            for (int tm = 0; tm < TM; tm++) {
                const uint32_t* Ar = As + tm * 16 * sb2;
                uint32_t a0 = Ar[(g)     * sb2 + 8 * s + qt];
                uint32_t a2 = Ar[(g)     * sb2 + 8 * s + qt + 4];
                uint32_t a1 = Ar[(g + 8) * sb2 + 8 * s + qt];
                uint32_t a3 = Ar[(g + 8) * sb2 + 8 * s + qt + 4];
                #pragma unroll
                for (int j = 0; j < NTW; j++) {
                    uint32_t b0 = se ? bq[j].z : bq[j].x;
                    uint32_t b1 = se ? bq[j].w : bq[j].y;
                    mma16(c[tm][j], a0, a1, a2, a3, b0, b1);
                }
            }
        }
    }
}

// bf16 fragment pack index: element (k,n) of a KxN col-fragment weight.
DEV_INLINE int packB(int n, int k, int N) {
    int p = k >> 1, lo = k & 1;
    int qt = p & 3, half = (p >> 2) & 1, s = p >> 3;
    int t = s >> 1, se = s & 1;
    int u32i = (t * (N * 4) + n * 4 + qt) * 4 + se * 2 + half;
    return u32i * 2 + lo;
}

__global__ void pack_weights(const float* __restrict__ W_E, const float* __restrict__ W_G,
                             const float* __restrict__ W_Oe, const float* __restrict__ W_e1,
                             const float* __restrict__ W_e2)
{
    int i = blockIdx.x * 256 + threadIdx.x;
    if (i < 4096) {                       // WEG: K=64, N=64
        int k = i >> 6, n = i & 63;
        float v = n < 32 ? W_E[k * 32 + n] : W_G[k * 32 + n - 32];
        g_WEGb[packB(n, k, 64)] = __float2bfloat16(v);
    } else if (i < 6144) {                // WOe: K=32, N=64
        int j = i - 4096; int k = j >> 6, n = j & 63;
        g_WOeb[packB(n, k, 64)] = __float2bfloat16(W_Oe[j]);
    } else if (i < 14336) {               // We1: K=64, N=128
        int j = i - 6144; int k = j >> 7, n = j & 127;
        g_We1b[packB(n, k, 128)] = __float2bfloat16(W_e1[j]);
    } else if (i < 22528) {               // We2: K=128, N=64
        int j = i - 14336; int k = j >> 6, n = j & 63;
        g_We2b[packB(n, k, 64)] = __float2bfloat16(W_e2[j]);
    }
}

// K and V -> interleaved bf16 pairs (both use layout [row*256 + p*32 + h])
__global__ void kvconv_kernel()
{
    int idx = blockIdx.x * 256 + threadIdx.x;    // over ROWS*512
    int row = idx >> 9, t = idx & 511;
    int half = t >> 8, u = t & 255;
    int dp = u >> 5, h = u & 31;
    const float* base = g_qkv + (size_t)row * 1536 + 512 + half * 512 + dp * 64 + h;
    __nv_bfloat162 v = __floats2bfloat162_rn(base[0], base[32]);
    if (half == 0) g_kb[(size_t)row * 256 + u] = v;
    else           g_vb[(size_t)row * 256 + u] = v;
}

// ---------------- LayerNorm over 512, one block per row ----------------
__global__ void __launch_bounds__(128) ln512_kernel(
    const float* __restrict__ x, const float* __restrict__ g,
    const float* __restrict__ b, float* __restrict__ y)
{
    int row = blockIdx.x, tid = threadIdx.x;
    const float4* xr = (const float4*)(x + (size_t)row * 512);
    float4 v = xr[tid];
    float s  = v.x + v.y + v.z + v.w;
    float s2 = v.x*v.x + v.y*v.y + v.z*v.z + v.w*v.w;
    #pragma unroll
    for (int o = 16; o; o >>= 1) {
        s  += __shfl_xor_sync(0xffffffffu, s,  o);
        s2 += __shfl_xor_sync(0xffffffffu, s2, o);
    }
    __shared__ float aS[4], aS2[4];
    if ((tid & 31) == 0) { aS[tid >> 5] = s; aS2[tid >> 5] = s2; }
    __syncthreads();
    s  = aS[0] + aS[1] + aS[2] + aS[3];
    s2 = aS2[0] + aS2[1] + aS2[2] + aS2[3];
    float mean = s * (1.f / 512.f);
    float rstd = rsqrtf(s2 * (1.f / 512.f) - mean * mean + EPSc);
    int c = tid * 4;
    float4 gv = *(const float4*)(g + c);
    float4 bv = *(const float4*)(b + c);
    float4 o;
    o.x = (v.x - mean) * rstd * gv.x + bv.x;
    o.y = (v.y - mean) * rstd * gv.y + bv.y;
    o.z = (v.z - mean) * rstd * gv.z + bv.z;
    o.w = (v.w - mean) * rstd * gv.w + bv.w;
    ((float4*)(y + (size_t)row * 512))[tid] = o;
}

// ---------------- tf32 tensor GEMM for h-path ----------------
constexpr int TG_SMEM_BYTES = (128 * 68 + 64 * 72) * 4;   // 53248
template<int MODE>
__global__ void __launch_bounds__(256) tgemm(
    const float* __restrict__ A, const float* __restrict__ B, float* __restrict__ C,
    const float* __restrict__ bias, const float* __restrict__ res,
    int M, int N, int K)
{
    extern __shared__ float ts[];
    float* As = ts;              // 128 x 68
    float* Bs = ts + 128 * 68;   // 64 x 72
    int tid = threadIdx.x;
    int row0 = blockIdx.y * 128, col0 = blockIdx.x * 64;
    int w = tid >> 5;
    int g = (tid & 31) >> 2, qt = tid & 3;
    float acc[8][4] = {};

    for (int k0 = 0; k0 < K; k0 += 64) {
        #pragma unroll
        for (int i = 0; i < 8; i++) {
            int idx = tid + i * 256;
            int r = idx >> 4, c4 = idx & 15;
            float4 v = *(const float4*)&A[(size_t)(row0 + r) * K + k0 + c4 * 4];
            float4 t;
            t.x = to_tf32(v.x); t.y = to_tf32(v.y); t.z = to_tf32(v.z); t.w = to_tf32(v.w);
            *(float4*)&As[r * 68 + c4 * 4] = t;
        }
        #pragma unroll
        for (int i = 0; i < 4; i++) {
            int idx = tid + i * 256;
            int r = idx >> 4, c4 = idx & 15;
            float4 v = *(const float4*)&B[(size_t)(k0 + r) * N + col0 + c4 * 4];
            float4 t;
            t.x = to_tf32(v.x); t.y = to_tf32(v.y); t.z = to_tf32(v.z); t.w = to_tf32(v.w);
            *(float4*)&Bs[r * 72 + c4 * 4] = t;
        }
        __syncthreads();
        wgemm<8, 8>(acc, As + w * 16 * 68, 68, Bs, 72, g, qt);
        __syncthreads();
    }
    #pragma unroll
    for (int j = 0; j < 8; j++) {
        int col = col0 + j * 8 + 2 * qt;
        #pragma unroll
        for (int hf = 0; hf < 2; hf++) {
            int r = row0 + w * 16 + g + hf * 8;
            float v0 = acc[j][hf * 2 + 0] + bias[col];
            float v1 = acc[j][hf * 2 + 1] + bias[col + 1];
            if (MODE == 1) {
                float2 rv = *(const float2*)&res[(size_t)r * N + col];
                v0 += rv.x; v1 += rv.y;
            }
            if (MODE == 2) {
                v0 = v0 > 0.f ? v0 : __expf(v0) - 1.f;
                v1 = v1 > 0.f ? v1 : __expf(v1) - 1.f;
            }
            float2 ov; ov.x = v0; ov.y = v1;
            *(float2*)&C[(size_t)r * N + col] = ov;
        }
    }
}

// LN of 64 rows x 64 cols: fp32 src (stride sstr) -> bf16x2 dst (dsb2 u32/row).
DEV_INLINE void ln64b(const float* __restrict__ src, int sstr, uint32_t* __restrict__ dst,
                      int dsb2, const float* __restrict__ gam,
                      const float* __restrict__ bet, int tid)
{
    int r = tid >> 2, sub = tid & 3;
    const float* p = src + r * sstr + sub * 16;
    float x[16]; float s = 0.f, s2 = 0.f;
    #pragma unroll
    for (int i = 0; i < 16; i += 4) {
        float4 v = *(const float4*)(p + i);
        x[i] = v.x; x[i+1] = v.y; x[i+2] = v.z; x[i+3] = v.w;
    }
    #pragma unroll
    for (int i = 0; i < 16; i++) { s += x[i]; s2 += x[i] * x[i]; }
    s  += __shfl_xor_sync(0xffffffffu, s, 1);  s  += __shfl_xor_sync(0xffffffffu, s, 2);
    s2 += __shfl_xor_sync(0xffffffffu, s2, 1); s2 += __shfl_xor_sync(0xffffffffu, s2, 2);
    float mean = s * (1.f / 64.f);
    float rstd = rsqrtf(s2 * (1.f / 64.f) - mean * mean + EPSc);
    uint32_t* d = dst + r * dsb2 + sub * 8;
    #pragma unroll
    for (int i = 0; i < 16; i += 2) {
        int c = sub * 16 + i;
        float y0 = (x[i]     - mean) * rstd * gam[c]     + bet[c];
        float y1 = (x[i + 1] - mean) * rstd * gam[c + 1] + bet[c + 1];
        __nv_bfloat162 h2 = __floats2bfloat162_rn(y0, y1);
        d[i >> 1] = *(uint32_t*)&h2;
    }
}

// Fused: load e tile from global, keep fp32 copy in sX, LN -> bf16x2 sXb.
DEV_INLINE void ln64g(const float* __restrict__ eg, float* __restrict__ sX,
                      uint32_t* __restrict__ sXb,
                      const float* __restrict__ gam, const float* __restrict__ bet, int tid)
{
    int r = tid >> 2, sub = tid & 3;
    const float* p = eg + r * 64 + sub * 16;
    float* q = sX + r * 68 + sub * 16;
    float x[16]; float s = 0.f, s2 = 0.f;
    #pragma unroll
    for (int i = 0; i < 16; i += 4) {
        float4 v = *(const float4*)(p + i);
        *(float4*)(q + i) = v;
        x[i] = v.x; x[i+1] = v.y; x[i+2] = v.z; x[i+3] = v.w;
    }
    #pragma unroll
    for (int i = 0; i < 16; i++) { s += x[i]; s2 += x[i] * x[i]; }
    s  += __shfl_xor_sync(0xffffffffu, s, 1);  s  += __shfl_xor_sync(0xffffffffu, s, 2);
    s2 += __shfl_xor_sync(0xffffffffu, s2, 1); s2 += __shfl_xor_sync(0xffffffffu, s2, 2);
    float mean = s * (1.f / 64.f);
    float rstd = rsqrtf(s2 * (1.f / 64.f) - mean * mean + EPSc);
    uint32_t* d = sXb + r * 36 + sub * 8;
    #pragma unroll
    for (int i = 0; i < 16; i += 2) {
        int c = sub * 16 + i;
        float y0 = (x[i]     - mean) * rstd * gam[c]     + bet[c];
        float y1 = (x[i + 1] - mean) * rstd * gam[c + 1] + bet[c + 1];
        __nv_bfloat162 h2 = __floats2bfloat162_rn(y0, y1);
        d[i >> 1] = *(uint32_t*)&h2;
    }
}

// ---------------- edge pipeline: 64 rows/CTA, 256 threads, 3 CTA/SM ------------
constexpr int EA_SMEM_BYTES = (4352 + 2176 + 2304 + 1280 + 4352) * 4;  // 57856

__global__ void __launch_bounds__(256, 3) ea_kernel(
    const float* __restrict__ e, const float* __restrict__ mask,
    const float* __restrict__ lng, const float* __restrict__ lnb,
    const float* __restrict__ flg, const float* __restrict__ flb,
    const float* __restrict__ b_E,  const float* __restrict__ b_G,
    const float* __restrict__ b_Oe, const float* __restrict__ b_e1,
    const float* __restrict__ b_e2,
    float* __restrict__ e_out)
{
    extern __shared__ float sm[];
    float*    sX  = sm;                          // 64 x 68 fp32 (e, then e2)
    float*    sAf = sm + 4352;                   // 64 x 34 fp32 (A_hat)
    uint32_t* sXb = (uint32_t*)(sm + 6528);      // 64 x 36 u32 (eln/eff bf16x2)
    uint32_t* sAb = (uint32_t*)(sm + 8832);      // 64 x 20 u32 (H bf16x2)
    uint32_t* sTb = (uint32_t*)(sm + 10112);     // 64 x 68 u32 (T bf16x2)

    int tid = threadIdx.x;
    int blk = blockIdx.x;
    int bl  = blk >> 2, quad = blk & 3;
    int b   = bl >> 8;
    int m0  = quad * 64;
    size_t R0 = (size_t)bl * 256 + m0;

    int w   = tid >> 5;
    int wm2 = w >> 2, wn = w & 3;       // rows wm2*32, col quarter wn
    int g   = (tid & 31) >> 2, qt = tid & 3;
    int rowb = wm2 * 32;

    const uint32_t* WEGu = (const uint32_t*)g_WEGb;
    const uint32_t* WOeu = (const uint32_t*)g_WOeb;
    const uint32_t* We1u = (const uint32_t*)g_We1b;
    const uint32_t* We2u = (const uint32_t*)g_We2b;

    // Pa: load e + LN(e) -> sX (fp32 copy) and sXb (bf16)
    ln64g(e + R0 * 64, sX, sXb, lng, lnb, tid);
    __syncthreads();

    // Pb: QK (bf16 K) -> sAf  +  GEMM1 (E|G)
    {
        int h = tid & 31, mr = tid >> 5;
        float q[16];
        const float* Qp = g_qkv + (size_t)bl * 1536 + h;
        #pragma unroll
        for (int d = 0; d < 16; d++) q[d] = Qp[d * 32];
        const __nv_bfloat162* Kb = g_kb + ((size_t)(b * 256) + m0) * 256 + h;
        #pragma unroll
        for (int rr = 0; rr < 8; rr++) {
            int ml = mr + rr * 8;
            const __nv_bfloat162* Kp = Kb + (size_t)ml * 256;
            float a = 0.f;
            #pragma unroll
            for (int dp = 0; dp < 8; dp++) {
                float2 kv = __bfloat1622float2(Kp[dp * 32]);
                a += q[2 * dp] * kv.x + q[2 * dp + 1] * kv.y;
            }
            sAf[ml * 34 + h] = a * 0.25f;
        }
    }
    float c1[2][2][4] = {};
    wgemm_b<2, 2, 4, 64>(c1, sXb + rowb * 36, 36, WEGu + wn * 256, g, qt);
    __syncthreads();

    // Pc: epilogue — wn<2: H (cols 0..31) -> g_Hb + sAb ; wn>=2: gate -> g_gateb
    {
        #pragma unroll
        for (int tm = 0; tm < 2; tm++) {
            float mk0 = mask[(size_t)bl * 256 + m0 + rowb + tm * 16 + g];
            float mk1 = mask[(size_t)bl * 256 + m0 + rowb + tm * 16 + g + 8];
            #pragma unroll
            for (int j = 0; j < 2; j++) {
                int colg = wn * 16 + j * 8 + 2 * qt;
                if (wn < 2) {
                    int col = colg;
                    float bv0 = b_E[col], bv1 = b_E[col + 1];
                    #pragma unroll
                    for (int hf = 0; hf < 2; hf++) {
                        int r = rowb + tm * 16 + g + hf * 8;
                        float A0 = sAf[r * 34 + col], A1 = sAf[r * 34 + col + 1];
                        float H0 = fminf(fmaxf(A0, -5.f), 5.f) + c1[tm][j][hf * 2 + 0] + bv0;
                        float H1 = fminf(fmaxf(A1, -5.f), 5.f) + c1[tm][j][hf * 2 + 1] + bv1;
                        float mk = hf ? mk1 : mk0;
                        __nv_bfloat162 hm = __floats2bfloat162_rn(H0 + mk, H1 + mk);
                        g_Hb[(R0 + r) * 16 + (col >> 1)] = *(uint32_t*)&hm;
                        __nv_bfloat162 hb = __floats2bfloat162_rn(H0, H1);
                        sAb[r * 20 + (col >> 1)] = *(uint32_t*)&hb;
                    }
                } else {
                    int col = colg - 32;
                    float bv0 = b_G[col], bv1 = b_G[col + 1];
                    #pragma unroll
                    for (int hf = 0; hf < 2; hf++) {
                        int r = rowb + tm * 16 + g + hf * 8;
                        float mk = hf ? mk1 : mk0;
                        float g0 = 1.f / (1.f + __expf(-(c1[tm][j][hf * 2 + 0] + bv0 + mk)));
                        float g1 = 1.f / (1.f + __expf(-(c1[tm][j][hf * 2 + 1] + bv1 + mk)));
                        __nv_bfloat162 gb = __floats2bfloat162_rn(g0, g1);
                        g_gateb[(R0 + r) * 16 + (col >> 1)] = *(uint32_t*)&gb;
                    }
                }
            }
        }
    }
    __syncthreads();

    // Pd: GEMM2  e2 = H @ W_Oe + b + e(sX)   (regs + sX overwrite)
    float e2r[2][2][4];
    {
        float c2[2][2][4] = {};
        wgemm_b<2, 2, 2, 64>(c2, sAb + rowb * 20, 20, WOeu + wn * 256, g, qt);
        #pragma unroll
        for (int tm = 0; tm < 2; tm++)
            #pragma unroll
            for (int j = 0; j < 2; j++) {
                int col = wn * 16 + j * 8 + 2 * qt;
                float bo0 = b_Oe[col], bo1 = b_Oe[col + 1];
                #pragma unroll
                for (int hf = 0; hf < 2; hf++) {
                    int r = rowb + tm * 16 + g + hf * 8;
                    float ev0 = sX[r * 68 + col], ev1 = sX[r * 68 + col + 1];
                    float v0 = c2[tm][j][hf * 2 + 0] + bo0 + ev0;
                    float v1 = c2[tm][j][hf * 2 + 1] + bo1 + ev1;
                    e2r[tm][j][hf * 2 + 0] = v0;
                    e2r[tm][j][hf * 2 + 1] = v1;
                    sX[r * 68 + col]     = v0;
                    sX[r * 68 + col + 1] = v1;
                }
            }
    }
    __syncthreads();

    // Pe: LN(e2) -> sXb (bf16 eff)
    ln64b(sX, 68, sXb, 36, flg, flb, tid);
    __syncthreads();

    // Pf: GEMM3  T = elu(eff @ W_e1 + b) -> sTb, two 16-col halves per warp
    #pragma unroll
    for (int half = 0; half < 2; half++) {
        float c3[2][2][4] = {};
        int cb = wn * 32 + half * 16;
        wgemm_b<2, 2, 4, 128>(c3, sXb + rowb * 36, 36, We1u + cb * 16, g, qt);
        #pragma unroll
        for (int tm = 0; tm < 2; tm++)
            #pragma unroll
            for (int j = 0; j < 2; j++) {
                int col = cb + j * 8 + 2 * qt;
                float bb0 = b_e1[col], bb1 = b_e1[col + 1];
                #pragma unroll
                for (int hf = 0; hf < 2; hf++) {
                    int r = rowb + tm * 16 + g + hf * 8;
                    float v0 = c3[tm][j][hf * 2 + 0] + bb0;
                    float v1 = c3[tm][j][hf * 2 + 1] + bb1;
                    v0 = v0 > 0.f ? v0 : __expf(v0) - 1.f;
                    v1 = v1 > 0.f ? v1 : __expf(v1) - 1.f;
                    __nv_bfloat162 tb = __floats2bfloat162_rn(v0, v1);
                    sTb[r * 68 + (col >> 1)] = *(uint32_t*)&tb;
                }
            }
    }
    __syncthreads();

    // Pg: GEMM4  e_out = T @ W_e2 + b + e2(regs)
    {
        float c4[2][2][4] = {};
        wgemm_b<2, 2, 8, 64>(c4, sTb + rowb * 68, 68, We2u + wn * 256, g, qt);
        #pragma unroll
        for (int tm = 0; tm < 2; tm++)
            #pragma unroll
            for (int j = 0; j < 2; j++) {
                int col = wn * 16 + j * 8 + 2 * qt;
                float bz0 = b_e2[col], bz1 = b_e2[col + 1];
                #pragma unroll
                for (int hf = 0; hf < 2; hf++) {
                    int r = rowb + tm * 16 + g + hf * 8;
                    float2 ov;
                    ov.x = c4[tm][j][hf * 2 + 0] + bz0 + e2r[tm][j][hf * 2 + 0];
                    ov.y = c4[tm][j][hf * 2 + 1] + bz1 + e2r[tm][j][hf * 2 + 1];
                    *(float2*)&e_out[(R0 + r) * 64 + col] = ov;
                }
            }
    }
}

// ---------------- softmax + gated V accumulation: one block per (b,l) ----------
__global__ void __launch_bounds__(256) eb_kernel()
{
    __shared__ float sH[256 * 36];
    __shared__ float sRed[256];
    __shared__ float sRed2[256];

    int tid = threadIdx.x;
    int bl  = blockIdx.x;
    int b   = bl >> 8;

    // load H (bf16x2) -> fp32 smem
    const uint4* Hg = (const uint4*)(g_Hb + (size_t)bl * 4096);
    #pragma unroll
    for (int i = 0; i < 4; i++) {
        int idx = tid + i * 256;          // 1024 uint4
        int m = idx >> 2, q = idx & 3;
        uint4 hv = Hg[idx];
        uint32_t ws[4] = {hv.x, hv.y, hv.z, hv.w};
        #pragma unroll
        for (int j = 0; j < 4; j++) {
            float2 f = __bfloat1622float2(*(__nv_bfloat162*)&ws[j]);
            sH[m * 36 + q * 8 + 2 * j]     = f.x;
            sH[m * 36 + q * 8 + 2 * j + 1] = f.y;
        }
    }
    __syncthreads();

    int h = tid & 31, grp = tid >> 5;
    float pmax = -1e30f;
    for (int mm = 0; mm < 32; mm++) {
        int m = grp * 32 + mm;
        pmax = fmaxf(pmax, sH[m * 36 + h]);
    }
    sRed[grp * 32 + h] = pmax;
    __syncthreads();
    float M = -1e30f;
    #pragma unroll
    for (int gg = 0; gg < 8; gg++) M = fmaxf(M, sRed[gg * 32 + h]);

    const uint32_t* gateR = g_gateb + (size_t)bl * 4096;
    float ssum = 0.f;
    for (int mm = 0; mm < 32; mm++) {
        int m = grp * 32 + mm;
        float wv = __expf(sH[m * 36 + h] - M);
        ssum += wv;
        uint32_t gw = gateR[m * 16 + (h >> 1)];
        float2 gf = __bfloat1622float2(*(__nv_bfloat162*)&gw);
        float gate = (h & 1) ? gf.y : gf.x;
        sH[m * 36 + h] = wv * gate;
    }
    sRed2[grp * 32 + h] = ssum;
    __syncthreads();
    float S = 0.f;
    #pragma unroll
    for (int gg = 0; gg < 8; gg++) S += sRed2[gg * 32 + h];
    float inv = 1.f / S;

    // V accumulation (bf16 packed V: one 4B load per m per thread)
    float a0 = 0.f, a1 = 0.f;
    const __nv_bfloat162* Vb = g_vb + (size_t)(b * 256) * 256 + grp * 32 + h;
    #pragma unroll 8
    for (int m = 0; m < 256; m++) {
        float wv = sH[m * 36 + h];
        float2 vv = __bfloat1622float2(Vb[(size_t)m * 256]);
        a0 += wv * vv.x;
        a1 += wv * vv.y;
    }
    int k0 = grp * 2;
    g_vatt[(size_t)bl * 512 + k0 * 32 + h]       = a0 * inv;
    g_vatt[(size_t)bl * 512 + (k0 + 1) * 32 + h] = a1 * inv;
}

// ---------------- launch ----------------
extern "C" void kernel_launch(void* const* d_in, const int* in_sizes, int n_in,
                              void* d_out, int out_size)
{
    const float* h         = (const float*)d_in[0];
    const float* e         = (const float*)d_in[1];
    const float* mask      = (const float*)d_in[2];
    const float* ln_h_g    = (const float*)d_in[3];
    const float* ln_h_b    = (const float*)d_in[4];
    const float* ln_e_g    = (const float*)d_in[5];
    const float* ln_e_b    = (const float*)d_in[6];
    const float* ffn_ln_h_g= (const float*)d_in[7];
    const float* ffn_ln_h_b= (const float*)d_in[8];
    const float* ffn_ln_e_g= (const float*)d_in[9];
    const float* ffn_ln_e_b= (const float*)d_in[10];
    const float* W_qkv     = (const float*)d_in[11];
    const float* b_qkv     = (const float*)d_in[12];
    const float* W_E       = (const float*)d_in[13];
    const float* b_E       = (const float*)d_in[14];
    const float* W_G       = (const float*)d_in[15];
    const float* b_G       = (const float*)d_in[16];
    const float* W_Oh      = (const float*)d_in[17];
    const float* b_Oh      = (const float*)d_in[18];
    const float* W_h1      = (const float*)d_in[19];
    const float* b_h1      = (const float*)d_in[20];
    const float* W_h2      = (const float*)d_in[21];
    const float* b_h2      = (const float*)d_in[22];
    const float* W_Oe      = (const float*)d_in[23];
    const float* b_Oe      = (const float*)d_in[24];
    const float* W_e1      = (const float*)d_in[25];
    const float* b_e1      = (const float*)d_in[26];
    const float* W_e2      = (const float*)d_in[27];
    const float* b_e2      = (const float*)d_in[28];

    float* h_out = (float*)d_out;
    float* e_out = (float*)d_out + (size_t)ROWS * DNn;

    float *p_hln, *p_qkv, *p_vatt, *p_h2, *p_hff, *p_t;
    cudaGetSymbolAddress((void**)&p_hln,  g_hln);
    cudaGetSymbolAddress((void**)&p_qkv,  g_qkv);
    cudaGetSymbolAddress((void**)&p_vatt, g_vatt);
    cudaGetSymbolAddress((void**)&p_h2,   g_h2);
    cudaGetSymbolAddress((void**)&p_hff,  g_hff);
    cudaGetSymbolAddress((void**)&p_t,    g_t);

    cudaFuncSetAttribute(ea_kernel, cudaFuncAttributeMaxDynamicSharedMemorySize,
                         EA_SMEM_BYTES);
    cudaFuncSetAttribute(tgemm<0>, cudaFuncAttributeMaxDynamicSharedMemorySize,
                         TG_SMEM_BYTES);
    cudaFuncSetAttribute(tgemm<1>, cudaFuncAttributeMaxDynamicSharedMemorySize,
                         TG_SMEM_BYTES);
    cudaFuncSetAttribute(tgemm<2>, cudaFuncAttributeMaxDynamicSharedMemorySize,
                         TG_SMEM_BYTES);

    // 0) pack edge weights (bf16 fragments)
    pack_weights<<<88, 256>>>(W_E, W_G, W_Oe, W_e1, W_e2);
    // 1) h_ln
    ln512_kernel<<<ROWS, 128>>>(h, ln_h_g, ln_h_b, p_hln);
    // 2) QKV = h_ln @ W_qkv + b_qkv   (tf32)
    tgemm<0><<<dim3(1536/64, ROWS/128), 256, TG_SMEM_BYTES>>>(p_hln, W_qkv, p_qkv,
                                               b_qkv, nullptr, ROWS, 1536, 512);
    // 2.5) K,V -> bf16 interleaved copies
    kvconv_kernel<<<ROWS * 2, 256>>>();
    // 3) edge pipeline (writes e_out, g_Hb(+mask), g_gateb)
    ea_kernel<<<ROWS * 4, 256, EA_SMEM_BYTES>>>(e, mask, ln_e_g, ln_e_b,
        ffn_ln_e_g, ffn_ln_e_b, b_E, b_G, b_Oe, b_e1, b_e2, e_out);
    // 4) softmax + gated V accumulation (writes g_vatt)
    eb_kernel<<<ROWS, 256>>>();
    // 5) h2 = V_att @ W_Oh + b + h
    tgemm<1><<<dim3(512/64, ROWS/128), 256, TG_SMEM_BYTES>>>(p_vatt, W_Oh, p_h2,
                                              b_Oh, h, ROWS, 512, 512);
    // 6) h_ff = LN(h2)
    ln512_kernel<<<ROWS, 128>>>(p_h2, ffn_ln_h_g, ffn_ln_h_b, p_hff);
    // 7) t = elu(h_ff @ W_h1 + b)
    tgemm<2><<<dim3(1024/64, ROWS/128), 256, TG_SMEM_BYTES>>>(p_hff, W_h1, p_t,
                                               b_h1, nullptr, ROWS, 1024, 512);
    // 8) h_out = t @ W_h2 + b + h2
    tgemm<1><<<dim3(512/64, ROWS/128), 256, TG_SMEM_BYTES>>>(p_t, W_h2, h_out,
                                              b_h2, p_h2, ROWS, 512, 1024);
}

// round 9
// speedup vs baseline: 4.9217x; 1.0230x over previous
#include <cuda_runtime.h>
#include <cuda_bf16.h>
#include <math.h>
#include <stdint.h>

#define DEV_INLINE __device__ __forceinline__

constexpr int Bn = 32, Ln = 256, DNn = 512;
constexpr int ROWS = Bn * Ln;            // 8192 (b,l) rows
constexpr int EROWS = ROWS * Ln;         // 2,097,152 edge rows
constexpr int FNn = 1024;
constexpr float EPSc = 1e-5f;

// ---------------- device scratch ----------------
__device__ float g_hln[ROWS * DNn];
__device__ float g_qkv[ROWS * 3 * DNn];
__device__ float g_vatt[ROWS * DNn];
__device__ float g_h2[ROWS * DNn];
__device__ float g_hff[ROWS * DNn];
__device__ float g_t[ROWS * FNn];
__device__ uint32_t g_Hb[(size_t)EROWS * 16];     // H_hat + mask, bf16x2
__device__ uint32_t g_gateb[(size_t)EROWS * 16];  // sigmoid(G+mask), bf16x2
// bf16 fragment-packed edge weights (see packB); bf16 K and V copies
__device__ __nv_bfloat16 g_WEGb[64 * 64];
__device__ __nv_bfloat16 g_WOeb[32 * 64];
__device__ __nv_bfloat16 g_We1b[64 * 128];
__device__ __nv_bfloat16 g_We2b[128 * 64];
__device__ __nv_bfloat162 g_kb[(size_t)ROWS * 256];   // [(row)*256 + dp*32 + h]
__device__ __nv_bfloat162 g_vb[(size_t)ROWS * 256];   // [(row)*256 + kp*32 + h]

DEV_INLINE uint32_t packbf(float a, float b) {
    __nv_bfloat162 h2 = __floats2bfloat162_rn(a, b);
    return *(uint32_t*)&h2;
}

DEV_INLINE void mma16(float c[4], uint32_t a0, uint32_t a1, uint32_t a2, uint32_t a3,
                      uint32_t b0, uint32_t b1)
{
    asm volatile(
        "mma.sync.aligned.m16n8k16.row.col.f32.bf16.bf16.f32 "
        "{%0,%1,%2,%3},{%4,%5,%6,%7},{%8,%9},{%0,%1,%2,%3};"
        : "+f"(c[0]), "+f"(c[1]), "+f"(c[2]), "+f"(c[3])
        : "r"(a0), "r"(a1), "r"(a2), "r"(a3), "r"(b0), "r"(b1));
}

// bf16 warp GEMM, m16n8k16. A in smem as u32 (bf16x2), sb2 = u32 words per row.
template<int TM, int NTW, int S, int N>
DEV_INLINE void wgemm_b(float c[TM][NTW][4], const uint32_t* __restrict__ As, int sb2,
                        const uint32_t* __restrict__ Bp, int g, int qt)
{
    #pragma unroll
    for (int t = 0; t < (S + 1) / 2; t++) {
        uint4 bq[NTW];
        #pragma unroll
        for (int j = 0; j < NTW; j++)
            bq[j] = *(const uint4*)&Bp[(t * (N * 4) + (j * 8 + g) * 4 + qt) * 4];
        #pragma unroll
        for (int se = 0; se < 2; se++) {
            int s = 2 * t + se;
            if (s >= S) break;
            #pragma unroll
            for (int tm = 0; tm < TM; tm++) {
                const uint32_t* Ar = As + tm * 16 * sb2;
                uint32_t a0 = Ar[(g)     * sb2 + 8 * s + qt];
                uint32_t a2 = Ar[(g)     * sb2 + 8 * s + qt + 4];
                uint32_t a1 = Ar[(g + 8) * sb2 + 8 * s + qt];
                uint32_t a3 = Ar[(g + 8) * sb2 + 8 * s + qt + 4];
                #pragma unroll
                for (int j = 0; j < NTW; j++) {
                    uint32_t b0 = se ? bq[j].z : bq[j].x;
                    uint32_t b1 = se ? bq[j].w : bq[j].y;
                    mma16(c[tm][j], a0, a1, a2, a3, b0, b1);
                }
            }
        }
    }
}

// bf16 fragment pack index: element (k,n) of a KxN col-fragment weight.
DEV_INLINE int packB(int n, int k, int N) {
    int p = k >> 1, lo = k & 1;
    int qt = p & 3, half = (p >> 2) & 1, s = p >> 3;
    int t = s >> 1, se = s & 1;
    int u32i = (t * (N * 4) + n * 4 + qt) * 4 + se * 2 + half;
    return u32i * 2 + lo;
}

__global__ void pack_weights(const float* __restrict__ W_E, const float* __restrict__ W_G,
                             const float* __restrict__ W_Oe, const float* __restrict__ W_e1,
                             const float* __restrict__ W_e2)
{
    int i = blockIdx.x * 256 + threadIdx.x;
    if (i < 4096) {                       // WEG: K=64, N=64
        int k = i >> 6, n = i & 63;
        float v = n < 32 ? W_E[k * 32 + n] : W_G[k * 32 + n - 32];
        g_WEGb[packB(n, k, 64)] = __float2bfloat16(v);
    } else if (i < 6144) {                // WOe: K=32, N=64
        int j = i - 4096; int k = j >> 6, n = j & 63;
        g_WOeb[packB(n, k, 64)] = __float2bfloat16(W_Oe[j]);
    } else if (i < 14336) {               // We1: K=64, N=128
        int j = i - 6144; int k = j >> 7, n = j & 127;
        g_We1b[packB(n, k, 128)] = __float2bfloat16(W_e1[j]);
    } else if (i < 22528) {               // We2: K=128, N=64
        int j = i - 14336; int k = j >> 6, n = j & 63;
        g_We2b[packB(n, k, 64)] = __float2bfloat16(W_e2[j]);
    }
}

// K and V -> interleaved bf16 pairs (both use layout [row*256 + p*32 + h])
__global__ void kvconv_kernel()
{
    int idx = blockIdx.x * 256 + threadIdx.x;    // over ROWS*512
    int row = idx >> 9, t = idx & 511;
    int half = t >> 8, u = t & 255;
    int dp = u >> 5, h = u & 31;
    const float* base = g_qkv + (size_t)row * 1536 + 512 + half * 512 + dp * 64 + h;
    __nv_bfloat162 v = __floats2bfloat162_rn(base[0], base[32]);
    if (half == 0) g_kb[(size_t)row * 256 + u] = v;
    else           g_vb[(size_t)row * 256 + u] = v;
}

// ---------------- LayerNorm over 512, one block per row ----------------
__global__ void __launch_bounds__(128) ln512_kernel(
    const float* __restrict__ x, const float* __restrict__ g,
    const float* __restrict__ b, float* __restrict__ y)
{
    int row = blockIdx.x, tid = threadIdx.x;
    const float4* xr = (const float4*)(x + (size_t)row * 512);
    float4 v = xr[tid];
    float s  = v.x + v.y + v.z + v.w;
    float s2 = v.x*v.x + v.y*v.y + v.z*v.z + v.w*v.w;
    #pragma unroll
    for (int o = 16; o; o >>= 1) {
        s  += __shfl_xor_sync(0xffffffffu, s,  o);
        s2 += __shfl_xor_sync(0xffffffffu, s2, o);
    }
    __shared__ float aS[4], aS2[4];
    if ((tid & 31) == 0) { aS[tid >> 5] = s; aS2[tid >> 5] = s2; }
    __syncthreads();
    s  = aS[0] + aS[1] + aS[2] + aS[3];
    s2 = aS2[0] + aS2[1] + aS2[2] + aS2[3];
    float mean = s * (1.f / 512.f);
    float rstd = rsqrtf(s2 * (1.f / 512.f) - mean * mean + EPSc);
    int c = tid * 4;
    float4 gv = *(const float4*)(g + c);
    float4 bv = *(const float4*)(b + c);
    float4 o;
    o.x = (v.x - mean) * rstd * gv.x + bv.x;
    o.y = (v.y - mean) * rstd * gv.y + bv.y;
    o.z = (v.z - mean) * rstd * gv.z + bv.z;
    o.w = (v.w - mean) * rstd * gv.w + bv.w;
    ((float4*)(y + (size_t)row * 512))[tid] = o;
}

// ---------------- bf16 tensor GEMM for h-path (128x64 tile, K-chunk 64) -------
// MODE 0: +bias ; MODE 1: +bias+res ; MODE 2: elu(+bias)
template<int MODE>
__global__ void __launch_bounds__(256) tgemm_bf(
    const float* __restrict__ A, const float* __restrict__ B, float* __restrict__ C,
    const float* __restrict__ bias, const float* __restrict__ res,
    int M, int N, int K)
{
    __shared__ uint32_t As[128 * 36];   // 128 rows x 32 k-pairs (u32 bf16x2)
    __shared__ uint32_t Bs[32 * 72];    // 32 k-pairs x 64 cols (+8 pad)
    int tid = threadIdx.x;
    int row0 = blockIdx.y * 128, col0 = blockIdx.x * 64;
    int w = tid >> 5;
    int g = (tid & 31) >> 2, qt = tid & 3;
    float acc[8][4] = {};

    for (int k0 = 0; k0 < K; k0 += 64) {
        #pragma unroll
        for (int i = 0; i < 8; i++) {
            int idx = tid + i * 256;
            int r = idx >> 4, c4 = idx & 15;
            float4 v = *(const float4*)&A[(size_t)(row0 + r) * K + k0 + c4 * 4];
            As[r * 36 + c4 * 2]     = packbf(v.x, v.y);
            As[r * 36 + c4 * 2 + 1] = packbf(v.z, v.w);
        }
        #pragma unroll
        for (int i = 0; i < 2; i++) {
            int idx = tid + i * 256;
            int pr = idx >> 4, c4 = idx & 15;
            float4 v0 = *(const float4*)&B[(size_t)(k0 + 2 * pr)     * N + col0 + c4 * 4];
            float4 v1 = *(const float4*)&B[(size_t)(k0 + 2 * pr + 1) * N + col0 + c4 * 4];
            Bs[pr * 72 + c4 * 4 + 0] = packbf(v0.x, v1.x);
            Bs[pr * 72 + c4 * 4 + 1] = packbf(v0.y, v1.y);
            Bs[pr * 72 + c4 * 4 + 2] = packbf(v0.z, v1.z);
            Bs[pr * 72 + c4 * 4 + 3] = packbf(v0.w, v1.w);
        }
        __syncthreads();
        const uint32_t* Ar = As + w * 16 * 36;
        #pragma unroll
        for (int s = 0; s < 4; s++) {
            uint32_t a0 = Ar[(g)     * 36 + 8 * s + qt];
            uint32_t a1 = Ar[(g + 8) * 36 + 8 * s + qt];
            uint32_t a2 = Ar[(g)     * 36 + 8 * s + qt + 4];
            uint32_t a3 = Ar[(g + 8) * 36 + 8 * s + qt + 4];
            #pragma unroll
            for (int j = 0; j < 8; j++) {
                uint32_t b0 = Bs[(8 * s + qt)     * 72 + j * 8 + g];
                uint32_t b1 = Bs[(8 * s + qt + 4) * 72 + j * 8 + g];
                mma16(acc[j], a0, a1, a2, a3, b0, b1);
            }
        }
        __syncthreads();
    }
    #pragma unroll
    for (int j = 0; j < 8; j++) {
        int col = col0 + j * 8 + 2 * qt;
        #pragma unroll
        for (int hf = 0; hf < 2; hf++) {
            int r = row0 + w * 16 + g + hf * 8;
            float v0 = acc[j][hf * 2 + 0] + bias[col];
            float v1 = acc[j][hf * 2 + 1] + bias[col + 1];
            if (MODE == 1) {
                float2 rv = *(const float2*)&res[(size_t)r * N + col];
                v0 += rv.x; v1 += rv.y;
            }
            if (MODE == 2) {
                v0 = v0 > 0.f ? v0 : __expf(v0) - 1.f;
                v1 = v1 > 0.f ? v1 : __expf(v1) - 1.f;
            }
            float2 ov; ov.x = v0; ov.y = v1;
            *(float2*)&C[(size_t)r * N + col] = ov;
        }
    }
}

// LN of 64 rows x 64 cols: fp32 src (stride sstr) -> bf16x2 dst (dsb2 u32/row).
DEV_INLINE void ln64b(const float* __restrict__ src, int sstr, uint32_t* __restrict__ dst,
                      int dsb2, const float* __restrict__ gam,
                      const float* __restrict__ bet, int tid)
{
    int r = tid >> 2, sub = tid & 3;
    const float* p = src + r * sstr + sub * 16;
    float x[16]; float s = 0.f, s2 = 0.f;
    #pragma unroll
    for (int i = 0; i < 16; i += 4) {
        float4 v = *(const float4*)(p + i);
        x[i] = v.x; x[i+1] = v.y; x[i+2] = v.z; x[i+3] = v.w;
    }
    #pragma unroll
    for (int i = 0; i < 16; i++) { s += x[i]; s2 += x[i] * x[i]; }
    s  += __shfl_xor_sync(0xffffffffu, s, 1);  s  += __shfl_xor_sync(0xffffffffu, s, 2);
    s2 += __shfl_xor_sync(0xffffffffu, s2, 1); s2 += __shfl_xor_sync(0xffffffffu, s2, 2);
    float mean = s * (1.f / 64.f);
    float rstd = rsqrtf(s2 * (1.f / 64.f) - mean * mean + EPSc);
    uint32_t* d = dst + r * dsb2 + sub * 8;
    #pragma unroll
    for (int i = 0; i < 16; i += 2) {
        int c = sub * 16 + i;
        float y0 = (x[i]     - mean) * rstd * gam[c]     + bet[c];
        float y1 = (x[i + 1] - mean) * rstd * gam[c + 1] + bet[c + 1];
        d[i >> 1] = packbf(y0, y1);
    }
}

// Fused: load e tile from global, keep fp32 copy in sX, LN -> bf16x2 sXb.
DEV_INLINE void ln64g(const float* __restrict__ eg, float* __restrict__ sX,
                      uint32_t* __restrict__ sXb,
                      const float* __restrict__ gam, const float* __restrict__ bet, int tid)
{
    int r = tid >> 2, sub = tid & 3;
    const float* p = eg + r * 64 + sub * 16;
    float* q = sX + r * 68 + sub * 16;
    float x[16]; float s = 0.f, s2 = 0.f;
    #pragma unroll
    for (int i = 0; i < 16; i += 4) {
        float4 v = *(const float4*)(p + i);
        *(float4*)(q + i) = v;
        x[i] = v.x; x[i+1] = v.y; x[i+2] = v.z; x[i+3] = v.w;
    }
    #pragma unroll
    for (int i = 0; i < 16; i++) { s += x[i]; s2 += x[i] * x[i]; }
    s  += __shfl_xor_sync(0xffffffffu, s, 1);  s  += __shfl_xor_sync(0xffffffffu, s, 2);
    s2 += __shfl_xor_sync(0xffffffffu, s2, 1); s2 += __shfl_xor_sync(0xffffffffu, s2, 2);
    float mean = s * (1.f / 64.f);
    float rstd = rsqrtf(s2 * (1.f / 64.f) - mean * mean + EPSc);
    uint32_t* d = sXb + r * 36 + sub * 8;
    #pragma unroll
    for (int i = 0; i < 16; i += 2) {
        int c = sub * 16 + i;
        float y0 = (x[i]     - mean) * rstd * gam[c]     + bet[c];
        float y1 = (x[i + 1] - mean) * rstd * gam[c + 1] + bet[c + 1];
        d[i >> 1] = packbf(y0, y1);
    }
}

// ---------------- edge pipeline: 64 rows/CTA, 256 threads, 3 CTA/SM ------------
constexpr int EA_SMEM_BYTES = (4352 + 2176 + 2304 + 1280 + 4352) * 4;  // 57856

__global__ void __launch_bounds__(256, 3) ea_kernel(
    const float* __restrict__ e, const float* __restrict__ mask,
    const float* __restrict__ lng, const float* __restrict__ lnb,
    const float* __restrict__ flg, const float* __restrict__ flb,
    const float* __restrict__ b_E,  const float* __restrict__ b_G,
    const float* __restrict__ b_Oe, const float* __restrict__ b_e1,
    const float* __restrict__ b_e2,
    float* __restrict__ e_out)
{
    extern __shared__ float sm[];
    float*    sX  = sm;                          // 64 x 68 fp32 (e, then e2)
    float*    sAf = sm + 4352;                   // 64 x 34 fp32 (A_hat)
    uint32_t* sXb = (uint32_t*)(sm + 6528);      // 64 x 36 u32 (eln/eff bf16x2)
    uint32_t* sAb = (uint32_t*)(sm + 8832);      // 64 x 20 u32 (H bf16x2)
    uint32_t* sTb = (uint32_t*)(sm + 10112);     // 64 x 68 u32 (T bf16x2)

    int tid = threadIdx.x;
    int blk = blockIdx.x;
    int bl  = blk >> 2, quad = blk & 3;
    int b   = bl >> 8;
    int m0  = quad * 64;
    size_t R0 = (size_t)bl * 256 + m0;

    int w   = tid >> 5;
    int wm2 = w >> 2, wn = w & 3;       // rows wm2*32, col quarter wn
    int g   = (tid & 31) >> 2, qt = tid & 3;
    int rowb = wm2 * 32;

    const uint32_t* WEGu = (const uint32_t*)g_WEGb;
    const uint32_t* WOeu = (const uint32_t*)g_WOeb;
    const uint32_t* We1u = (const uint32_t*)g_We1b;
    const uint32_t* We2u = (const uint32_t*)g_We2b;

    // Pa: load e + LN(e) -> sX (fp32 copy) and sXb (bf16)
    ln64g(e + R0 * 64, sX, sXb, lng, lnb, tid);
    __syncthreads();

    // Pb: QK (bf16 K) -> sAf  +  GEMM1 (E|G)
    {
        int h = tid & 31, mr = tid >> 5;
        float q[16];
        const float* Qp = g_qkv + (size_t)bl * 1536 + h;
        #pragma unroll
        for (int d = 0; d < 16; d++) q[d] = Qp[d * 32];
        const __nv_bfloat162* Kb = g_kb + ((size_t)(b * 256) + m0) * 256 + h;
        #pragma unroll
        for (int rr = 0; rr < 8; rr++) {
            int ml = mr + rr * 8;
            const __nv_bfloat162* Kp = Kb + (size_t)ml * 256;
            float a = 0.f;
            #pragma unroll
            for (int dp = 0; dp < 8; dp++) {
                float2 kv = __bfloat1622float2(Kp[dp * 32]);
                a += q[2 * dp] * kv.x + q[2 * dp + 1] * kv.y;
            }
            sAf[ml * 34 + h] = a * 0.25f;
        }
    }
    float c1[2][2][4] = {};
    wgemm_b<2, 2, 4, 64>(c1, sXb + rowb * 36, 36, WEGu + wn * 256, g, qt);
    __syncthreads();

    // Pc: epilogue — wn<2: H (cols 0..31) -> g_Hb + sAb ; wn>=2: gate -> g_gateb
    {
        #pragma unroll
        for (int tm = 0; tm < 2; tm++) {
            float mk0 = mask[(size_t)bl * 256 + m0 + rowb + tm * 16 + g];
            float mk1 = mask[(size_t)bl * 256 + m0 + rowb + tm * 16 + g + 8];
            #pragma unroll
            for (int j = 0; j < 2; j++) {
                int colg = wn * 16 + j * 8 + 2 * qt;
                if (wn < 2) {
                    int col = colg;
                    float bv0 = b_E[col], bv1 = b_E[col + 1];
                    #pragma unroll
                    for (int hf = 0; hf < 2; hf++) {
                        int r = rowb + tm * 16 + g + hf * 8;
                        float A0 = sAf[r * 34 + col], A1 = sAf[r * 34 + col + 1];
                        float H0 = fminf(fmaxf(A0, -5.f), 5.f) + c1[tm][j][hf * 2 + 0] + bv0;
                        float H1 = fminf(fmaxf(A1, -5.f), 5.f) + c1[tm][j][hf * 2 + 1] + bv1;
                        float mk = hf ? mk1 : mk0;
                        g_Hb[(R0 + r) * 16 + (col >> 1)] = packbf(H0 + mk, H1 + mk);
                        sAb[r * 20 + (col >> 1)] = packbf(H0, H1);
                    }
                } else {
                    int col = colg - 32;
                    float bv0 = b_G[col], bv1 = b_G[col + 1];
                    #pragma unroll
                    for (int hf = 0; hf < 2; hf++) {
                        int r = rowb + tm * 16 + g + hf * 8;
                        float mk = hf ? mk1 : mk0;
                        float g0 = 1.f / (1.f + __expf(-(c1[tm][j][hf * 2 + 0] + bv0 + mk)));
                        float g1 = 1.f / (1.f + __expf(-(c1[tm][j][hf * 2 + 1] + bv1 + mk)));
                        g_gateb[(R0 + r) * 16 + (col >> 1)] = packbf(g0, g1);
                    }
                }
            }
        }
    }
    __syncthreads();

    // Pd: GEMM2  e2 = H @ W_Oe + b + e(sX)   (regs + sX overwrite)
    float e2r[2][2][4];
    {
        float c2[2][2][4] = {};
        wgemm_b<2, 2, 2, 64>(c2, sAb + rowb * 20, 20, WOeu + wn * 256, g, qt);
        #pragma unroll
        for (int tm = 0; tm < 2; tm++)
            #pragma unroll
            for (int j = 0; j < 2; j++) {
                int col = wn * 16 + j * 8 + 2 * qt;
                float bo0 = b_Oe[col], bo1 = b_Oe[col + 1];
                #pragma unroll
                for (int hf = 0; hf < 2; hf++) {
                    int r = rowb + tm * 16 + g + hf * 8;
                    float ev0 = sX[r * 68 + col], ev1 = sX[r * 68 + col + 1];
                    float v0 = c2[tm][j][hf * 2 + 0] + bo0 + ev0;
                    float v1 = c2[tm][j][hf * 2 + 1] + bo1 + ev1;
                    e2r[tm][j][hf * 2 + 0] = v0;
                    e2r[tm][j][hf * 2 + 1] = v1;
                    sX[r * 68 + col]     = v0;
                    sX[r * 68 + col + 1] = v1;
                }
            }
    }
    __syncthreads();

    // Pe: LN(e2) -> sXb (bf16 eff)
    ln64b(sX, 68, sXb, 36, flg, flb, tid);
    __syncthreads();

    // Pf: GEMM3  T = elu(eff @ W_e1 + b) -> sTb, two 16-col halves per warp
    #pragma unroll
    for (int half = 0; half < 2; half++) {
        float c3[2][2][4] = {};
        int cb = wn * 32 + half * 16;
        wgemm_b<2, 2, 4, 128>(c3, sXb + rowb * 36, 36, We1u + cb * 16, g, qt);
        #pragma unroll
        for (int tm = 0; tm < 2; tm++)
            #pragma unroll
            for (int j = 0; j < 2; j++) {
                int col = cb + j * 8 + 2 * qt;
                float bb0 = b_e1[col], bb1 = b_e1[col + 1];
                #pragma unroll
                for (int hf = 0; hf < 2; hf++) {
                    int r = rowb + tm * 16 + g + hf * 8;
                    float v0 = c3[tm][j][hf * 2 + 0] + bb0;
                    float v1 = c3[tm][j][hf * 2 + 1] + bb1;
                    v0 = v0 > 0.f ? v0 : __expf(v0) - 1.f;
                    v1 = v1 > 0.f ? v1 : __expf(v1) - 1.f;
                    sTb[r * 68 + (col >> 1)] = packbf(v0, v1);
                }
            }
    }
    __syncthreads();

    // Pg: GEMM4  e_out = T @ W_e2 + b + e2(regs)
    {
        float c4[2][2][4] = {};
        wgemm_b<2, 2, 8, 64>(c4, sTb + rowb * 68, 68, We2u + wn * 256, g, qt);
        #pragma unroll
        for (int tm = 0; tm < 2; tm++)
            #pragma unroll
            for (int j = 0; j < 2; j++) {
                int col = wn * 16 + j * 8 + 2 * qt;
                float bz0 = b_e2[col], bz1 = b_e2[col + 1];
                #pragma unroll
                for (int hf = 0; hf < 2; hf++) {
                    int r = rowb + tm * 16 + g + hf * 8;
                    float2 ov;
                    ov.x = c4[tm][j][hf * 2 + 0] + bz0 + e2r[tm][j][hf * 2 + 0];
                    ov.y = c4[tm][j][hf * 2 + 1] + bz1 + e2r[tm][j][hf * 2 + 1];
                    *(float2*)&e_out[(R0 + r) * 64 + col] = ov;
                }
            }
    }
}

// ---------------- softmax + gated V accumulation: one block per (b,l) ----------
__global__ void __launch_bounds__(256) eb_kernel()
{
    __shared__ float sH[256 * 36];
    __shared__ float sRed[256];
    __shared__ float sRed2[256];

    int tid = threadIdx.x;
    int bl  = blockIdx.x;
    int b   = bl >> 8;

    // load H (bf16x2) -> fp32 smem
    const uint4* Hg = (const uint4*)(g_Hb + (size_t)bl * 4096);
    #pragma unroll
    for (int i = 0; i < 4; i++) {
        int idx = tid + i * 256;          // 1024 uint4
        int m = idx >> 2, q = idx & 3;
        uint4 hv = Hg[idx];
        uint32_t ws[4] = {hv.x, hv.y, hv.z, hv.w};
        #pragma unroll
        for (int j = 0; j < 4; j++) {
            float2 f = __bfloat1622float2(*(__nv_bfloat162*)&ws[j]);
            sH[m * 36 + q * 8 + 2 * j]     = f.x;
            sH[m * 36 + q * 8 + 2 * j + 1] = f.y;
        }
    }
    __syncthreads();

    int h = tid & 31, grp = tid >> 5;
    float pmax = -1e30f;
    for (int mm = 0; mm < 32; mm++) {
        int m = grp * 32 + mm;
        pmax = fmaxf(pmax, sH[m * 36 + h]);
    }
    sRed[grp * 32 + h] = pmax;
    __syncthreads();
    float M = -1e30f;
    #pragma unroll
    for (int gg = 0; gg < 8; gg++) M = fmaxf(M, sRed[gg * 32 + h]);

    const uint32_t* gateR = g_gateb + (size_t)bl * 4096;
    float ssum = 0.f;
    for (int mm = 0; mm < 32; mm++) {
        int m = grp * 32 + mm;
        float wv = __expf(sH[m * 36 + h] - M);
        ssum += wv;
        uint32_t gw = gateR[m * 16 + (h >> 1)];
        float2 gf = __bfloat1622float2(*(__nv_bfloat162*)&gw);
        float gate = (h & 1) ? gf.y : gf.x;
        sH[m * 36 + h] = wv * gate;
    }
    sRed2[grp * 32 + h] = ssum;
    __syncthreads();
    float S = 0.f;
    #pragma unroll
    for (int gg = 0; gg < 8; gg++) S += sRed2[gg * 32 + h];
    float inv = 1.f / S;

    // V accumulation (bf16 packed V: one 4B load per m per thread)
    float a0 = 0.f, a1 = 0.f;
    const __nv_bfloat162* Vb = g_vb + (size_t)(b * 256) * 256 + grp * 32 + h;
    #pragma unroll 8
    for (int m = 0; m < 256; m++) {
        float wv = sH[m * 36 + h];
        float2 vv = __bfloat1622float2(Vb[(size_t)m * 256]);
        a0 += wv * vv.x;
        a1 += wv * vv.y;
    }
    int k0 = grp * 2;
    g_vatt[(size_t)bl * 512 + k0 * 32 + h]       = a0 * inv;
    g_vatt[(size_t)bl * 512 + (k0 + 1) * 32 + h] = a1 * inv;
}

// ---------------- launch ----------------
extern "C" void kernel_launch(void* const* d_in, const int* in_sizes, int n_in,
                              void* d_out, int out_size)
{
    const float* h         = (const float*)d_in[0];
    const float* e         = (const float*)d_in[1];
    const float* mask      = (const float*)d_in[2];
    const float* ln_h_g    = (const float*)d_in[3];
    const float* ln_h_b    = (const float*)d_in[4];
    const float* ln_e_g    = (const float*)d_in[5];
    const float* ln_e_b    = (const float*)d_in[6];
    const float* ffn_ln_h_g= (const float*)d_in[7];
    const float* ffn_ln_h_b= (const float*)d_in[8];
    const float* ffn_ln_e_g= (const float*)d_in[9];
    const float* ffn_ln_e_b= (const float*)d_in[10];
    const float* W_qkv     = (const float*)d_in[11];
    const float* b_qkv     = (const float*)d_in[12];
    const float* W_E       = (const float*)d_in[13];
    const float* b_E       = (const float*)d_in[14];
    const float* W_G       = (const float*)d_in[15];
    const float* b_G       = (const float*)d_in[16];
    const float* W_Oh      = (const float*)d_in[17];
    const float* b_Oh      = (const float*)d_in[18];
    const float* W_h1      = (const float*)d_in[19];
    const float* b_h1      = (const float*)d_in[20];
    const float* W_h2      = (const float*)d_in[21];
    const float* b_h2      = (const float*)d_in[22];
    const float* W_Oe      = (const float*)d_in[23];
    const float* b_Oe      = (const float*)d_in[24];
    const float* W_e1      = (const float*)d_in[25];
    const float* b_e1      = (const float*)d_in[26];
    const float* W_e2      = (const float*)d_in[27];
    const float* b_e2      = (const float*)d_in[28];

    float* h_out = (float*)d_out;
    float* e_out = (float*)d_out + (size_t)ROWS * DNn;

    float *p_hln, *p_qkv, *p_vatt, *p_h2, *p_hff, *p_t;
    cudaGetSymbolAddress((void**)&p_hln,  g_hln);
    cudaGetSymbolAddress((void**)&p_qkv,  g_qkv);
    cudaGetSymbolAddress((void**)&p_vatt, g_vatt);
    cudaGetSymbolAddress((void**)&p_h2,   g_h2);
    cudaGetSymbolAddress((void**)&p_hff,  g_hff);
    cudaGetSymbolAddress((void**)&p_t,    g_t);

    cudaFuncSetAttribute(ea_kernel, cudaFuncAttributeMaxDynamicSharedMemorySize,
                         EA_SMEM_BYTES);

    // 0) pack edge weights (bf16 fragments)
    pack_weights<<<88, 256>>>(W_E, W_G, W_Oe, W_e1, W_e2);
    // 1) h_ln
    ln512_kernel<<<ROWS, 128>>>(h, ln_h_g, ln_h_b, p_hln);
    // 2) QKV = h_ln @ W_qkv + b_qkv   (bf16)
    tgemm_bf<0><<<dim3(1536/64, ROWS/128), 256>>>(p_hln, W_qkv, p_qkv,
                                                  b_qkv, nullptr, ROWS, 1536, 512);
    // 2.5) K,V -> bf16 interleaved copies
    kvconv_kernel<<<ROWS * 2, 256>>>();
    // 3) edge pipeline (writes e_out, g_Hb(+mask), g_gateb)
    ea_kernel<<<ROWS * 4, 256, EA_SMEM_BYTES>>>(e, mask, ln_e_g, ln_e_b,
        ffn_ln_e_g, ffn_ln_e_b, b_E, b_G, b_Oe, b_e1, b_e2, e_out);
    // 4) softmax + gated V accumulation (writes g_vatt)
    eb_kernel<<<ROWS, 256>>>();
    // 5) h2 = V_att @ W_Oh + b + h
    tgemm_bf<1><<<dim3(512/64, ROWS/128), 256>>>(p_vatt, W_Oh, p_h2,
                                                 b_Oh, h, ROWS, 512, 512);
    // 6) h_ff = LN(h2)
    ln512_kernel<<<ROWS, 128>>>(p_h2, ffn_ln_h_g, ffn_ln_h_b, p_hff);
    // 7) t = elu(h_ff @ W_h1 + b)
    tgemm_bf<2><<<dim3(1024/64, ROWS/128), 256>>>(p_hff, W_h1, p_t,
                                                  b_h1, nullptr, ROWS, 1024, 512);
    // 8) h_out = t @ W_h2 + b + h2
    tgemm_bf<1><<<dim3(512/64, ROWS/128), 256>>>(p_t, W_h2, h_out,
                                                 b_h2, p_h2, ROWS, 512, 1024);
}